// round 4
// baseline (speedup 1.0000x reference)
#include <cuda_runtime.h>
#include <math.h>

// Problem constants (fixed by the reference)
#define SEQ   2048
#define BAT   2
#define NH    16
#define DHD   64
#define DM    1024
#define NTOK  (SEQ * BAT)   // 4096

// Scratch (allocation-free rule: __device__ globals)
__device__ float g_q[NTOK * DM];
__device__ float g_k[NTOK * DM];
__device__ float g_v[NTOK * DM];
__device__ float g_x[NTOK * DM];

// ---------------------------------------------------------------------------
// SGEMM: C[M,N] = A[M,K] @ B[K,N] + bias[N]   (all row-major, fp32)
// 128x128x8 tiles, 256 threads, 8x8 microtile.
// ---------------------------------------------------------------------------
__global__ __launch_bounds__(256, 2)
void sgemm_bias(const float* __restrict__ A, const float* __restrict__ B,
                const float* __restrict__ bias, float* __restrict__ C,
                int M, int N, int K)
{
    __shared__ float As[8][128];
    __shared__ float Bs[8][128];

    const int tid = threadIdx.x;
    const int bx = blockIdx.x;     // N tile
    const int by = blockIdx.y;     // M tile

    const float* Ab = A + (size_t)by * 128 * K;
    const float* Bb = B + (size_t)bx * 128;

    const int arow = tid >> 1;             // 0..127
    const int acol = (tid & 1) * 4;        // 0 or 4
    const int brow = tid >> 5;             // 0..7
    const int bcol = (tid & 31) * 4;       // 0..124
    const int ty = tid >> 4;               // 0..15
    const int tx = tid & 15;               // 0..15

    float acc[8][8];
#pragma unroll
    for (int i = 0; i < 8; i++)
#pragma unroll
        for (int j = 0; j < 8; j++) acc[i][j] = 0.0f;

    for (int k0 = 0; k0 < K; k0 += 8) {
        float4 a4 = *(const float4*)(Ab + (size_t)arow * K + k0 + acol);
        As[acol + 0][arow] = a4.x;
        As[acol + 1][arow] = a4.y;
        As[acol + 2][arow] = a4.z;
        As[acol + 3][arow] = a4.w;
        *(float4*)(&Bs[brow][bcol]) =
            *(const float4*)(Bb + (size_t)(k0 + brow) * N + bcol);
        __syncthreads();

#pragma unroll
        for (int k = 0; k < 8; k++) {
            float a[8], b[8];
            *(float4*)(a)     = *(float4*)(&As[k][ty * 8]);
            *(float4*)(a + 4) = *(float4*)(&As[k][ty * 8 + 4]);
            *(float4*)(b)     = *(float4*)(&Bs[k][tx * 8]);
            *(float4*)(b + 4) = *(float4*)(&Bs[k][tx * 8 + 4]);
#pragma unroll
            for (int i = 0; i < 8; i++)
#pragma unroll
                for (int j = 0; j < 8; j++)
                    acc[i][j] += a[i] * b[j];
        }
        __syncthreads();
    }

    const int colbase = bx * 128 + tx * 8;
#pragma unroll
    for (int i = 0; i < 8; i++) {
        const int row = by * 128 + ty * 8 + i;
        float* Crow = C + (size_t)row * N + colbase;
#pragma unroll
        for (int j = 0; j < 8; j += 4) {
            float4 o;
            o.x = acc[i][j + 0] + bias[colbase + j + 0];
            o.y = acc[i][j + 1] + bias[colbase + j + 1];
            o.z = acc[i][j + 2] + bias[colbase + j + 2];
            o.w = acc[i][j + 3] + bias[colbase + j + 3];
            *(float4*)(Crow + j) = o;
        }
    }
}

// ---------------------------------------------------------------------------
// Flash attention (causal), fp32, online softmax.
// Layout of Q/K/V/X scratch: [(s*BAT + b) * DM + h*DHD + d]
// grid: (SEQ/64, BAT*NH), block: 256
// ---------------------------------------------------------------------------
#define FSTR 68   // padded smem row stride

__global__ __launch_bounds__(256)
void flash_attn(const float* __restrict__ Q, const float* __restrict__ K,
                const float* __restrict__ V, float* __restrict__ O)
{
    extern __shared__ float sm[];
    float* Qs = sm;                 // [d][r] : Qs[d*FSTR + r]
    float* Ks = Qs + 64 * FSTR;     // [d][c] : Ks[d*FSTR + c]
    float* Vs = Ks + 64 * FSTR;     // [j][d] : Vs[j*FSTR + d]
    float* Ps = Vs + 64 * FSTR;     // [c][r] : Ps[c*FSTR + r]

    const int qb = blockIdx.x;          // query tile (0..31)
    const int bh = blockIdx.y;          // 0..31
    const int b  = bh >> 4;
    const int h  = bh & 15;
    const int tid = threadIdx.x;
    const int ty = tid >> 4;            // 0..15 -> rows ty*4..+3
    const int tx = tid & 15;            // 0..15 -> cols tx*4..+3
    const int r0 = ty * 4;
    const int c0 = tx * 4;

    // Load Q tile (64 rows x 64 d), transposed into Qs[d][r]
#pragma unroll
    for (int it = 0; it < 4; it++) {
        int i = tid + it * 256;
        int r = i >> 4, d4 = (i & 15) * 4;
        const float* p = Q + ((size_t)(qb * 64 + r) * BAT + b) * DM + h * DHD + d4;
        float4 v = *(const float4*)p;
        Qs[(d4 + 0) * FSTR + r] = v.x;
        Qs[(d4 + 1) * FSTR + r] = v.y;
        Qs[(d4 + 2) * FSTR + r] = v.z;
        Qs[(d4 + 3) * FSTR + r] = v.w;
    }

    float m_i[4], l_i[4], o_acc[4][4];
#pragma unroll
    for (int i = 0; i < 4; i++) {
        m_i[i] = -1e30f;
        l_i[i] = 0.0f;
#pragma unroll
        for (int d = 0; d < 4; d++) o_acc[i][d] = 0.0f;
    }
    const float scale = 0.125f;  // 1/sqrt(64)

    for (int kb = 0; kb <= qb; kb++) {
        __syncthreads();  // prior iter readers done (also fences Q stores on kb=0)

        // Load K (transposed) and V tiles
#pragma unroll
        for (int it = 0; it < 4; it++) {
            int i = tid + it * 256;
            int r = i >> 4, d4 = (i & 15) * 4;
            size_t g = ((size_t)(kb * 64 + r) * BAT + b) * DM + h * DHD + d4;
            float4 kv = *(const float4*)(K + g);
            Ks[(d4 + 0) * FSTR + r] = kv.x;
            Ks[(d4 + 1) * FSTR + r] = kv.y;
            Ks[(d4 + 2) * FSTR + r] = kv.z;
            Ks[(d4 + 3) * FSTR + r] = kv.w;
            float4 vv = *(const float4*)(V + g);
            *(float4*)(Vs + (size_t)r * FSTR + d4) = vv;
        }
        __syncthreads();

        // S = Q @ K^T (4x4 per thread)
        float s[4][4];
#pragma unroll
        for (int i = 0; i < 4; i++)
#pragma unroll
            for (int j = 0; j < 4; j++) s[i][j] = 0.0f;

#pragma unroll 8
        for (int d = 0; d < 64; d++) {
            float a[4], bb[4];
            *(float4*)a  = *(float4*)(Qs + d * FSTR + r0);
            *(float4*)bb = *(float4*)(Ks + d * FSTR + c0);
#pragma unroll
            for (int i = 0; i < 4; i++)
#pragma unroll
                for (int j = 0; j < 4; j++)
                    s[i][j] += a[i] * bb[j];
        }

        // scale + causal mask (only diagonal block partially masked)
        const bool diag = (kb == qb);
#pragma unroll
        for (int i = 0; i < 4; i++)
#pragma unroll
            for (int j = 0; j < 4; j++) {
                s[i][j] *= scale;
                if (diag && (c0 + j) > (r0 + i)) s[i][j] = -1e30f;
            }

        // Online softmax: rowwise max + sum via 16-lane shfl groups
#pragma unroll
        for (int i = 0; i < 4; i++) {
            float mx = fmaxf(fmaxf(s[i][0], s[i][1]), fmaxf(s[i][2], s[i][3]));
            mx = fmaxf(mx, __shfl_xor_sync(0xffffffffu, mx, 1));
            mx = fmaxf(mx, __shfl_xor_sync(0xffffffffu, mx, 2));
            mx = fmaxf(mx, __shfl_xor_sync(0xffffffffu, mx, 4));
            mx = fmaxf(mx, __shfl_xor_sync(0xffffffffu, mx, 8));
            float m_new = fmaxf(m_i[i], mx);
            float corr = __expf(m_i[i] - m_new);
            float rs = 0.0f;
#pragma unroll
            for (int j = 0; j < 4; j++) {
                float p = __expf(s[i][j] - m_new);
                s[i][j] = p;
                rs += p;
            }
            rs += __shfl_xor_sync(0xffffffffu, rs, 1);
            rs += __shfl_xor_sync(0xffffffffu, rs, 2);
            rs += __shfl_xor_sync(0xffffffffu, rs, 4);
            rs += __shfl_xor_sync(0xffffffffu, rs, 8);
            l_i[i] = l_i[i] * corr + rs;
            m_i[i] = m_new;
#pragma unroll
            for (int d = 0; d < 4; d++) o_acc[i][d] *= corr;
        }

        // Stage P transposed: Ps[c][r]
#pragma unroll
        for (int j = 0; j < 4; j++)
#pragma unroll
            for (int i = 0; i < 4; i++)
                Ps[(c0 + j) * FSTR + r0 + i] = s[i][j];
        __syncthreads();

        // O += P @ V  (thread owns rows r0..r0+3, d-cols c0..c0+3)
#pragma unroll 8
        for (int j = 0; j < 64; j++) {
            float p[4], vv[4];
            *(float4*)p  = *(float4*)(Ps + j * FSTR + r0);
            *(float4*)vv = *(float4*)(Vs + j * FSTR + c0);
#pragma unroll
            for (int i = 0; i < 4; i++)
#pragma unroll
                for (int d = 0; d < 4; d++)
                    o_acc[i][d] += p[i] * vv[d];
        }
    }

    // Epilogue: normalize by l and write out
#pragma unroll
    for (int i = 0; i < 4; i++) {
        float inv = 1.0f / l_i[i];
        float4 o;
        o.x = o_acc[i][0] * inv;
        o.y = o_acc[i][1] * inv;
        o.z = o_acc[i][2] * inv;
        o.w = o_acc[i][3] * inv;
        *(float4*)(O + ((size_t)(qb * 64 + r0 + i) * BAT + b) * DM + h * DHD + c0) = o;
    }
}

// ---------------------------------------------------------------------------
// kernel_launch: 3 input projections -> flash attention -> output projection
// Inputs (metadata order): query, key, value, mask, Wq, bq, Wk, bk, Wv, bv, Wo, bo
// ---------------------------------------------------------------------------
extern "C" void kernel_launch(void* const* d_in, const int* in_sizes, int n_in,
                              void* d_out, int out_size)
{
    const float* query = (const float*)d_in[0];
    const float* key   = (const float*)d_in[1];
    const float* value = (const float*)d_in[2];
    // d_in[3] = mask (tril causal) — handled analytically in flash_attn
    const float* Wq = (const float*)d_in[4];
    const float* bq = (const float*)d_in[5];
    const float* Wk = (const float*)d_in[6];
    const float* bk = (const float*)d_in[7];
    const float* Wv = (const float*)d_in[8];
    const float* bv = (const float*)d_in[9];
    const float* Wo = (const float*)d_in[10];
    const float* bo = (const float*)d_in[11];
    float* out = (float*)d_out;

    // Opt-in to >48KB dynamic smem for the flash kernel (host-side, idempotent,
    // capture-legal). Done first so it precedes any launch.
    const int fsmem = 4 * 64 * FSTR * (int)sizeof(float);  // 69632 B
    cudaFuncSetAttribute(flash_attn, cudaFuncAttributeMaxDynamicSharedMemorySize, fsmem);

    float *qp, *kp, *vp, *xp;
    cudaGetSymbolAddress((void**)&qp, g_q);
    cudaGetSymbolAddress((void**)&kp, g_k);
    cudaGetSymbolAddress((void**)&vp, g_v);
    cudaGetSymbolAddress((void**)&xp, g_x);

    const dim3 gg(DM / 128, NTOK / 128);   // (8, 32)

    sgemm_bias<<<gg, 256>>>(query, Wq, bq, qp, NTOK, DM, DM);
    sgemm_bias<<<gg, 256>>>(key,   Wk, bk, kp, NTOK, DM, DM);
    sgemm_bias<<<gg, 256>>>(value, Wv, bv, vp, NTOK, DM, DM);

    flash_attn<<<dim3(SEQ / 64, BAT * NH), 256, fsmem>>>(qp, kp, vp, xp);

    sgemm_bias<<<gg, 256>>>(xp, Wo, bo, out, NTOK, DM, DM);
}

// round 5
// speedup vs baseline: 1.3606x; 1.3606x over previous
#include <cuda_runtime.h>
#include <math.h>
#include <stdint.h>

// Problem constants (fixed by the reference)
#define SEQ   2048
#define BAT   2
#define NH    16
#define DHD   64
#define DM    1024
#define NTOK  (SEQ * BAT)   // 4096

// Scratch (allocation-free rule: __device__ globals)
__device__ float g_q[NTOK * DM];
__device__ float g_k[NTOK * DM];
__device__ float g_v[NTOK * DM];
__device__ float g_x[NTOK * DM];

// ---------------------------------------------------------------------------
// tf32 helpers
// ---------------------------------------------------------------------------
__device__ __forceinline__ uint32_t f2tf(float f) {
    uint32_t r;
    asm("cvt.rna.tf32.f32 %0, %1;" : "=r"(r) : "f"(f));
    return r;
}

__device__ __forceinline__ void mma_tf32(float* c, const uint32_t* a, const uint32_t* b) {
    asm volatile(
        "mma.sync.aligned.m16n8k8.row.col.f32.tf32.tf32.f32 "
        "{%0,%1,%2,%3}, {%4,%5,%6,%7}, {%8,%9}, {%0,%1,%2,%3};"
        : "+f"(c[0]), "+f"(c[1]), "+f"(c[2]), "+f"(c[3])
        : "r"(a[0]), "r"(a[1]), "r"(a[2]), "r"(a[3]),
          "r"(b[0]), "r"(b[1]));
}

// ---------------------------------------------------------------------------
// tf32 tensor-core GEMM: C[M,N] = A[M,K] @ B[K,N] + bias[N]  (row-major fp32 io)
// CTA tile 128x128, k-step 16. 256 threads = 8 warps, warp tile 64x32
// (m16n8k8 frags: 4 m-tiles x 4 n-tiles per warp).
// Inputs converted fp32 -> tf32 with round-to-nearest at smem staging
// (truncation would introduce a coherent -2.4e-4 scale bias).
// ---------------------------------------------------------------------------
#define KSTEP 16
#define SSTR  132   // padded smem stride (128 + 4)

__global__ __launch_bounds__(256)
void tf32_gemm_bias(const float* __restrict__ A, const float* __restrict__ B,
                    const float* __restrict__ bias, float* __restrict__ C,
                    int M, int N, int K)
{
    __shared__ uint32_t As[KSTEP][SSTR];   // As[k][m] = tf32(A[bm+m][k0+k])
    __shared__ uint32_t Bs[KSTEP][SSTR];   // Bs[k][n] = tf32(B[k0+k][bn+n])

    const int tid  = threadIdx.x;
    const int lane = tid & 31;
    const int warp = tid >> 5;
    const int wm = (warp & 1) * 64;        // warp row offset (2 warp-rows)
    const int wn = (warp >> 1) * 32;       // warp col offset (4 warp-cols)
    const int bm = blockIdx.y * 128;
    const int bn = blockIdx.x * 128;

    const int g = lane >> 2;               // 0..7
    const int t = lane & 3;                // 0..3

    // Staging assignments
    const int am = tid >> 1;               // 0..127  (A row)
    const int ak = (tid & 1) * 8;          // 0 or 8  (A col base, 8 floats)
    const int bk = tid >> 4;               // 0..15   (B row)
    const int bn8 = (tid & 15) * 8;        // B col base, 8 floats

    const float* Ag = A + (size_t)(bm + am) * K + ak;
    const float* Bg = B + (size_t)bk * N + bn + bn8;

    float acc[4][4][4];
#pragma unroll
    for (int i = 0; i < 4; i++)
#pragma unroll
        for (int j = 0; j < 4; j++)
#pragma unroll
            for (int r = 0; r < 4; r++) acc[i][j][r] = 0.0f;

    // Prefetch first stage
    float4 pa0 = *(const float4*)(Ag);
    float4 pa1 = *(const float4*)(Ag + 4);
    float4 pb0 = *(const float4*)(Bg);
    float4 pb1 = *(const float4*)(Bg + 4);

    for (int k0 = 0; k0 < K; k0 += KSTEP) {
        // Stage (with RNA conversion to tf32)
        As[ak + 0][am] = f2tf(pa0.x);
        As[ak + 1][am] = f2tf(pa0.y);
        As[ak + 2][am] = f2tf(pa0.z);
        As[ak + 3][am] = f2tf(pa0.w);
        As[ak + 4][am] = f2tf(pa1.x);
        As[ak + 5][am] = f2tf(pa1.y);
        As[ak + 6][am] = f2tf(pa1.z);
        As[ak + 7][am] = f2tf(pa1.w);
        {
            uint4 u0, u1;
            u0.x = f2tf(pb0.x); u0.y = f2tf(pb0.y); u0.z = f2tf(pb0.z); u0.w = f2tf(pb0.w);
            u1.x = f2tf(pb1.x); u1.y = f2tf(pb1.y); u1.z = f2tf(pb1.z); u1.w = f2tf(pb1.w);
            *(uint4*)(&Bs[bk][bn8])     = u0;
            *(uint4*)(&Bs[bk][bn8 + 4]) = u1;
        }
        __syncthreads();

        // Prefetch next stage
        if (k0 + KSTEP < K) {
            pa0 = *(const float4*)(Ag + k0 + KSTEP);
            pa1 = *(const float4*)(Ag + k0 + KSTEP + 4);
            pb0 = *(const float4*)(Bg + (size_t)(k0 + KSTEP) * N);
            pb1 = *(const float4*)(Bg + (size_t)(k0 + KSTEP) * N + 4);
        }

        // Two k=8 MMA steps
#pragma unroll
        for (int ks = 0; ks < KSTEP; ks += 8) {
            uint32_t a[4][4], b[4][2];
#pragma unroll
            for (int mt = 0; mt < 4; mt++) {
                const int row = wm + mt * 16 + g;
                a[mt][0] = As[ks + t][row];
                a[mt][1] = As[ks + t][row + 8];
                a[mt][2] = As[ks + t + 4][row];
                a[mt][3] = As[ks + t + 4][row + 8];
            }
#pragma unroll
            for (int nt = 0; nt < 4; nt++) {
                const int col = wn + nt * 8 + g;
                b[nt][0] = Bs[ks + t][col];
                b[nt][1] = Bs[ks + t + 4][col];
            }
#pragma unroll
            for (int mt = 0; mt < 4; mt++)
#pragma unroll
                for (int nt = 0; nt < 4; nt++)
                    mma_tf32(acc[mt][nt], a[mt], b[nt]);
        }
        __syncthreads();
    }

    // Epilogue: c0/c1 at (row, col..col+1), c2/c3 at (row+8, col..col+1)
#pragma unroll
    for (int mt = 0; mt < 4; mt++) {
#pragma unroll
        for (int nt = 0; nt < 4; nt++) {
            const int row = bm + wm + mt * 16 + g;
            const int col = bn + wn + nt * 8 + t * 2;
            float b0 = bias[col], b1 = bias[col + 1];
            float2 v0 = make_float2(acc[mt][nt][0] + b0, acc[mt][nt][1] + b1);
            float2 v1 = make_float2(acc[mt][nt][2] + b0, acc[mt][nt][3] + b1);
            *(float2*)(C + (size_t)row * N + col)       = v0;
            *(float2*)(C + (size_t)(row + 8) * N + col) = v1;
        }
    }
}

// ---------------------------------------------------------------------------
// Flash attention (causal), fp32, online softmax.  (unchanged from R3)
// Layout of Q/K/V/X scratch: [(s*BAT + b) * DM + h*DHD + d]
// grid: (SEQ/64, BAT*NH), block: 256
// ---------------------------------------------------------------------------
#define FSTR 68   // padded smem row stride

__global__ __launch_bounds__(256)
void flash_attn(const float* __restrict__ Q, const float* __restrict__ K,
                const float* __restrict__ V, float* __restrict__ O)
{
    extern __shared__ float sm[];
    float* Qs = sm;                 // [d][r] : Qs[d*FSTR + r]
    float* Ks = Qs + 64 * FSTR;     // [d][c] : Ks[d*FSTR + c]
    float* Vs = Ks + 64 * FSTR;     // [j][d] : Vs[j*FSTR + d]
    float* Ps = Vs + 64 * FSTR;     // [c][r] : Ps[c*FSTR + r]

    const int qb = blockIdx.x;          // query tile (0..31)
    const int bh = blockIdx.y;          // 0..31
    const int b  = bh >> 4;
    const int h  = bh & 15;
    const int tid = threadIdx.x;
    const int ty = tid >> 4;            // 0..15 -> rows ty*4..+3
    const int tx = tid & 15;            // 0..15 -> cols tx*4..+3
    const int r0 = ty * 4;
    const int c0 = tx * 4;

    // Load Q tile (64 rows x 64 d), transposed into Qs[d][r]
#pragma unroll
    for (int it = 0; it < 4; it++) {
        int i = tid + it * 256;
        int r = i >> 4, d4 = (i & 15) * 4;
        const float* p = Q + ((size_t)(qb * 64 + r) * BAT + b) * DM + h * DHD + d4;
        float4 v = *(const float4*)p;
        Qs[(d4 + 0) * FSTR + r] = v.x;
        Qs[(d4 + 1) * FSTR + r] = v.y;
        Qs[(d4 + 2) * FSTR + r] = v.z;
        Qs[(d4 + 3) * FSTR + r] = v.w;
    }

    float m_i[4], l_i[4], o_acc[4][4];
#pragma unroll
    for (int i = 0; i < 4; i++) {
        m_i[i] = -1e30f;
        l_i[i] = 0.0f;
#pragma unroll
        for (int d = 0; d < 4; d++) o_acc[i][d] = 0.0f;
    }
    const float scale = 0.125f;  // 1/sqrt(64)

    for (int kb = 0; kb <= qb; kb++) {
        __syncthreads();  // prior iter readers done (also fences Q stores on kb=0)

        // Load K (transposed) and V tiles
#pragma unroll
        for (int it = 0; it < 4; it++) {
            int i = tid + it * 256;
            int r = i >> 4, d4 = (i & 15) * 4;
            size_t gidx = ((size_t)(kb * 64 + r) * BAT + b) * DM + h * DHD + d4;
            float4 kv = *(const float4*)(K + gidx);
            Ks[(d4 + 0) * FSTR + r] = kv.x;
            Ks[(d4 + 1) * FSTR + r] = kv.y;
            Ks[(d4 + 2) * FSTR + r] = kv.z;
            Ks[(d4 + 3) * FSTR + r] = kv.w;
            float4 vv = *(const float4*)(V + gidx);
            *(float4*)(Vs + (size_t)r * FSTR + d4) = vv;
        }
        __syncthreads();

        // S = Q @ K^T (4x4 per thread)
        float s[4][4];
#pragma unroll
        for (int i = 0; i < 4; i++)
#pragma unroll
            for (int j = 0; j < 4; j++) s[i][j] = 0.0f;

#pragma unroll 8
        for (int d = 0; d < 64; d++) {
            float a[4], bb[4];
            *(float4*)a  = *(float4*)(Qs + d * FSTR + r0);
            *(float4*)bb = *(float4*)(Ks + d * FSTR + c0);
#pragma unroll
            for (int i = 0; i < 4; i++)
#pragma unroll
                for (int j = 0; j < 4; j++)
                    s[i][j] += a[i] * bb[j];
        }

        // scale + causal mask (only diagonal block partially masked)
        const bool diag = (kb == qb);
#pragma unroll
        for (int i = 0; i < 4; i++)
#pragma unroll
            for (int j = 0; j < 4; j++) {
                s[i][j] *= scale;
                if (diag && (c0 + j) > (r0 + i)) s[i][j] = -1e30f;
            }

        // Online softmax: rowwise max + sum via 16-lane shfl groups
#pragma unroll
        for (int i = 0; i < 4; i++) {
            float mx = fmaxf(fmaxf(s[i][0], s[i][1]), fmaxf(s[i][2], s[i][3]));
            mx = fmaxf(mx, __shfl_xor_sync(0xffffffffu, mx, 1));
            mx = fmaxf(mx, __shfl_xor_sync(0xffffffffu, mx, 2));
            mx = fmaxf(mx, __shfl_xor_sync(0xffffffffu, mx, 4));
            mx = fmaxf(mx, __shfl_xor_sync(0xffffffffu, mx, 8));
            float m_new = fmaxf(m_i[i], mx);
            float corr = __expf(m_i[i] - m_new);
            float rs = 0.0f;
#pragma unroll
            for (int j = 0; j < 4; j++) {
                float p = __expf(s[i][j] - m_new);
                s[i][j] = p;
                rs += p;
            }
            rs += __shfl_xor_sync(0xffffffffu, rs, 1);
            rs += __shfl_xor_sync(0xffffffffu, rs, 2);
            rs += __shfl_xor_sync(0xffffffffu, rs, 4);
            rs += __shfl_xor_sync(0xffffffffu, rs, 8);
            l_i[i] = l_i[i] * corr + rs;
            m_i[i] = m_new;
#pragma unroll
            for (int d = 0; d < 4; d++) o_acc[i][d] *= corr;
        }

        // Stage P transposed: Ps[c][r]
#pragma unroll
        for (int j = 0; j < 4; j++)
#pragma unroll
            for (int i = 0; i < 4; i++)
                Ps[(c0 + j) * FSTR + r0 + i] = s[i][j];
        __syncthreads();

        // O += P @ V  (thread owns rows r0..r0+3, d-cols c0..c0+3)
#pragma unroll 8
        for (int j = 0; j < 64; j++) {
            float p[4], vv[4];
            *(float4*)p  = *(float4*)(Ps + j * FSTR + r0);
            *(float4*)vv = *(float4*)(Vs + j * FSTR + c0);
#pragma unroll
            for (int i = 0; i < 4; i++)
#pragma unroll
                for (int d = 0; d < 4; d++)
                    o_acc[i][d] += p[i] * vv[d];
        }
    }

    // Epilogue: normalize by l and write out
#pragma unroll
    for (int i = 0; i < 4; i++) {
        float inv = 1.0f / l_i[i];
        float4 o;
        o.x = o_acc[i][0] * inv;
        o.y = o_acc[i][1] * inv;
        o.z = o_acc[i][2] * inv;
        o.w = o_acc[i][3] * inv;
        *(float4*)(O + ((size_t)(qb * 64 + r0 + i) * BAT + b) * DM + h * DHD + c0) = o;
    }
}

// ---------------------------------------------------------------------------
// kernel_launch: 3 input projections -> flash attention -> output projection
// Inputs: query, key, value, mask, Wq, bq, Wk, bk, Wv, bv, Wo, bo
// ---------------------------------------------------------------------------
extern "C" void kernel_launch(void* const* d_in, const int* in_sizes, int n_in,
                              void* d_out, int out_size)
{
    const float* query = (const float*)d_in[0];
    const float* key   = (const float*)d_in[1];
    const float* value = (const float*)d_in[2];
    // d_in[3] = mask (tril causal) — handled analytically in flash_attn
    const float* Wq = (const float*)d_in[4];
    const float* bq = (const float*)d_in[5];
    const float* Wk = (const float*)d_in[6];
    const float* bk = (const float*)d_in[7];
    const float* Wv = (const float*)d_in[8];
    const float* bv = (const float*)d_in[9];
    const float* Wo = (const float*)d_in[10];
    const float* bo = (const float*)d_in[11];
    float* out = (float*)d_out;

    const int fsmem = 4 * 64 * FSTR * (int)sizeof(float);  // 69632 B
    cudaFuncSetAttribute(flash_attn, cudaFuncAttributeMaxDynamicSharedMemorySize, fsmem);

    float *qp, *kp, *vp, *xp;
    cudaGetSymbolAddress((void**)&qp, g_q);
    cudaGetSymbolAddress((void**)&kp, g_k);
    cudaGetSymbolAddress((void**)&vp, g_v);
    cudaGetSymbolAddress((void**)&xp, g_x);

    const dim3 gg(DM / 128, NTOK / 128);   // (8, 32)

    tf32_gemm_bias<<<gg, 256>>>(query, Wq, bq, qp, NTOK, DM, DM);
    tf32_gemm_bias<<<gg, 256>>>(key,   Wk, bk, kp, NTOK, DM, DM);
    tf32_gemm_bias<<<gg, 256>>>(value, Wv, bv, vp, NTOK, DM, DM);

    flash_attn<<<dim3(SEQ / 64, BAT * NH), 256, fsmem>>>(qp, kp, vp, xp);

    tf32_gemm_bias<<<gg, 256>>>(xp, Wo, bo, out, NTOK, DM, DM);
}

// round 6
// speedup vs baseline: 2.4321x; 1.7875x over previous
#include <cuda_runtime.h>
#include <cuda_fp16.h>
#include <math.h>
#include <stdint.h>

// Problem constants (fixed by the reference)
#define SEQ   2048
#define BAT   2
#define NH    16
#define DHD   64
#define DM    1024
#define NTOK  (SEQ * BAT)   // 4096

// Scratch (allocation-free rule: __device__ globals)
__device__ float g_q[NTOK * DM];
__device__ float g_k[NTOK * DM];
__device__ float g_v[NTOK * DM];
__device__ float g_x[NTOK * DM];

// ---------------------------------------------------------------------------
// mma helpers
// ---------------------------------------------------------------------------
__device__ __forceinline__ uint32_t f2tf(float f) {
    uint32_t r;
    asm("cvt.rna.tf32.f32 %0, %1;" : "=r"(r) : "f"(f));
    return r;
}

__device__ __forceinline__ void mma_tf32(float* c, const uint32_t* a,
                                         uint32_t b0, uint32_t b1) {
    asm volatile(
        "mma.sync.aligned.m16n8k8.row.col.f32.tf32.tf32.f32 "
        "{%0,%1,%2,%3}, {%4,%5,%6,%7}, {%8,%9}, {%0,%1,%2,%3};"
        : "+f"(c[0]), "+f"(c[1]), "+f"(c[2]), "+f"(c[3])
        : "r"(a[0]), "r"(a[1]), "r"(a[2]), "r"(a[3]), "r"(b0), "r"(b1));
}

__device__ __forceinline__ void mma_f16(float* c, uint32_t a0, uint32_t a1,
                                        uint32_t a2, uint32_t a3,
                                        uint32_t b0, uint32_t b1) {
    asm volatile(
        "mma.sync.aligned.m16n8k16.row.col.f32.f16.f16.f32 "
        "{%0,%1,%2,%3}, {%4,%5,%6,%7}, {%8,%9}, {%0,%1,%2,%3};"
        : "+f"(c[0]), "+f"(c[1]), "+f"(c[2]), "+f"(c[3])
        : "r"(a0), "r"(a1), "r"(a2), "r"(a3), "r"(b0), "r"(b1));
}

// ---------------------------------------------------------------------------
// tf32 tensor-core GEMM: C[M,N] = A[M,K] @ B[K,N] + bias[N]  (unchanged R4)
// ---------------------------------------------------------------------------
#define KSTEP 16
#define SSTR  132

__global__ __launch_bounds__(256)
void tf32_gemm_bias(const float* __restrict__ A, const float* __restrict__ B,
                    const float* __restrict__ bias, float* __restrict__ C,
                    int M, int N, int K)
{
    __shared__ uint32_t As[KSTEP][SSTR];
    __shared__ uint32_t Bs[KSTEP][SSTR];

    const int tid  = threadIdx.x;
    const int lane = tid & 31;
    const int warp = tid >> 5;
    const int wm = (warp & 1) * 64;
    const int wn = (warp >> 1) * 32;
    const int bm = blockIdx.y * 128;
    const int bn = blockIdx.x * 128;

    const int g = lane >> 2;
    const int t = lane & 3;

    const int am = tid >> 1;
    const int ak = (tid & 1) * 8;
    const int bk = tid >> 4;
    const int bn8 = (tid & 15) * 8;

    const float* Ag = A + (size_t)(bm + am) * K + ak;
    const float* Bg = B + (size_t)bk * N + bn + bn8;

    float acc[4][4][4];
#pragma unroll
    for (int i = 0; i < 4; i++)
#pragma unroll
        for (int j = 0; j < 4; j++)
#pragma unroll
            for (int r = 0; r < 4; r++) acc[i][j][r] = 0.0f;

    float4 pa0 = *(const float4*)(Ag);
    float4 pa1 = *(const float4*)(Ag + 4);
    float4 pb0 = *(const float4*)(Bg);
    float4 pb1 = *(const float4*)(Bg + 4);

    for (int k0 = 0; k0 < K; k0 += KSTEP) {
        As[ak + 0][am] = f2tf(pa0.x);
        As[ak + 1][am] = f2tf(pa0.y);
        As[ak + 2][am] = f2tf(pa0.z);
        As[ak + 3][am] = f2tf(pa0.w);
        As[ak + 4][am] = f2tf(pa1.x);
        As[ak + 5][am] = f2tf(pa1.y);
        As[ak + 6][am] = f2tf(pa1.z);
        As[ak + 7][am] = f2tf(pa1.w);
        {
            uint4 u0, u1;
            u0.x = f2tf(pb0.x); u0.y = f2tf(pb0.y); u0.z = f2tf(pb0.z); u0.w = f2tf(pb0.w);
            u1.x = f2tf(pb1.x); u1.y = f2tf(pb1.y); u1.z = f2tf(pb1.z); u1.w = f2tf(pb1.w);
            *(uint4*)(&Bs[bk][bn8])     = u0;
            *(uint4*)(&Bs[bk][bn8 + 4]) = u1;
        }
        __syncthreads();

        if (k0 + KSTEP < K) {
            pa0 = *(const float4*)(Ag + k0 + KSTEP);
            pa1 = *(const float4*)(Ag + k0 + KSTEP + 4);
            pb0 = *(const float4*)(Bg + (size_t)(k0 + KSTEP) * N);
            pb1 = *(const float4*)(Bg + (size_t)(k0 + KSTEP) * N + 4);
        }

#pragma unroll
        for (int ks = 0; ks < KSTEP; ks += 8) {
            uint32_t a[4][4], b[4][2];
#pragma unroll
            for (int mt = 0; mt < 4; mt++) {
                const int row = wm + mt * 16 + g;
                a[mt][0] = As[ks + t][row];
                a[mt][1] = As[ks + t][row + 8];
                a[mt][2] = As[ks + t + 4][row];
                a[mt][3] = As[ks + t + 4][row + 8];
            }
#pragma unroll
            for (int nt = 0; nt < 4; nt++) {
                const int col = wn + nt * 8 + g;
                b[nt][0] = Bs[ks + t][col];
                b[nt][1] = Bs[ks + t + 4][col];
            }
#pragma unroll
            for (int mt = 0; mt < 4; mt++)
#pragma unroll
                for (int nt = 0; nt < 4; nt++)
                    mma_tf32(acc[mt][nt], a[mt], b[nt][0], b[nt][1]);
        }
        __syncthreads();
    }

#pragma unroll
    for (int mt = 0; mt < 4; mt++) {
#pragma unroll
        for (int nt = 0; nt < 4; nt++) {
            const int row = bm + wm + mt * 16 + g;
            const int col = bn + wn + nt * 8 + t * 2;
            float b0 = bias[col], b1 = bias[col + 1];
            float2 v0 = make_float2(acc[mt][nt][0] + b0, acc[mt][nt][1] + b1);
            float2 v1 = make_float2(acc[mt][nt][2] + b0, acc[mt][nt][3] + b1);
            *(float2*)(C + (size_t)row * N + col)       = v0;
            *(float2*)(C + (size_t)(row + 8) * N + col) = v1;
        }
    }
}

// ---------------------------------------------------------------------------
// Flash attention (causal) on tensor cores.
// Br=128 q-rows x Bc=64 k-cols per CTA, 256 threads (8 warps x 16 rows).
// QK^T: tf32 m16n8k8 (Q frags in regs, K staged swizzled in smem).
// P*V : f16 m16n8k16 (P stays in registers via FA2 fragment-layout match,
//                     V staged transposed as half2 pairs).
// grid: (SEQ/128, BAT*NH)
// ---------------------------------------------------------------------------
#define KSTR 72   // Ks stride in floats
#define VSTR 36   // Vs stride in half2

// swizzled Ks index: conflict-free fragment loads, <=2-way staging stores
__device__ __forceinline__ int KIDX(int d, int c) {
    return d * KSTR + (c ^ (4 * ((d >> 2) & 7)));
}

__global__ __launch_bounds__(256)
void flash_attn_mma(const float* __restrict__ Q, const float* __restrict__ K,
                    const float* __restrict__ V, float* __restrict__ O)
{
    __shared__ uint32_t Ks[64 * KSTR];   // [d][c] tf32 (swizzled)
    __shared__ __half2  Vs[64 * VSTR];   // [d][j2] = (V[2j2][d], V[2j2+1][d])

    const int qb = (int)(gridDim.x - 1 - blockIdx.x);  // heavy tiles first
    const int bh = blockIdx.y;
    const int b  = bh >> 4;
    const int h  = bh & 15;
    const int tid  = threadIdx.x;
    const int lane = tid & 31;
    const int warp = tid >> 5;
    const int g = lane >> 2;
    const int t = lane & 3;
    const int wr0 = warp * 16;

    const size_t rowstride = (size_t)BAT * DM;
    const size_t headoff = (size_t)b * DM + h * DHD;

    // ---- Q fragments in registers (rows wr0+g, wr0+g+8; tf32) ----
    uint32_t qf[8][4];
    {
        const float* Qr0 = Q + (size_t)(qb * 128 + wr0 + g) * rowstride + headoff;
        const float* Qr8 = Qr0 + 8 * rowstride;
#pragma unroll
        for (int ks = 0; ks < 8; ks++) {
            qf[ks][0] = f2tf(Qr0[8 * ks + t]);
            qf[ks][1] = f2tf(Qr8[8 * ks + t]);
            qf[ks][2] = f2tf(Qr0[8 * ks + t + 4]);
            qf[ks][3] = f2tf(Qr8[8 * ks + t + 4]);
        }
    }

    float o[8][4];
#pragma unroll
    for (int nt = 0; nt < 8; nt++)
#pragma unroll
        for (int r = 0; r < 4; r++) o[nt][r] = 0.0f;
    float m0 = -1e30f, m1 = -1e30f, l0 = 0.0f, l1 = 0.0f;

    const int kbmax = 2 * qb + 1;
    for (int kb = 0; kb <= kbmax; kb++) {
        __syncthreads();
        // ---- stage K tile: Ks[d][c] = tf32(K[kb*64+c][d]) ----
#pragma unroll
        for (int it = 0; it < 4; it++) {
            int i = tid + it * 256;          // 0..1023
            int c = i >> 4;                  // 0..63
            int d4 = (i & 15) * 4;
            const float* p = K + (size_t)(kb * 64 + c) * rowstride + headoff + d4;
            float4 kv = *(const float4*)p;
            Ks[KIDX(d4 + 0, c)] = f2tf(kv.x);
            Ks[KIDX(d4 + 1, c)] = f2tf(kv.y);
            Ks[KIDX(d4 + 2, c)] = f2tf(kv.z);
            Ks[KIDX(d4 + 3, c)] = f2tf(kv.w);
        }
        // ---- stage V tile transposed as half2 pairs ----
#pragma unroll
        for (int it = 0; it < 2; it++) {
            int i = tid + it * 256;          // 0..511
            int j2 = i >> 4;                 // 0..31
            int d4 = (i & 15) * 4;
            const float* p0 = V + (size_t)(kb * 64 + 2 * j2) * rowstride + headoff + d4;
            const float* p1 = p0 + rowstride;
            float4 v0 = *(const float4*)p0;
            float4 v1 = *(const float4*)p1;
            Vs[(d4 + 0) * VSTR + j2] = __floats2half2_rn(v0.x, v1.x);
            Vs[(d4 + 1) * VSTR + j2] = __floats2half2_rn(v0.y, v1.y);
            Vs[(d4 + 2) * VSTR + j2] = __floats2half2_rn(v0.z, v1.z);
            Vs[(d4 + 3) * VSTR + j2] = __floats2half2_rn(v0.w, v1.w);
        }
        __syncthreads();

        // ---- S = Q @ K^T ----
        float s[8][4];
#pragma unroll
        for (int nt = 0; nt < 8; nt++)
#pragma unroll
            for (int r = 0; r < 4; r++) s[nt][r] = 0.0f;

#pragma unroll
        for (int ks = 0; ks < 8; ks++) {
#pragma unroll
            for (int nt = 0; nt < 8; nt++) {
                uint32_t b0 = Ks[KIDX(8 * ks + t,     nt * 8 + g)];
                uint32_t b1 = Ks[KIDX(8 * ks + t + 4, nt * 8 + g)];
                mma_tf32(s[nt], qf[ks], b0, b1);
            }
        }

        // ---- scale (+ causal mask on diagonal-crossing warps) ----
        const int rg  = qb * 128 + wr0 + g;
        const int rg8 = rg + 8;
        if (kb * 64 + 63 > rg - (int)g + 0 + wr0 - wr0 && (kb * 64 + 63 > qb * 128 + wr0)) {
#pragma unroll
            for (int nt = 0; nt < 8; nt++) {
                int c0 = kb * 64 + nt * 8 + 2 * t;
                s[nt][0] = (c0     > rg ) ? -1e30f : s[nt][0] * 0.125f;
                s[nt][1] = (c0 + 1 > rg ) ? -1e30f : s[nt][1] * 0.125f;
                s[nt][2] = (c0     > rg8) ? -1e30f : s[nt][2] * 0.125f;
                s[nt][3] = (c0 + 1 > rg8) ? -1e30f : s[nt][3] * 0.125f;
            }
        } else {
#pragma unroll
            for (int nt = 0; nt < 8; nt++)
#pragma unroll
                for (int r = 0; r < 4; r++) s[nt][r] *= 0.125f;
        }

        // ---- online softmax (rows g and g+8) ----
        float mx0 = -1e30f, mx1 = -1e30f;
#pragma unroll
        for (int nt = 0; nt < 8; nt++) {
            mx0 = fmaxf(mx0, fmaxf(s[nt][0], s[nt][1]));
            mx1 = fmaxf(mx1, fmaxf(s[nt][2], s[nt][3]));
        }
        mx0 = fmaxf(mx0, __shfl_xor_sync(0xffffffffu, mx0, 1));
        mx0 = fmaxf(mx0, __shfl_xor_sync(0xffffffffu, mx0, 2));
        mx1 = fmaxf(mx1, __shfl_xor_sync(0xffffffffu, mx1, 1));
        mx1 = fmaxf(mx1, __shfl_xor_sync(0xffffffffu, mx1, 2));

        float mn0 = fmaxf(m0, mx0), mn1 = fmaxf(m1, mx1);
        float corr0 = __expf(m0 - mn0), corr1 = __expf(m1 - mn1);
        m0 = mn0; m1 = mn1;

        float rs0 = 0.0f, rs1 = 0.0f;
        uint32_t ph[8], ph8[8];
#pragma unroll
        for (int nt = 0; nt < 8; nt++) {
            float p0 = __expf(s[nt][0] - mn0);
            float p1 = __expf(s[nt][1] - mn0);
            float p2 = __expf(s[nt][2] - mn1);
            float p3 = __expf(s[nt][3] - mn1);
            rs0 += p0 + p1;
            rs1 += p2 + p3;
            __half2 h0 = __floats2half2_rn(p0, p1);
            __half2 h1 = __floats2half2_rn(p2, p3);
            ph[nt]  = *(uint32_t*)&h0;
            ph8[nt] = *(uint32_t*)&h1;
        }
        rs0 += __shfl_xor_sync(0xffffffffu, rs0, 1);
        rs0 += __shfl_xor_sync(0xffffffffu, rs0, 2);
        rs1 += __shfl_xor_sync(0xffffffffu, rs1, 1);
        rs1 += __shfl_xor_sync(0xffffffffu, rs1, 2);
        l0 = l0 * corr0 + rs0;
        l1 = l1 * corr1 + rs1;

#pragma unroll
        for (int nt = 0; nt < 8; nt++) {
            o[nt][0] *= corr0; o[nt][1] *= corr0;
            o[nt][2] *= corr1; o[nt][3] *= corr1;
        }

        // ---- O += P @ V  (f16 mma, P from registers) ----
#pragma unroll
        for (int kk = 0; kk < 4; kk++) {
#pragma unroll
            for (int nt = 0; nt < 8; nt++) {
                const __half2* vp = &Vs[(nt * 8 + g) * VSTR + kk * 8 + t];
                uint32_t b0 = *(const uint32_t*)(vp);
                uint32_t b1 = *(const uint32_t*)(vp + 4);
                mma_f16(o[nt], ph[2 * kk], ph8[2 * kk],
                        ph[2 * kk + 1], ph8[2 * kk + 1], b0, b1);
            }
        }
    }

    // ---- epilogue: normalize, write ----
    float inv0 = 1.0f / l0, inv1 = 1.0f / l1;
    float* Or0 = O + (size_t)(qb * 128 + wr0 + g) * rowstride + headoff;
    float* Or8 = Or0 + 8 * rowstride;
#pragma unroll
    for (int nt = 0; nt < 8; nt++) {
        *(float2*)(Or0 + nt * 8 + 2 * t) = make_float2(o[nt][0] * inv0, o[nt][1] * inv0);
        *(float2*)(Or8 + nt * 8 + 2 * t) = make_float2(o[nt][2] * inv1, o[nt][3] * inv1);
    }
}

// ---------------------------------------------------------------------------
// kernel_launch
// Inputs: query, key, value, mask, Wq, bq, Wk, bk, Wv, bv, Wo, bo
// ---------------------------------------------------------------------------
extern "C" void kernel_launch(void* const* d_in, const int* in_sizes, int n_in,
                              void* d_out, int out_size)
{
    const float* query = (const float*)d_in[0];
    const float* key   = (const float*)d_in[1];
    const float* value = (const float*)d_in[2];
    // d_in[3] = mask (tril causal) — handled analytically in flash_attn_mma
    const float* Wq = (const float*)d_in[4];
    const float* bq = (const float*)d_in[5];
    const float* Wk = (const float*)d_in[6];
    const float* bk = (const float*)d_in[7];
    const float* Wv = (const float*)d_in[8];
    const float* bv = (const float*)d_in[9];
    const float* Wo = (const float*)d_in[10];
    const float* bo = (const float*)d_in[11];
    float* out = (float*)d_out;

    float *qp, *kp, *vp, *xp;
    cudaGetSymbolAddress((void**)&qp, g_q);
    cudaGetSymbolAddress((void**)&kp, g_k);
    cudaGetSymbolAddress((void**)&vp, g_v);
    cudaGetSymbolAddress((void**)&xp, g_x);

    const dim3 gg(DM / 128, NTOK / 128);   // (8, 32)

    tf32_gemm_bias<<<gg, 256>>>(query, Wq, bq, qp, NTOK, DM, DM);
    tf32_gemm_bias<<<gg, 256>>>(key,   Wk, bk, kp, NTOK, DM, DM);
    tf32_gemm_bias<<<gg, 256>>>(value, Wv, bv, vp, NTOK, DM, DM);

    flash_attn_mma<<<dim3(SEQ / 128, BAT * NH), 256>>>(qp, kp, vp, xp);

    tf32_gemm_bias<<<gg, 256>>>(xp, Wo, bo, out, NTOK, DM, DM);
}

// round 7
// speedup vs baseline: 2.6915x; 1.1066x over previous
#include <cuda_runtime.h>
#include <cuda_fp16.h>
#include <math.h>
#include <stdint.h>

// Problem constants (fixed by the reference)
#define SEQ   2048
#define BAT   2
#define NH    16
#define DHD   64
#define DM    1024
#define NTOK  (SEQ * BAT)   // 4096

// Scratch (allocation-free rule: __device__ globals)
__device__ float g_q[NTOK * DM];
__device__ float g_k[NTOK * DM];
__device__ float g_v[NTOK * DM];
__device__ float g_x[NTOK * DM];

// ---------------------------------------------------------------------------
// mma helpers
// ---------------------------------------------------------------------------
__device__ __forceinline__ uint32_t f2tf(float f) {
    uint32_t r;
    asm("cvt.rna.tf32.f32 %0, %1;" : "=r"(r) : "f"(f));
    return r;
}

__device__ __forceinline__ void mma_tf32(float* c, const uint32_t* a,
                                         uint32_t b0, uint32_t b1) {
    asm volatile(
        "mma.sync.aligned.m16n8k8.row.col.f32.tf32.tf32.f32 "
        "{%0,%1,%2,%3}, {%4,%5,%6,%7}, {%8,%9}, {%0,%1,%2,%3};"
        : "+f"(c[0]), "+f"(c[1]), "+f"(c[2]), "+f"(c[3])
        : "r"(a[0]), "r"(a[1]), "r"(a[2]), "r"(a[3]), "r"(b0), "r"(b1));
}

__device__ __forceinline__ void mma_f16(float* c, uint32_t a0, uint32_t a1,
                                        uint32_t a2, uint32_t a3,
                                        uint32_t b0, uint32_t b1) {
    asm volatile(
        "mma.sync.aligned.m16n8k16.row.col.f32.f16.f16.f32 "
        "{%0,%1,%2,%3}, {%4,%5,%6,%7}, {%8,%9}, {%0,%1,%2,%3};"
        : "+f"(c[0]), "+f"(c[1]), "+f"(c[2]), "+f"(c[3])
        : "r"(a0), "r"(a1), "r"(a2), "r"(a3), "r"(b0), "r"(b1));
}

// ---------------------------------------------------------------------------
// fp16 tensor-core GEMM: C[M,N] = A[M,K] @ B[K,N] + bias[N]  (fp32 io)
// fp16 has the same 11-bit mantissa as tf32 -> identical accuracy, 2x rate.
// CTA tile 128x128, k-step 16 (one m16n8k16 per warp-tile per step),
// double-buffered smem (one __syncthreads per k-step), 256 threads = 8 warps,
// warp tile 64x32 (4 m-tiles x 4 n-tiles).
// Up to 3 independent GEMMs in one launch via blockIdx.z (tail-wave sharing).
// ---------------------------------------------------------------------------
#define ASTR2 10    // smem stride in half2 units (8 data + 2 pad)

struct GemmArgs {
    const float* A[3];
    const float* W[3];
    const float* bias[3];
    float*       C[3];
};

__global__ __launch_bounds__(256)
void h16_gemm_bias(GemmArgs ga, int M, int N, int K)
{
    const int z = blockIdx.z;
    const float* __restrict__ A    = ga.A[z];
    const float* __restrict__ B    = ga.W[z];
    const float* __restrict__ bias = ga.bias[z];
    float*       __restrict__ C    = ga.C[z];

    // As2[buf][m][j]: half2 = A[m][2j],A[m][2j+1]   (j = 0..7)
    // Bs2[buf][n][j]: half2 = B[2j][n],B[2j+1][n]
    __shared__ uint32_t As2[2][128 * ASTR2];
    __shared__ uint32_t Bs2[2][128 * ASTR2];

    const int tid  = threadIdx.x;
    const int lane = tid & 31;
    const int warp = tid >> 5;
    const int wm = (warp & 1) * 64;
    const int wn = (warp >> 1) * 32;
    const int bm = blockIdx.y * 128;
    const int bn = blockIdx.x * 128;
    const int g = lane >> 2;
    const int t = lane & 3;

    // staging assignments
    const int am  = tid >> 1;          // A row 0..127
    const int ak  = (tid & 1) * 8;     // A col base (8 floats)
    const int bj  = tid & 7;           // B k-pair index (rows 2bj, 2bj+1)
    const int bn4 = (tid >> 3) * 4;    // B col base (4 floats) 0..124

    const float* Ag = A + (size_t)(bm + am) * K + ak;
    const float* Bg = B + (size_t)(2 * bj) * N + bn + bn4;

    float acc[4][4][4];
#pragma unroll
    for (int i = 0; i < 4; i++)
#pragma unroll
        for (int j = 0; j < 4; j++)
#pragma unroll
            for (int r = 0; r < 4; r++) acc[i][j][r] = 0.0f;

    // prefetch k0 = 0
    float4 pa0 = *(const float4*)(Ag);
    float4 pa1 = *(const float4*)(Ag + 4);
    float4 pb0 = *(const float4*)(Bg);
    float4 pb1 = *(const float4*)(Bg + N);

    // stage buffer 0
    {
        __half2 h0 = __floats2half2_rn(pa0.x, pa0.y);
        __half2 h1 = __floats2half2_rn(pa0.z, pa0.w);
        __half2 h2 = __floats2half2_rn(pa1.x, pa1.y);
        __half2 h3 = __floats2half2_rn(pa1.z, pa1.w);
        uint32_t* ad = &As2[0][am * ASTR2 + (ak >> 1)];
        ad[0] = *(uint32_t*)&h0; ad[1] = *(uint32_t*)&h1;
        ad[2] = *(uint32_t*)&h2; ad[3] = *(uint32_t*)&h3;
        __half2 w0 = __floats2half2_rn(pb0.x, pb1.x);
        __half2 w1 = __floats2half2_rn(pb0.y, pb1.y);
        __half2 w2 = __floats2half2_rn(pb0.z, pb1.z);
        __half2 w3 = __floats2half2_rn(pb0.w, pb1.w);
        Bs2[0][(bn4 + 0) * ASTR2 + bj] = *(uint32_t*)&w0;
        Bs2[0][(bn4 + 1) * ASTR2 + bj] = *(uint32_t*)&w1;
        Bs2[0][(bn4 + 2) * ASTR2 + bj] = *(uint32_t*)&w2;
        Bs2[0][(bn4 + 3) * ASTR2 + bj] = *(uint32_t*)&w3;
    }
    __syncthreads();

    const int NIT = K / 16;   // 64
    int cur = 0;
    for (int it = 0; it < NIT; it++) {
        // prefetch next stage
        if (it + 1 < NIT) {
            const float* Agn = Ag + (it + 1) * 16;
            pa0 = *(const float4*)(Agn);
            pa1 = *(const float4*)(Agn + 4);
            const float* Bgn = Bg + (size_t)(it + 1) * 16 * N;
            pb0 = *(const float4*)(Bgn);
            pb1 = *(const float4*)(Bgn + N);
        }

        // fragments + 16 MMAs
        uint32_t a[4][4], b[4][2];
#pragma unroll
        for (int mt = 0; mt < 4; mt++) {
            const int row = wm + mt * 16 + g;
            a[mt][0] = As2[cur][row * ASTR2 + t];
            a[mt][1] = As2[cur][(row + 8) * ASTR2 + t];
            a[mt][2] = As2[cur][row * ASTR2 + t + 4];
            a[mt][3] = As2[cur][(row + 8) * ASTR2 + t + 4];
        }
#pragma unroll
        for (int nt = 0; nt < 4; nt++) {
            const int col = wn + nt * 8 + g;
            b[nt][0] = Bs2[cur][col * ASTR2 + t];
            b[nt][1] = Bs2[cur][col * ASTR2 + t + 4];
        }
#pragma unroll
        for (int mt = 0; mt < 4; mt++)
#pragma unroll
            for (int nt = 0; nt < 4; nt++)
                mma_f16(acc[mt][nt], a[mt][0], a[mt][1], a[mt][2], a[mt][3],
                        b[nt][0], b[nt][1]);

        // stage next buffer (other half; no race with current readers)
        if (it + 1 < NIT) {
            const int nb = cur ^ 1;
            __half2 h0 = __floats2half2_rn(pa0.x, pa0.y);
            __half2 h1 = __floats2half2_rn(pa0.z, pa0.w);
            __half2 h2 = __floats2half2_rn(pa1.x, pa1.y);
            __half2 h3 = __floats2half2_rn(pa1.z, pa1.w);
            uint32_t* ad = &As2[nb][am * ASTR2 + (ak >> 1)];
            ad[0] = *(uint32_t*)&h0; ad[1] = *(uint32_t*)&h1;
            ad[2] = *(uint32_t*)&h2; ad[3] = *(uint32_t*)&h3;
            __half2 w0 = __floats2half2_rn(pb0.x, pb1.x);
            __half2 w1 = __floats2half2_rn(pb0.y, pb1.y);
            __half2 w2 = __floats2half2_rn(pb0.z, pb1.z);
            __half2 w3 = __floats2half2_rn(pb0.w, pb1.w);
            Bs2[nb][(bn4 + 0) * ASTR2 + bj] = *(uint32_t*)&w0;
            Bs2[nb][(bn4 + 1) * ASTR2 + bj] = *(uint32_t*)&w1;
            Bs2[nb][(bn4 + 2) * ASTR2 + bj] = *(uint32_t*)&w2;
            Bs2[nb][(bn4 + 3) * ASTR2 + bj] = *(uint32_t*)&w3;
        }
        __syncthreads();
        cur ^= 1;
    }

    // epilogue: c0/c1 at (row, col..col+1), c2/c3 at (row+8, ...)
#pragma unroll
    for (int mt = 0; mt < 4; mt++) {
#pragma unroll
        for (int nt = 0; nt < 4; nt++) {
            const int row = bm + wm + mt * 16 + g;
            const int col = bn + wn + nt * 8 + t * 2;
            float b0 = bias[col], b1 = bias[col + 1];
            float2 v0 = make_float2(acc[mt][nt][0] + b0, acc[mt][nt][1] + b1);
            float2 v1 = make_float2(acc[mt][nt][2] + b0, acc[mt][nt][3] + b1);
            *(float2*)(C + (size_t)row * N + col)       = v0;
            *(float2*)(C + (size_t)(row + 8) * N + col) = v1;
        }
    }
}

// ---------------------------------------------------------------------------
// Flash attention (causal) on tensor cores.  (unchanged from R5 — 193us)
// ---------------------------------------------------------------------------
#define KSTR 72   // Ks stride in floats
#define VSTR 36   // Vs stride in half2

__device__ __forceinline__ int KIDX(int d, int c) {
    return d * KSTR + (c ^ (4 * ((d >> 2) & 7)));
}

__global__ __launch_bounds__(256)
void flash_attn_mma(const float* __restrict__ Q, const float* __restrict__ K,
                    const float* __restrict__ V, float* __restrict__ O)
{
    __shared__ uint32_t Ks[64 * KSTR];   // [d][c] tf32 (swizzled)
    __shared__ __half2  Vs[64 * VSTR];   // [d][j2] = (V[2j2][d], V[2j2+1][d])

    const int qb = (int)(gridDim.x - 1 - blockIdx.x);  // heavy tiles first
    const int bh = blockIdx.y;
    const int b  = bh >> 4;
    const int h  = bh & 15;
    const int tid  = threadIdx.x;
    const int lane = tid & 31;
    const int warp = tid >> 5;
    const int g = lane >> 2;
    const int t = lane & 3;
    const int wr0 = warp * 16;

    const size_t rowstride = (size_t)BAT * DM;
    const size_t headoff = (size_t)b * DM + h * DHD;

    uint32_t qf[8][4];
    {
        const float* Qr0 = Q + (size_t)(qb * 128 + wr0 + g) * rowstride + headoff;
        const float* Qr8 = Qr0 + 8 * rowstride;
#pragma unroll
        for (int ks = 0; ks < 8; ks++) {
            qf[ks][0] = f2tf(Qr0[8 * ks + t]);
            qf[ks][1] = f2tf(Qr8[8 * ks + t]);
            qf[ks][2] = f2tf(Qr0[8 * ks + t + 4]);
            qf[ks][3] = f2tf(Qr8[8 * ks + t + 4]);
        }
    }

    float o[8][4];
#pragma unroll
    for (int nt = 0; nt < 8; nt++)
#pragma unroll
        for (int r = 0; r < 4; r++) o[nt][r] = 0.0f;
    float m0 = -1e30f, m1 = -1e30f, l0 = 0.0f, l1 = 0.0f;

    const int kbmax = 2 * qb + 1;
    for (int kb = 0; kb <= kbmax; kb++) {
        __syncthreads();
#pragma unroll
        for (int it = 0; it < 4; it++) {
            int i = tid + it * 256;
            int c = i >> 4;
            int d4 = (i & 15) * 4;
            const float* p = K + (size_t)(kb * 64 + c) * rowstride + headoff + d4;
            float4 kv = *(const float4*)p;
            Ks[KIDX(d4 + 0, c)] = f2tf(kv.x);
            Ks[KIDX(d4 + 1, c)] = f2tf(kv.y);
            Ks[KIDX(d4 + 2, c)] = f2tf(kv.z);
            Ks[KIDX(d4 + 3, c)] = f2tf(kv.w);
        }
#pragma unroll
        for (int it = 0; it < 2; it++) {
            int i = tid + it * 256;
            int j2 = i >> 4;
            int d4 = (i & 15) * 4;
            const float* p0 = V + (size_t)(kb * 64 + 2 * j2) * rowstride + headoff + d4;
            const float* p1 = p0 + rowstride;
            float4 v0 = *(const float4*)p0;
            float4 v1 = *(const float4*)p1;
            Vs[(d4 + 0) * VSTR + j2] = __floats2half2_rn(v0.x, v1.x);
            Vs[(d4 + 1) * VSTR + j2] = __floats2half2_rn(v0.y, v1.y);
            Vs[(d4 + 2) * VSTR + j2] = __floats2half2_rn(v0.z, v1.z);
            Vs[(d4 + 3) * VSTR + j2] = __floats2half2_rn(v0.w, v1.w);
        }
        __syncthreads();

        float s[8][4];
#pragma unroll
        for (int nt = 0; nt < 8; nt++)
#pragma unroll
            for (int r = 0; r < 4; r++) s[nt][r] = 0.0f;

#pragma unroll
        for (int ks = 0; ks < 8; ks++) {
#pragma unroll
            for (int nt = 0; nt < 8; nt++) {
                uint32_t b0 = Ks[KIDX(8 * ks + t,     nt * 8 + g)];
                uint32_t b1 = Ks[KIDX(8 * ks + t + 4, nt * 8 + g)];
                mma_tf32(s[nt], qf[ks], b0, b1);
            }
        }

        const int rg  = qb * 128 + wr0 + g;
        const int rg8 = rg + 8;
        if (kb * 64 + 63 > qb * 128 + wr0) {
#pragma unroll
            for (int nt = 0; nt < 8; nt++) {
                int c0 = kb * 64 + nt * 8 + 2 * t;
                s[nt][0] = (c0     > rg ) ? -1e30f : s[nt][0] * 0.125f;
                s[nt][1] = (c0 + 1 > rg ) ? -1e30f : s[nt][1] * 0.125f;
                s[nt][2] = (c0     > rg8) ? -1e30f : s[nt][2] * 0.125f;
                s[nt][3] = (c0 + 1 > rg8) ? -1e30f : s[nt][3] * 0.125f;
            }
        } else {
#pragma unroll
            for (int nt = 0; nt < 8; nt++)
#pragma unroll
                for (int r = 0; r < 4; r++) s[nt][r] *= 0.125f;
        }

        float mx0 = -1e30f, mx1 = -1e30f;
#pragma unroll
        for (int nt = 0; nt < 8; nt++) {
            mx0 = fmaxf(mx0, fmaxf(s[nt][0], s[nt][1]));
            mx1 = fmaxf(mx1, fmaxf(s[nt][2], s[nt][3]));
        }
        mx0 = fmaxf(mx0, __shfl_xor_sync(0xffffffffu, mx0, 1));
        mx0 = fmaxf(mx0, __shfl_xor_sync(0xffffffffu, mx0, 2));
        mx1 = fmaxf(mx1, __shfl_xor_sync(0xffffffffu, mx1, 1));
        mx1 = fmaxf(mx1, __shfl_xor_sync(0xffffffffu, mx1, 2));

        float mn0 = fmaxf(m0, mx0), mn1 = fmaxf(m1, mx1);
        float corr0 = __expf(m0 - mn0), corr1 = __expf(m1 - mn1);
        m0 = mn0; m1 = mn1;

        float rs0 = 0.0f, rs1 = 0.0f;
        uint32_t ph[8], ph8[8];
#pragma unroll
        for (int nt = 0; nt < 8; nt++) {
            float p0 = __expf(s[nt][0] - mn0);
            float p1 = __expf(s[nt][1] - mn0);
            float p2 = __expf(s[nt][2] - mn1);
            float p3 = __expf(s[nt][3] - mn1);
            rs0 += p0 + p1;
            rs1 += p2 + p3;
            __half2 h0 = __floats2half2_rn(p0, p1);
            __half2 h1 = __floats2half2_rn(p2, p3);
            ph[nt]  = *(uint32_t*)&h0;
            ph8[nt] = *(uint32_t*)&h1;
        }
        rs0 += __shfl_xor_sync(0xffffffffu, rs0, 1);
        rs0 += __shfl_xor_sync(0xffffffffu, rs0, 2);
        rs1 += __shfl_xor_sync(0xffffffffu, rs1, 1);
        rs1 += __shfl_xor_sync(0xffffffffu, rs1, 2);
        l0 = l0 * corr0 + rs0;
        l1 = l1 * corr1 + rs1;

#pragma unroll
        for (int nt = 0; nt < 8; nt++) {
            o[nt][0] *= corr0; o[nt][1] *= corr0;
            o[nt][2] *= corr1; o[nt][3] *= corr1;
        }

#pragma unroll
        for (int kk = 0; kk < 4; kk++) {
#pragma unroll
            for (int nt = 0; nt < 8; nt++) {
                const __half2* vp = &Vs[(nt * 8 + g) * VSTR + kk * 8 + t];
                uint32_t b0 = *(const uint32_t*)(vp);
                uint32_t b1 = *(const uint32_t*)(vp + 4);
                mma_f16(o[nt], ph[2 * kk], ph8[2 * kk],
                        ph[2 * kk + 1], ph8[2 * kk + 1], b0, b1);
            }
        }
    }

    float inv0 = 1.0f / l0, inv1 = 1.0f / l1;
    float* Or0 = O + (size_t)(qb * 128 + wr0 + g) * rowstride + headoff;
    float* Or8 = Or0 + 8 * rowstride;
#pragma unroll
    for (int nt = 0; nt < 8; nt++) {
        *(float2*)(Or0 + nt * 8 + 2 * t) = make_float2(o[nt][0] * inv0, o[nt][1] * inv0);
        *(float2*)(Or8 + nt * 8 + 2 * t) = make_float2(o[nt][2] * inv1, o[nt][3] * inv1);
    }
}

// ---------------------------------------------------------------------------
// kernel_launch
// Inputs: query, key, value, mask, Wq, bq, Wk, bk, Wv, bv, Wo, bo
// ---------------------------------------------------------------------------
extern "C" void kernel_launch(void* const* d_in, const int* in_sizes, int n_in,
                              void* d_out, int out_size)
{
    const float* query = (const float*)d_in[0];
    const float* key   = (const float*)d_in[1];
    const float* value = (const float*)d_in[2];
    // d_in[3] = mask (tril causal) — handled analytically in flash_attn_mma
    const float* Wq = (const float*)d_in[4];
    const float* bq = (const float*)d_in[5];
    const float* Wk = (const float*)d_in[6];
    const float* bk = (const float*)d_in[7];
    const float* Wv = (const float*)d_in[8];
    const float* bv = (const float*)d_in[9];
    const float* Wo = (const float*)d_in[10];
    const float* bo = (const float*)d_in[11];
    float* out = (float*)d_out;

    float *qp, *kp, *vp, *xp;
    cudaGetSymbolAddress((void**)&qp, g_q);
    cudaGetSymbolAddress((void**)&kp, g_k);
    cudaGetSymbolAddress((void**)&vp, g_v);
    cudaGetSymbolAddress((void**)&xp, g_x);

    // Fused Q/K/V projections: one launch, 3 GEMMs via blockIdx.z
    GemmArgs proj;
    proj.A[0] = query; proj.W[0] = Wq; proj.bias[0] = bq; proj.C[0] = qp;
    proj.A[1] = key;   proj.W[1] = Wk; proj.bias[1] = bk; proj.C[1] = kp;
    proj.A[2] = value; proj.W[2] = Wv; proj.bias[2] = bv; proj.C[2] = vp;
    h16_gemm_bias<<<dim3(DM / 128, NTOK / 128, 3), 256>>>(proj, NTOK, DM, DM);

    flash_attn_mma<<<dim3(SEQ / 128, BAT * NH), 256>>>(qp, kp, vp, xp);

    GemmArgs oproj;
    oproj.A[0] = xp; oproj.W[0] = Wo; oproj.bias[0] = bo; oproj.C[0] = out;
    oproj.A[1] = xp; oproj.W[1] = Wo; oproj.bias[1] = bo; oproj.C[1] = out;
    oproj.A[2] = xp; oproj.W[2] = Wo; oproj.bias[2] = bo; oproj.C[2] = out;
    h16_gemm_bias<<<dim3(DM / 128, NTOK / 128, 1), 256>>>(oproj, NTOK, DM, DM);
}

// round 8
// speedup vs baseline: 4.1468x; 1.5407x over previous
#include <cuda_runtime.h>
#include <cuda_fp16.h>
#include <math.h>
#include <stdint.h>

// Problem constants (fixed by the reference)
#define SEQ   2048
#define BAT   2
#define NH    16
#define DHD   64
#define DM    1024
#define NTOK  (SEQ * BAT)   // 4096

// Scratch (allocation-free rule: __device__ globals)
__device__ float   g_q[NTOK * DM];        // fp32 Q/K/V projections (flash input)
__device__ float   g_k[NTOK * DM];
__device__ float   g_v[NTOK * DM];
__device__ __half  g_hq[NTOK * DM];       // fp16 copies of query/key/value (gemm A)
__device__ __half  g_hk[NTOK * DM];
__device__ __half  g_hv[NTOK * DM];
__device__ __half  g_hx[NTOK * DM];       // fp16 attention output (o-proj A)
__device__ uint32_t g_wt[4][DM * DM / 2]; // fp16 transposed+pair-packed weights

// ---------------------------------------------------------------------------
// mma / async helpers
// ---------------------------------------------------------------------------
__device__ __forceinline__ uint32_t f2tf(float f) {
    uint32_t r;
    asm("cvt.rna.tf32.f32 %0, %1;" : "=r"(r) : "f"(f));
    return r;
}

__device__ __forceinline__ void mma_tf32(float* c, const uint32_t* a,
                                         uint32_t b0, uint32_t b1) {
    asm volatile(
        "mma.sync.aligned.m16n8k8.row.col.f32.tf32.tf32.f32 "
        "{%0,%1,%2,%3}, {%4,%5,%6,%7}, {%8,%9}, {%0,%1,%2,%3};"
        : "+f"(c[0]), "+f"(c[1]), "+f"(c[2]), "+f"(c[3])
        : "r"(a[0]), "r"(a[1]), "r"(a[2]), "r"(a[3]), "r"(b0), "r"(b1));
}

__device__ __forceinline__ void mma_f16(float* c, uint32_t a0, uint32_t a1,
                                        uint32_t a2, uint32_t a3,
                                        uint32_t b0, uint32_t b1) {
    asm volatile(
        "mma.sync.aligned.m16n8k16.row.col.f32.f16.f16.f32 "
        "{%0,%1,%2,%3}, {%4,%5,%6,%7}, {%8,%9}, {%0,%1,%2,%3};"
        : "+f"(c[0]), "+f"(c[1]), "+f"(c[2]), "+f"(c[3])
        : "r"(a0), "r"(a1), "r"(a2), "r"(a3), "r"(b0), "r"(b1));
}

__device__ __forceinline__ void ldsm_x4(uint32_t& r0, uint32_t& r1,
                                        uint32_t& r2, uint32_t& r3, uint32_t addr) {
    asm volatile("ldmatrix.sync.aligned.m8n8.x4.shared.b16 {%0,%1,%2,%3}, [%4];"
                 : "=r"(r0), "=r"(r1), "=r"(r2), "=r"(r3) : "r"(addr));
}

__device__ __forceinline__ void cp16(uint32_t saddr, const void* g) {
    asm volatile("cp.async.cg.shared.global [%0], [%1], 16;" :: "r"(saddr), "l"(g));
}
#define CP_COMMIT() asm volatile("cp.async.commit_group;")
#define CP_WAIT1()  asm volatile("cp.async.wait_group 1;" ::: "memory")

// ---------------------------------------------------------------------------
// Convert kernels
// ---------------------------------------------------------------------------
struct CvtArgs { const float* src[3]; __half* dst[3]; };

__global__ __launch_bounds__(256)
void cvt_f2h(CvtArgs ca, int n)
{
    const float* __restrict__ s = ca.src[blockIdx.z];
    __half* __restrict__ d = ca.dst[blockIdx.z];
    int idx = (blockIdx.x * 256 + threadIdx.x) * 4;
    if (idx < n) {
        float4 v = *(const float4*)(s + idx);
        __half2 h0 = __floats2half2_rn(v.x, v.y);
        __half2 h1 = __floats2half2_rn(v.z, v.w);
        uint2 u;
        u.x = *(uint32_t*)&h0;
        u.y = *(uint32_t*)&h1;
        *(uint2*)(d + idx) = u;
    }
}

// Weight convert + transpose + k-pair pack:
// Wt[n][j2] = half2( W[2j2][n], W[2j2+1][n] )   (uint32 array, row stride K/2)
struct CvtWArgs { const float* W[4]; uint32_t* Wt[4]; };

__global__ __launch_bounds__(256)
void cvt_w_trans(CvtWArgs cw)
{
    __shared__ float T[32][33];
    const float* __restrict__ W = cw.W[blockIdx.z];
    uint32_t* __restrict__ Wt = cw.Wt[blockIdx.z];
    const int k0 = blockIdx.x * 32;
    const int n0 = blockIdx.y * 32;
    const int tid = threadIdx.x;

#pragma unroll
    for (int i = 0; i < 4; i++) {
        int kk = i * 8 + (tid >> 5);
        int nn = tid & 31;
        T[kk][nn] = W[(size_t)(k0 + kk) * DM + n0 + nn];
    }
    __syncthreads();

#pragma unroll
    for (int i = 0; i < 2; i++) {
        int p = tid + i * 256;
        int nn = p >> 4;        // 0..31
        int j2 = p & 15;        // 0..15
        __half2 h = __floats2half2_rn(T[2 * j2][nn], T[2 * j2 + 1][nn]);
        Wt[(size_t)(n0 + nn) * (DM / 2) + (k0 / 2) + j2] = *(uint32_t*)&h;
    }
}

// ---------------------------------------------------------------------------
// fp16 pipelined tensor-core GEMM: C[M,N] = A@B + bias (fp16 in, fp32 out)
// A: row-major fp16 [M][K].  B: pre-transposed pair-packed Wt[n][k/2] uint32.
// CTA 128x128, k-step 32, 3-stage cp.async pipeline, 256 threads = 8 warps,
// warp tile 64x32.  A-frags via ldmatrix.x4, B-frags via conflict-free LDS.32.
// Smem chunks (16B) swizzled: chunk' = chunk ^ ((row>>1)&3).
// ---------------------------------------------------------------------------
#define STG 3

struct HGemmArgs {
    const __half*   A[3];
    const uint32_t* Bt[3];
    const float*    bias[3];
    float*          C[3];
};

__global__ __launch_bounds__(256)
void h16_gemm_pipe(HGemmArgs ga, int M, int N, int K)
{
    const int z = blockIdx.z;
    const __half*   __restrict__ A    = ga.A[z];
    const uint32_t* __restrict__ Bt   = ga.Bt[z];
    const float*    __restrict__ bias = ga.bias[z];
    float*          __restrict__ C    = ga.C[z];

    // per stage: A 128 rows x 32 halves (64B) = 8KB ; B 128 rows x 16 u32 = 8KB
    __shared__ __align__(16) unsigned char smA[STG][8192];
    __shared__ __align__(16) unsigned char smB[STG][8192];

    const int tid  = threadIdx.x;
    const int lane = tid & 31;
    const int warp = tid >> 5;
    const int wm = (warp & 1) * 64;
    const int wn = (warp >> 1) * 32;
    const int bm = blockIdx.y * 128;
    const int bn = blockIdx.x * 128;
    const int g = lane >> 2;
    const int t = lane & 3;

    // ---- staging: each thread owns row rS, 16B chunks cS0, cS0+1 ----
    const int rS  = tid >> 1;              // 0..127
    const int cS0 = (tid & 1) * 2;         // 0 or 2
    const int swS = (rS >> 1) & 3;
    const int offA0 = (rS * 4 + (cS0 ^ swS)) * 16;
    const int offA1 = (rS * 4 + ((cS0 + 1) ^ swS)) * 16;
    const __half*   Agr = A  + (size_t)(bm + rS) * K + cS0 * 8;
    const uint32_t* Bgr = Bt + (size_t)(bn + rS) * (K / 2) + cS0 * 4;

    uint32_t saA[STG], saB[STG];
#pragma unroll
    for (int s = 0; s < STG; s++) {
        saA[s] = (uint32_t)__cvta_generic_to_shared(&smA[s][0]);
        saB[s] = (uint32_t)__cvta_generic_to_shared(&smB[s][0]);
    }

    float acc[4][4][4];
#pragma unroll
    for (int i = 0; i < 4; i++)
#pragma unroll
        for (int j = 0; j < 4; j++)
#pragma unroll
            for (int r = 0; r < 4; r++) acc[i][j][r] = 0.0f;

    const int NIT = K / 32;   // 32

    // ---- prologue: issue stages 0, 1 ----
#pragma unroll
    for (int s = 0; s < STG - 1; s++) {
        cp16(saA[s] + offA0, Agr + s * 32);
        cp16(saA[s] + offA1, Agr + s * 32 + 8);
        cp16(saB[s] + offA0, Bgr + s * 16);
        cp16(saB[s] + offA1, Bgr + s * 16 + 4);
        CP_COMMIT();
    }

    // fragment address pieces (constant over iterations)
    const int lr = lane & 15;
    const int lc = lane >> 4;
    int aoff[4][2];
#pragma unroll
    for (int mt = 0; mt < 4; mt++) {
        const int r = wm + mt * 16 + lr;
        const int sw = (r >> 1) & 3;
#pragma unroll
        for (int kk = 0; kk < 2; kk++)
            aoff[mt][kk] = (r * 4 + ((2 * kk + lc) ^ sw)) * 16;
    }

    int st = 0;
    for (int it = 0; it < NIT; it++) {
        CP_WAIT1();
        __syncthreads();

        // issue stage it+2 (into the buffer just freed by compute of it-1)
        if (it + STG - 1 < NIT) {
            const int s2 = (st + STG - 1) % STG;
            const int kof = (it + STG - 1) * 32;
            cp16(saA[s2] + offA0, Agr + kof);
            cp16(saA[s2] + offA1, Agr + kof + 8);
            cp16(saB[s2] + offA0, Bgr + kof / 2);
            cp16(saB[s2] + offA1, Bgr + kof / 2 + 4);
        }
        CP_COMMIT();

        // ---- compute current stage ----
        const uint32_t sa = saA[st];
        const uint32_t* Bs = (const uint32_t*)&smB[st][0];
#pragma unroll
        for (int kk = 0; kk < 2; kk++) {
            uint32_t a[4][4];
#pragma unroll
            for (int mt = 0; mt < 4; mt++)
                ldsm_x4(a[mt][0], a[mt][1], a[mt][2], a[mt][3], sa + aoff[mt][kk]);
            uint32_t b0[4], b1[4];
#pragma unroll
            for (int nt = 0; nt < 4; nt++) {
                const int n = wn + nt * 8 + g;
                const int v = (n >> 1) & 3;
                b0[nt] = Bs[n * 16 + (((2 * kk)     ^ v) << 2) + t];
                b1[nt] = Bs[n * 16 + (((2 * kk + 1) ^ v) << 2) + t];
            }
#pragma unroll
            for (int mt = 0; mt < 4; mt++)
#pragma unroll
                for (int nt = 0; nt < 4; nt++)
                    mma_f16(acc[mt][nt], a[mt][0], a[mt][1], a[mt][2], a[mt][3],
                            b0[nt], b1[nt]);
        }
        st = (st + 1) % STG;
    }

    // ---- epilogue ----
#pragma unroll
    for (int mt = 0; mt < 4; mt++) {
#pragma unroll
        for (int nt = 0; nt < 4; nt++) {
            const int row = bm + wm + mt * 16 + g;
            const int col = bn + wn + nt * 8 + t * 2;
            float b0 = bias[col], b1 = bias[col + 1];
            float2 v0 = make_float2(acc[mt][nt][0] + b0, acc[mt][nt][1] + b1);
            float2 v1 = make_float2(acc[mt][nt][2] + b0, acc[mt][nt][3] + b1);
            *(float2*)(C + (size_t)row * N + col)       = v0;
            *(float2*)(C + (size_t)(row + 8) * N + col) = v1;
        }
    }
}

// ---------------------------------------------------------------------------
// Flash attention (causal) on tensor cores.  (R5/R6 design — 193us)
// Output now written as fp16 into g_hx (feeds o-projection GEMM directly).
// ---------------------------------------------------------------------------
#define KSTR 72   // Ks stride in floats
#define VSTR 36   // Vs stride in half2

__device__ __forceinline__ int KIDX(int d, int c) {
    return d * KSTR + (c ^ (4 * ((d >> 2) & 7)));
}

__global__ __launch_bounds__(256)
void flash_attn_mma(const float* __restrict__ Q, const float* __restrict__ K,
                    const float* __restrict__ V, __half* __restrict__ X)
{
    __shared__ uint32_t Ks[64 * KSTR];
    __shared__ __half2  Vs[64 * VSTR];

    const int qb = (int)(gridDim.x - 1 - blockIdx.x);
    const int bh = blockIdx.y;
    const int b  = bh >> 4;
    const int h  = bh & 15;
    const int tid  = threadIdx.x;
    const int lane = tid & 31;
    const int warp = tid >> 5;
    const int g = lane >> 2;
    const int t = lane & 3;
    const int wr0 = warp * 16;

    const size_t rowstride = (size_t)BAT * DM;
    const size_t headoff = (size_t)b * DM + h * DHD;

    uint32_t qf[8][4];
    {
        const float* Qr0 = Q + (size_t)(qb * 128 + wr0 + g) * rowstride + headoff;
        const float* Qr8 = Qr0 + 8 * rowstride;
#pragma unroll
        for (int ks = 0; ks < 8; ks++) {
            qf[ks][0] = f2tf(Qr0[8 * ks + t]);
            qf[ks][1] = f2tf(Qr8[8 * ks + t]);
            qf[ks][2] = f2tf(Qr0[8 * ks + t + 4]);
            qf[ks][3] = f2tf(Qr8[8 * ks + t + 4]);
        }
    }

    float o[8][4];
#pragma unroll
    for (int nt = 0; nt < 8; nt++)
#pragma unroll
        for (int r = 0; r < 4; r++) o[nt][r] = 0.0f;
    float m0 = -1e30f, m1 = -1e30f, l0 = 0.0f, l1 = 0.0f;

    const int kbmax = 2 * qb + 1;
    for (int kb = 0; kb <= kbmax; kb++) {
        __syncthreads();
#pragma unroll
        for (int it = 0; it < 4; it++) {
            int i = tid + it * 256;
            int c = i >> 4;
            int d4 = (i & 15) * 4;
            const float* p = K + (size_t)(kb * 64 + c) * rowstride + headoff + d4;
            float4 kv = *(const float4*)p;
            Ks[KIDX(d4 + 0, c)] = f2tf(kv.x);
            Ks[KIDX(d4 + 1, c)] = f2tf(kv.y);
            Ks[KIDX(d4 + 2, c)] = f2tf(kv.z);
            Ks[KIDX(d4 + 3, c)] = f2tf(kv.w);
        }
#pragma unroll
        for (int it = 0; it < 2; it++) {
            int i = tid + it * 256;
            int j2 = i >> 4;
            int d4 = (i & 15) * 4;
            const float* p0 = V + (size_t)(kb * 64 + 2 * j2) * rowstride + headoff + d4;
            const float* p1 = p0 + rowstride;
            float4 v0 = *(const float4*)p0;
            float4 v1 = *(const float4*)p1;
            Vs[(d4 + 0) * VSTR + j2] = __floats2half2_rn(v0.x, v1.x);
            Vs[(d4 + 1) * VSTR + j2] = __floats2half2_rn(v0.y, v1.y);
            Vs[(d4 + 2) * VSTR + j2] = __floats2half2_rn(v0.z, v1.z);
            Vs[(d4 + 3) * VSTR + j2] = __floats2half2_rn(v0.w, v1.w);
        }
        __syncthreads();

        float s[8][4];
#pragma unroll
        for (int nt = 0; nt < 8; nt++)
#pragma unroll
            for (int r = 0; r < 4; r++) s[nt][r] = 0.0f;

#pragma unroll
        for (int ks = 0; ks < 8; ks++) {
#pragma unroll
            for (int nt = 0; nt < 8; nt++) {
                uint32_t b0 = Ks[KIDX(8 * ks + t,     nt * 8 + g)];
                uint32_t b1 = Ks[KIDX(8 * ks + t + 4, nt * 8 + g)];
                mma_tf32(s[nt], qf[ks], b0, b1);
            }
        }

        const int rg  = qb * 128 + wr0 + g;
        const int rg8 = rg + 8;
        if (kb * 64 + 63 > qb * 128 + wr0) {
#pragma unroll
            for (int nt = 0; nt < 8; nt++) {
                int c0 = kb * 64 + nt * 8 + 2 * t;
                s[nt][0] = (c0     > rg ) ? -1e30f : s[nt][0] * 0.125f;
                s[nt][1] = (c0 + 1 > rg ) ? -1e30f : s[nt][1] * 0.125f;
                s[nt][2] = (c0     > rg8) ? -1e30f : s[nt][2] * 0.125f;
                s[nt][3] = (c0 + 1 > rg8) ? -1e30f : s[nt][3] * 0.125f;
            }
        } else {
#pragma unroll
            for (int nt = 0; nt < 8; nt++)
#pragma unroll
                for (int r = 0; r < 4; r++) s[nt][r] *= 0.125f;
        }

        float mx0 = -1e30f, mx1 = -1e30f;
#pragma unroll
        for (int nt = 0; nt < 8; nt++) {
            mx0 = fmaxf(mx0, fmaxf(s[nt][0], s[nt][1]));
            mx1 = fmaxf(mx1, fmaxf(s[nt][2], s[nt][3]));
        }
        mx0 = fmaxf(mx0, __shfl_xor_sync(0xffffffffu, mx0, 1));
        mx0 = fmaxf(mx0, __shfl_xor_sync(0xffffffffu, mx0, 2));
        mx1 = fmaxf(mx1, __shfl_xor_sync(0xffffffffu, mx1, 1));
        mx1 = fmaxf(mx1, __shfl_xor_sync(0xffffffffu, mx1, 2));

        float mn0 = fmaxf(m0, mx0), mn1 = fmaxf(m1, mx1);
        float corr0 = __expf(m0 - mn0), corr1 = __expf(m1 - mn1);
        m0 = mn0; m1 = mn1;

        float rs0 = 0.0f, rs1 = 0.0f;
        uint32_t ph[8], ph8[8];
#pragma unroll
        for (int nt = 0; nt < 8; nt++) {
            float p0 = __expf(s[nt][0] - mn0);
            float p1 = __expf(s[nt][1] - mn0);
            float p2 = __expf(s[nt][2] - mn1);
            float p3 = __expf(s[nt][3] - mn1);
            rs0 += p0 + p1;
            rs1 += p2 + p3;
            __half2 h0 = __floats2half2_rn(p0, p1);
            __half2 h1 = __floats2half2_rn(p2, p3);
            ph[nt]  = *(uint32_t*)&h0;
            ph8[nt] = *(uint32_t*)&h1;
        }
        rs0 += __shfl_xor_sync(0xffffffffu, rs0, 1);
        rs0 += __shfl_xor_sync(0xffffffffu, rs0, 2);
        rs1 += __shfl_xor_sync(0xffffffffu, rs1, 1);
        rs1 += __shfl_xor_sync(0xffffffffu, rs1, 2);
        l0 = l0 * corr0 + rs0;
        l1 = l1 * corr1 + rs1;

#pragma unroll
        for (int nt = 0; nt < 8; nt++) {
            o[nt][0] *= corr0; o[nt][1] *= corr0;
            o[nt][2] *= corr1; o[nt][3] *= corr1;
        }

#pragma unroll
        for (int kk = 0; kk < 4; kk++) {
#pragma unroll
            for (int nt = 0; nt < 8; nt++) {
                const __half2* vp = &Vs[(nt * 8 + g) * VSTR + kk * 8 + t];
                uint32_t b0 = *(const uint32_t*)(vp);
                uint32_t b1 = *(const uint32_t*)(vp + 4);
                mma_f16(o[nt], ph[2 * kk], ph8[2 * kk],
                        ph[2 * kk + 1], ph8[2 * kk + 1], b0, b1);
            }
        }
    }

    // epilogue: normalize, write fp16
    float inv0 = 1.0f / l0, inv1 = 1.0f / l1;
    __half* Xr0 = X + (size_t)(qb * 128 + wr0 + g) * rowstride + headoff;
    __half* Xr8 = Xr0 + 8 * rowstride;
#pragma unroll
    for (int nt = 0; nt < 8; nt++) {
        __half2 h0 = __floats2half2_rn(o[nt][0] * inv0, o[nt][1] * inv0);
        __half2 h1 = __floats2half2_rn(o[nt][2] * inv1, o[nt][3] * inv1);
        *(uint32_t*)(Xr0 + nt * 8 + 2 * t) = *(uint32_t*)&h0;
        *(uint32_t*)(Xr8 + nt * 8 + 2 * t) = *(uint32_t*)&h1;
    }
}

// ---------------------------------------------------------------------------
// kernel_launch
// Inputs: query, key, value, mask, Wq, bq, Wk, bk, Wv, bv, Wo, bo
// ---------------------------------------------------------------------------
extern "C" void kernel_launch(void* const* d_in, const int* in_sizes, int n_in,
                              void* d_out, int out_size)
{
    const float* query = (const float*)d_in[0];
    const float* key   = (const float*)d_in[1];
    const float* value = (const float*)d_in[2];
    // d_in[3] = mask (tril causal) — handled analytically in flash_attn_mma
    const float* Wq = (const float*)d_in[4];
    const float* bq = (const float*)d_in[5];
    const float* Wk = (const float*)d_in[6];
    const float* bk = (const float*)d_in[7];
    const float* Wv = (const float*)d_in[8];
    const float* bv = (const float*)d_in[9];
    const float* Wo = (const float*)d_in[10];
    const float* bo = (const float*)d_in[11];
    float* out = (float*)d_out;

    float *qp, *kp, *vp;
    __half *hq, *hk, *hv, *hx;
    uint32_t* wt;
    cudaGetSymbolAddress((void**)&qp, g_q);
    cudaGetSymbolAddress((void**)&kp, g_k);
    cudaGetSymbolAddress((void**)&vp, g_v);
    cudaGetSymbolAddress((void**)&hq, g_hq);
    cudaGetSymbolAddress((void**)&hk, g_hk);
    cudaGetSymbolAddress((void**)&hv, g_hv);
    cudaGetSymbolAddress((void**)&hx, g_hx);
    cudaGetSymbolAddress((void**)&wt, g_wt);

    uint32_t* wtq = wt;
    uint32_t* wtk = wt + (size_t)DM * DM / 2;
    uint32_t* wtv = wt + (size_t)DM * DM;
    uint32_t* wto = wt + (size_t)DM * DM * 3 / 2;

    // 1) convert inputs fp32 -> fp16
    CvtArgs ca;
    ca.src[0] = query; ca.dst[0] = hq;
    ca.src[1] = key;   ca.dst[1] = hk;
    ca.src[2] = value; ca.dst[2] = hv;
    cvt_f2h<<<dim3(NTOK * DM / 1024, 1, 3), 256>>>(ca, NTOK * DM);

    // 2) convert + transpose + pair-pack weights
    CvtWArgs cw;
    cw.W[0] = Wq; cw.Wt[0] = wtq;
    cw.W[1] = Wk; cw.Wt[1] = wtk;
    cw.W[2] = Wv; cw.Wt[2] = wtv;
    cw.W[3] = Wo; cw.Wt[3] = wto;
    cvt_w_trans<<<dim3(DM / 32, DM / 32, 4), 256>>>(cw);

    // 3) fused Q/K/V projections
    HGemmArgs proj;
    proj.A[0] = hq; proj.Bt[0] = wtq; proj.bias[0] = bq; proj.C[0] = qp;
    proj.A[1] = hk; proj.Bt[1] = wtk; proj.bias[1] = bk; proj.C[1] = kp;
    proj.A[2] = hv; proj.Bt[2] = wtv; proj.bias[2] = bv; proj.C[2] = vp;
    h16_gemm_pipe<<<dim3(DM / 128, NTOK / 128, 3), 256>>>(proj, NTOK, DM, DM);

    // 4) attention (writes fp16 x)
    flash_attn_mma<<<dim3(SEQ / 128, BAT * NH), 256>>>(qp, kp, vp, hx);

    // 5) output projection
    HGemmArgs oproj;
    oproj.A[0] = hx; oproj.Bt[0] = wto; oproj.bias[0] = bo; oproj.C[0] = out;
    oproj.A[1] = hx; oproj.Bt[1] = wto; oproj.bias[1] = bo; oproj.C[1] = out;
    oproj.A[2] = hx; oproj.Bt[2] = wto; oproj.bias[2] = bo; oproj.C[2] = out;
    h16_gemm_pipe<<<dim3(DM / 128, NTOK / 128, 1), 256>>>(oproj, NTOK, DM, DM);
}

// round 9
// speedup vs baseline: 5.3170x; 1.2822x over previous
#include <cuda_runtime.h>
#include <cuda_fp16.h>
#include <math.h>
#include <stdint.h>

// Problem constants (fixed by the reference)
#define SEQ   2048
#define BAT   2
#define NH    16
#define DHD   64
#define DM    1024
#define NTOK  (SEQ * BAT)   // 4096

// Scratch (allocation-free rule: __device__ globals)
__device__ __half  g_hq[NTOK * DM];       // fp16 copies of query/key/value (gemm A)
__device__ __half  g_hk[NTOK * DM];
__device__ __half  g_hv[NTOK * DM];
__device__ __half  g_pq[NTOK * DM];       // fp16 Q/K/V projections (flash input)
__device__ __half  g_pk[NTOK * DM];
__device__ __half  g_pv[NTOK * DM];
__device__ __half  g_hx[NTOK * DM];       // fp16 attention output (o-proj A)
__device__ uint32_t g_wt[4][DM * DM / 2]; // fp16 transposed+pair-packed weights

// ---------------------------------------------------------------------------
// mma / async helpers
// ---------------------------------------------------------------------------
__device__ __forceinline__ void mma_f16(float* c, uint32_t a0, uint32_t a1,
                                        uint32_t a2, uint32_t a3,
                                        uint32_t b0, uint32_t b1) {
    asm volatile(
        "mma.sync.aligned.m16n8k16.row.col.f32.f16.f16.f32 "
        "{%0,%1,%2,%3}, {%4,%5,%6,%7}, {%8,%9}, {%0,%1,%2,%3};"
        : "+f"(c[0]), "+f"(c[1]), "+f"(c[2]), "+f"(c[3])
        : "r"(a0), "r"(a1), "r"(a2), "r"(a3), "r"(b0), "r"(b1));
}

__device__ __forceinline__ void ldsm_x4(uint32_t& r0, uint32_t& r1,
                                        uint32_t& r2, uint32_t& r3, uint32_t addr) {
    asm volatile("ldmatrix.sync.aligned.m8n8.x4.shared.b16 {%0,%1,%2,%3}, [%4];"
                 : "=r"(r0), "=r"(r1), "=r"(r2), "=r"(r3) : "r"(addr));
}

__device__ __forceinline__ void ldsm_x4_trans(uint32_t& r0, uint32_t& r1,
                                              uint32_t& r2, uint32_t& r3, uint32_t addr) {
    asm volatile("ldmatrix.sync.aligned.m8n8.x4.trans.shared.b16 {%0,%1,%2,%3}, [%4];"
                 : "=r"(r0), "=r"(r1), "=r"(r2), "=r"(r3) : "r"(addr));
}

__device__ __forceinline__ void cp16(uint32_t saddr, const void* g) {
    asm volatile("cp.async.cg.shared.global [%0], [%1], 16;" :: "r"(saddr), "l"(g));
}
#define CP_COMMIT() asm volatile("cp.async.commit_group;")
#define CP_WAIT1()  asm volatile("cp.async.wait_group 1;" ::: "memory")
#define CP_WAIT2()  asm volatile("cp.async.wait_group 2;" ::: "memory")

// ---------------------------------------------------------------------------
// Convert kernels
// ---------------------------------------------------------------------------
struct CvtArgs { const float* src[3]; __half* dst[3]; };

__global__ __launch_bounds__(256)
void cvt_f2h(CvtArgs ca, int n)
{
    const float* __restrict__ s = ca.src[blockIdx.z];
    __half* __restrict__ d = ca.dst[blockIdx.z];
    int idx = (blockIdx.x * 256 + threadIdx.x) * 4;
    if (idx < n) {
        float4 v = *(const float4*)(s + idx);
        __half2 h0 = __floats2half2_rn(v.x, v.y);
        __half2 h1 = __floats2half2_rn(v.z, v.w);
        uint2 u;
        u.x = *(uint32_t*)&h0;
        u.y = *(uint32_t*)&h1;
        *(uint2*)(d + idx) = u;
    }
}

// Weight convert + transpose + k-pair pack: Wt[n][j2] = half2(W[2j2][n], W[2j2+1][n])
struct CvtWArgs { const float* W[4]; uint32_t* Wt[4]; };

__global__ __launch_bounds__(256)
void cvt_w_trans(CvtWArgs cw)
{
    __shared__ float T[32][33];
    const float* __restrict__ W = cw.W[blockIdx.z];
    uint32_t* __restrict__ Wt = cw.Wt[blockIdx.z];
    const int k0 = blockIdx.x * 32;
    const int n0 = blockIdx.y * 32;
    const int tid = threadIdx.x;

#pragma unroll
    for (int i = 0; i < 4; i++) {
        int kk = i * 8 + (tid >> 5);
        int nn = tid & 31;
        T[kk][nn] = W[(size_t)(k0 + kk) * DM + n0 + nn];
    }
    __syncthreads();

#pragma unroll
    for (int i = 0; i < 2; i++) {
        int p = tid + i * 256;
        int nn = p >> 4;
        int j2 = p & 15;
        __half2 h = __floats2half2_rn(T[2 * j2][nn], T[2 * j2 + 1][nn]);
        Wt[(size_t)(n0 + nn) * (DM / 2) + (k0 / 2) + j2] = *(uint32_t*)&h;
    }
}

// ---------------------------------------------------------------------------
// fp16 pipelined tensor-core GEMM (R7 design), now with optional fp16 output.
// ---------------------------------------------------------------------------
#define STG 3

struct HGemmArgs {
    const __half*   A[3];
    const uint32_t* Bt[3];
    const float*    bias[3];
    float*          C[3];    // fp32 output (if Ch[z] == nullptr)
    __half*         Ch[3];   // fp16 output (if non-null)
};

__global__ __launch_bounds__(256)
void h16_gemm_pipe(HGemmArgs ga, int M, int N, int K)
{
    const int z = blockIdx.z;
    const __half*   __restrict__ A    = ga.A[z];
    const uint32_t* __restrict__ Bt   = ga.Bt[z];
    const float*    __restrict__ bias = ga.bias[z];

    __shared__ __align__(16) unsigned char smA[STG][8192];
    __shared__ __align__(16) unsigned char smB[STG][8192];

    const int tid  = threadIdx.x;
    const int lane = tid & 31;
    const int warp = tid >> 5;
    const int wm = (warp & 1) * 64;
    const int wn = (warp >> 1) * 32;
    const int bm = blockIdx.y * 128;
    const int bn = blockIdx.x * 128;
    const int g = lane >> 2;
    const int t = lane & 3;

    const int rS  = tid >> 1;
    const int cS0 = (tid & 1) * 2;
    const int swS = (rS >> 1) & 3;
    const int offA0 = (rS * 4 + (cS0 ^ swS)) * 16;
    const int offA1 = (rS * 4 + ((cS0 + 1) ^ swS)) * 16;
    const __half*   Agr = A  + (size_t)(bm + rS) * K + cS0 * 8;
    const uint32_t* Bgr = Bt + (size_t)(bn + rS) * (K / 2) + cS0 * 4;

    uint32_t saA[STG], saB[STG];
#pragma unroll
    for (int s = 0; s < STG; s++) {
        saA[s] = (uint32_t)__cvta_generic_to_shared(&smA[s][0]);
        saB[s] = (uint32_t)__cvta_generic_to_shared(&smB[s][0]);
    }

    float acc[4][4][4];
#pragma unroll
    for (int i = 0; i < 4; i++)
#pragma unroll
        for (int j = 0; j < 4; j++)
#pragma unroll
            for (int r = 0; r < 4; r++) acc[i][j][r] = 0.0f;

    const int NIT = K / 32;

#pragma unroll
    for (int s = 0; s < STG - 1; s++) {
        cp16(saA[s] + offA0, Agr + s * 32);
        cp16(saA[s] + offA1, Agr + s * 32 + 8);
        cp16(saB[s] + offA0, Bgr + s * 16);
        cp16(saB[s] + offA1, Bgr + s * 16 + 4);
        CP_COMMIT();
    }

    const int lr = lane & 15;
    const int lc = lane >> 4;
    int aoff[4][2];
#pragma unroll
    for (int mt = 0; mt < 4; mt++) {
        const int r = wm + mt * 16 + lr;
        const int sw = (r >> 1) & 3;
#pragma unroll
        for (int kk = 0; kk < 2; kk++)
            aoff[mt][kk] = (r * 4 + ((2 * kk + lc) ^ sw)) * 16;
    }

    int st = 0;
    for (int it = 0; it < NIT; it++) {
        CP_WAIT1();
        __syncthreads();

        if (it + STG - 1 < NIT) {
            const int s2 = (st + STG - 1) % STG;
            const int kof = (it + STG - 1) * 32;
            cp16(saA[s2] + offA0, Agr + kof);
            cp16(saA[s2] + offA1, Agr + kof + 8);
            cp16(saB[s2] + offA0, Bgr + kof / 2);
            cp16(saB[s2] + offA1, Bgr + kof / 2 + 4);
        }
        CP_COMMIT();

        const uint32_t sa = saA[st];
        const uint32_t* Bs = (const uint32_t*)&smB[st][0];
#pragma unroll
        for (int kk = 0; kk < 2; kk++) {
            uint32_t a[4][4];
#pragma unroll
            for (int mt = 0; mt < 4; mt++)
                ldsm_x4(a[mt][0], a[mt][1], a[mt][2], a[mt][3], sa + aoff[mt][kk]);
            uint32_t b0[4], b1[4];
#pragma unroll
            for (int nt = 0; nt < 4; nt++) {
                const int n = wn + nt * 8 + g;
                const int v = (n >> 1) & 3;
                b0[nt] = Bs[n * 16 + (((2 * kk)     ^ v) << 2) + t];
                b1[nt] = Bs[n * 16 + (((2 * kk + 1) ^ v) << 2) + t];
            }
#pragma unroll
            for (int mt = 0; mt < 4; mt++)
#pragma unroll
                for (int nt = 0; nt < 4; nt++)
                    mma_f16(acc[mt][nt], a[mt][0], a[mt][1], a[mt][2], a[mt][3],
                            b0[nt], b1[nt]);
        }
        st = (st + 1) % STG;
    }

    // epilogue (fp32 or fp16 destination)
    __half* Ch = ga.Ch[z];
    float*  C  = ga.C[z];
#pragma unroll
    for (int mt = 0; mt < 4; mt++) {
#pragma unroll
        for (int nt = 0; nt < 4; nt++) {
            const int row = bm + wm + mt * 16 + g;
            const int col = bn + wn + nt * 8 + t * 2;
            float b0 = bias[col], b1 = bias[col + 1];
            float v00 = acc[mt][nt][0] + b0, v01 = acc[mt][nt][1] + b1;
            float v10 = acc[mt][nt][2] + b0, v11 = acc[mt][nt][3] + b1;
            if (Ch) {
                __half2 h0 = __floats2half2_rn(v00, v01);
                __half2 h1 = __floats2half2_rn(v10, v11);
                *(uint32_t*)(Ch + (size_t)row * N + col)       = *(uint32_t*)&h0;
                *(uint32_t*)(Ch + (size_t)(row + 8) * N + col) = *(uint32_t*)&h1;
            } else {
                *(float2*)(C + (size_t)row * N + col)       = make_float2(v00, v01);
                *(float2*)(C + (size_t)(row + 8) * N + col) = make_float2(v10, v11);
            }
        }
    }
}

// ---------------------------------------------------------------------------
// Flash attention (causal), all-fp16 operands, fp32 accum.
// Br=128 x Bc=64, 256 threads (8 warps x 16 q-rows).
// K/V tiles: row-major fp16, cp.async 3-stage ring, ONE sync per tile.
// Smem swizzle: 16B chunk' = chunk ^ (row & 7)  (row = token, 8 chunks/row).
// QK^T: f16 m16n8k16, Q frags from gmem, K B-frags conflict-free LDS.32.
// P*V : f16 m16n8k16, P in registers (FA2 layout match), V B-frags via
//       ldmatrix.x4.trans.
// ---------------------------------------------------------------------------
__global__ __launch_bounds__(256)
void flash_attn_mma(const __half* __restrict__ Q, const __half* __restrict__ K,
                    const __half* __restrict__ V, __half* __restrict__ X)
{
    __shared__ __align__(16) __half Ks[STG][64 * 64];
    __shared__ __align__(16) __half Vs[STG][64 * 64];

    const int qb = (int)(gridDim.x - 1 - blockIdx.x);  // heavy tiles first
    const int bh = blockIdx.y;
    const int b  = bh >> 4;
    const int h  = bh & 15;
    const int tid  = threadIdx.x;
    const int lane = tid & 31;
    const int warp = tid >> 5;
    const int g = lane >> 2;
    const int t = lane & 3;
    const int wr0 = warp * 16;

    const int rowstride = BAT * DM;               // 2048 halves
    const int headoff = b * DM + h * DHD;

    uint32_t ksb[STG], vsb[STG];
#pragma unroll
    for (int s = 0; s < STG; s++) {
        ksb[s] = (uint32_t)__cvta_generic_to_shared(&Ks[s][0]);
        vsb[s] = (uint32_t)__cvta_generic_to_shared(&Vs[s][0]);
    }

    // staging: thread owns row rS, chunks c0, c0+1 of both K and V
    const int rS = tid >> 2;                 // 0..63
    const int c0 = (tid & 3) * 2;            // 0,2,4,6
    const int offS0 = (rS * 8 + (c0 ^ (rS & 7))) * 16;
    const int offS1 = (rS * 8 + ((c0 + 1) ^ (rS & 7))) * 16;
    const __half* Kgr = K + (size_t)rS * rowstride + headoff + c0 * 8;
    const __half* Vgr = V + (size_t)rS * rowstride + headoff + c0 * 8;

    // ---- Q fragments (fp16) straight from gmem ----
    uint32_t qa[4][4];
    {
        const __half* Qr0 = Q + (size_t)(qb * 128 + wr0 + g) * rowstride + headoff;
        const __half* Qr8 = Qr0 + 8 * rowstride;
#pragma unroll
        for (int kk = 0; kk < 4; kk++) {
            qa[kk][0] = *(const uint32_t*)(Qr0 + 16 * kk + 2 * t);
            qa[kk][1] = *(const uint32_t*)(Qr8 + 16 * kk + 2 * t);
            qa[kk][2] = *(const uint32_t*)(Qr0 + 16 * kk + 8 + 2 * t);
            qa[kk][3] = *(const uint32_t*)(Qr8 + 16 * kk + 8 + 2 * t);
        }
    }

    float o[8][4];
#pragma unroll
    for (int nt = 0; nt < 8; nt++)
#pragma unroll
        for (int r = 0; r < 4; r++) o[nt][r] = 0.0f;
    float m0 = -1e30f, m1 = -1e30f, l0 = 0.0f, l1 = 0.0f;

    const int kbmax = 2 * qb + 1;

    // prologue: stages 0, 1
#pragma unroll
    for (int s = 0; s < 2; s++) {
        const size_t go = (size_t)(s * 64) * rowstride;
        cp16(ksb[s] + offS0, Kgr + go);
        cp16(ksb[s] + offS1, Kgr + go + 8);
        cp16(vsb[s] + offS0, Vgr + go);
        cp16(vsb[s] + offS1, Vgr + go + 8);
        CP_COMMIT();
    }

    for (int kb = 0; kb <= kbmax; kb++) {
        const int st = kb % STG;
        __syncthreads();   // all threads done computing kb-1 (slot (kb+2)%3 free)

        if (kb + 2 <= kbmax) {
            const int s2 = (kb + 2) % STG;
            const size_t go = (size_t)((kb + 2) * 64) * rowstride;
            cp16(ksb[s2] + offS0, Kgr + go);
            cp16(ksb[s2] + offS1, Kgr + go + 8);
            cp16(vsb[s2] + offS0, Vgr + go);
            cp16(vsb[s2] + offS1, Vgr + go + 8);
        }
        CP_COMMIT();
        CP_WAIT2();        // stage kb complete (kb+1, kb+2 may be in flight)

        // ---- S = Q @ K^T ----
        const uint32_t* KsW = (const uint32_t*)&Ks[st][0];
        float s[8][4];
#pragma unroll
        for (int nt = 0; nt < 8; nt++)
#pragma unroll
            for (int r = 0; r < 4; r++) s[nt][r] = 0.0f;

#pragma unroll
        for (int kk = 0; kk < 4; kk++) {
#pragma unroll
            for (int nt = 0; nt < 8; nt++) {
                const int n = nt * 8 + g;      // n & 7 == g
                uint32_t b0 = KsW[n * 32 + (((2 * kk)     ^ g) << 2) + t];
                uint32_t b1 = KsW[n * 32 + (((2 * kk + 1) ^ g) << 2) + t];
                mma_f16(s[nt], qa[kk][0], qa[kk][1], qa[kk][2], qa[kk][3], b0, b1);
            }
        }

        // ---- scale + causal mask ----
        const int rg  = qb * 128 + wr0 + g;
        const int rg8 = rg + 8;
        if (kb * 64 + 63 > qb * 128 + wr0) {
#pragma unroll
            for (int nt = 0; nt < 8; nt++) {
                int cc = kb * 64 + nt * 8 + 2 * t;
                s[nt][0] = (cc     > rg ) ? -1e30f : s[nt][0] * 0.125f;
                s[nt][1] = (cc + 1 > rg ) ? -1e30f : s[nt][1] * 0.125f;
                s[nt][2] = (cc     > rg8) ? -1e30f : s[nt][2] * 0.125f;
                s[nt][3] = (cc + 1 > rg8) ? -1e30f : s[nt][3] * 0.125f;
            }
        } else {
#pragma unroll
            for (int nt = 0; nt < 8; nt++)
#pragma unroll
                for (int r = 0; r < 4; r++) s[nt][r] *= 0.125f;
        }

        // ---- online softmax ----
        float mx0 = -1e30f, mx1 = -1e30f;
#pragma unroll
        for (int nt = 0; nt < 8; nt++) {
            mx0 = fmaxf(mx0, fmaxf(s[nt][0], s[nt][1]));
            mx1 = fmaxf(mx1, fmaxf(s[nt][2], s[nt][3]));
        }
        mx0 = fmaxf(mx0, __shfl_xor_sync(0xffffffffu, mx0, 1));
        mx0 = fmaxf(mx0, __shfl_xor_sync(0xffffffffu, mx0, 2));
        mx1 = fmaxf(mx1, __shfl_xor_sync(0xffffffffu, mx1, 1));
        mx1 = fmaxf(mx1, __shfl_xor_sync(0xffffffffu, mx1, 2));

        float mn0 = fmaxf(m0, mx0), mn1 = fmaxf(m1, mx1);
        float corr0 = __expf(m0 - mn0), corr1 = __expf(m1 - mn1);
        m0 = mn0; m1 = mn1;

        float rs0 = 0.0f, rs1 = 0.0f;
        uint32_t ph[8], ph8[8];
#pragma unroll
        for (int nt = 0; nt < 8; nt++) {
            float p0 = __expf(s[nt][0] - mn0);
            float p1 = __expf(s[nt][1] - mn0);
            float p2 = __expf(s[nt][2] - mn1);
            float p3 = __expf(s[nt][3] - mn1);
            rs0 += p0 + p1;
            rs1 += p2 + p3;
            __half2 h0 = __floats2half2_rn(p0, p1);
            __half2 h1 = __floats2half2_rn(p2, p3);
            ph[nt]  = *(uint32_t*)&h0;
            ph8[nt] = *(uint32_t*)&h1;
        }
        rs0 += __shfl_xor_sync(0xffffffffu, rs0, 1);
        rs0 += __shfl_xor_sync(0xffffffffu, rs0, 2);
        rs1 += __shfl_xor_sync(0xffffffffu, rs1, 1);
        rs1 += __shfl_xor_sync(0xffffffffu, rs1, 2);
        l0 = l0 * corr0 + rs0;
        l1 = l1 * corr1 + rs1;

#pragma unroll
        for (int nt = 0; nt < 8; nt++) {
            o[nt][0] *= corr0; o[nt][1] *= corr0;
            o[nt][2] *= corr1; o[nt][3] *= corr1;
        }

        // ---- O += P @ V  (V B-frags via ldmatrix.x4.trans) ----
        const int lsub = lane & 7;
        const int sel  = lane >> 3;
        const int vrowbase = (sel & 1) * 8 + lsub;       // row within 16-block
        const int vchsel   = sel >> 1;                   // 0 or 1 (n +8)
#pragma unroll
        for (int kk = 0; kk < 4; kk++) {
            const int vrow = 16 * kk + vrowbase;
#pragma unroll
            for (int ntp = 0; ntp < 4; ntp++) {
                const int chunk = 2 * ntp + vchsel;
                uint32_t addr = vsb[st] + (vrow * 8 + (chunk ^ (vrow & 7))) * 16;
                uint32_t r0, r1, r2, r3;
                ldsm_x4_trans(r0, r1, r2, r3, addr);
                mma_f16(o[2 * ntp],     ph[2 * kk], ph8[2 * kk],
                        ph[2 * kk + 1], ph8[2 * kk + 1], r0, r1);
                mma_f16(o[2 * ntp + 1], ph[2 * kk], ph8[2 * kk],
                        ph[2 * kk + 1], ph8[2 * kk + 1], r2, r3);
            }
        }
    }

    // ---- epilogue: normalize, write fp16 ----
    float inv0 = 1.0f / l0, inv1 = 1.0f / l1;
    __half* Xr0 = X + (size_t)(qb * 128 + wr0 + g) * rowstride + headoff;
    __half* Xr8 = Xr0 + 8 * rowstride;
#pragma unroll
    for (int nt = 0; nt < 8; nt++) {
        __half2 h0 = __floats2half2_rn(o[nt][0] * inv0, o[nt][1] * inv0);
        __half2 h1 = __floats2half2_rn(o[nt][2] * inv1, o[nt][3] * inv1);
        *(uint32_t*)(Xr0 + nt * 8 + 2 * t) = *(uint32_t*)&h0;
        *(uint32_t*)(Xr8 + nt * 8 + 2 * t) = *(uint32_t*)&h1;
    }
}

// ---------------------------------------------------------------------------
// kernel_launch
// Inputs: query, key, value, mask, Wq, bq, Wk, bk, Wv, bv, Wo, bo
// ---------------------------------------------------------------------------
extern "C" void kernel_launch(void* const* d_in, const int* in_sizes, int n_in,
                              void* d_out, int out_size)
{
    const float* query = (const float*)d_in[0];
    const float* key   = (const float*)d_in[1];
    const float* value = (const float*)d_in[2];
    // d_in[3] = mask (tril causal) — handled analytically in flash_attn_mma
    const float* Wq = (const float*)d_in[4];
    const float* bq = (const float*)d_in[5];
    const float* Wk = (const float*)d_in[6];
    const float* bk = (const float*)d_in[7];
    const float* Wv = (const float*)d_in[8];
    const float* bv = (const float*)d_in[9];
    const float* Wo = (const float*)d_in[10];
    const float* bo = (const float*)d_in[11];
    float* out = (float*)d_out;

    __half *hq, *hk, *hv, *pq, *pk, *pv, *hx;
    uint32_t* wt;
    cudaGetSymbolAddress((void**)&hq, g_hq);
    cudaGetSymbolAddress((void**)&hk, g_hk);
    cudaGetSymbolAddress((void**)&hv, g_hv);
    cudaGetSymbolAddress((void**)&pq, g_pq);
    cudaGetSymbolAddress((void**)&pk, g_pk);
    cudaGetSymbolAddress((void**)&pv, g_pv);
    cudaGetSymbolAddress((void**)&hx, g_hx);
    cudaGetSymbolAddress((void**)&wt, g_wt);

    uint32_t* wtq = wt;
    uint32_t* wtk = wt + (size_t)DM * DM / 2;
    uint32_t* wtv = wt + (size_t)DM * DM;
    uint32_t* wto = wt + (size_t)DM * DM * 3 / 2;

    // 1) convert inputs fp32 -> fp16
    CvtArgs ca;
    ca.src[0] = query; ca.dst[0] = hq;
    ca.src[1] = key;   ca.dst[1] = hk;
    ca.src[2] = value; ca.dst[2] = hv;
    cvt_f2h<<<dim3(NTOK * DM / 1024, 1, 3), 256>>>(ca, NTOK * DM);

    // 2) convert + transpose + pair-pack weights
    CvtWArgs cw;
    cw.W[0] = Wq; cw.Wt[0] = wtq;
    cw.W[1] = Wk; cw.Wt[1] = wtk;
    cw.W[2] = Wv; cw.Wt[2] = wtv;
    cw.W[3] = Wo; cw.Wt[3] = wto;
    cvt_w_trans<<<dim3(DM / 32, DM / 32, 4), 256>>>(cw);

    // 3) fused Q/K/V projections (fp16 outputs)
    HGemmArgs proj;
    proj.A[0] = hq; proj.Bt[0] = wtq; proj.bias[0] = bq; proj.C[0] = nullptr; proj.Ch[0] = pq;
    proj.A[1] = hk; proj.Bt[1] = wtk; proj.bias[1] = bk; proj.C[1] = nullptr; proj.Ch[1] = pk;
    proj.A[2] = hv; proj.Bt[2] = wtv; proj.bias[2] = bv; proj.C[2] = nullptr; proj.Ch[2] = pv;
    h16_gemm_pipe<<<dim3(DM / 128, NTOK / 128, 3), 256>>>(proj, NTOK, DM, DM);

    // 4) attention (fp16 in, fp16 out)
    flash_attn_mma<<<dim3(SEQ / 128, BAT * NH), 256>>>(pq, pk, pv, hx);

    // 5) output projection (fp32 output)
    HGemmArgs oproj;
    oproj.A[0] = hx; oproj.Bt[0] = wto; oproj.bias[0] = bo; oproj.C[0] = out; oproj.Ch[0] = nullptr;
    oproj.A[1] = hx; oproj.Bt[1] = wto; oproj.bias[1] = bo; oproj.C[1] = out; oproj.Ch[1] = nullptr;
    oproj.A[2] = hx; oproj.Bt[2] = wto; oproj.bias[2] = bo; oproj.C[2] = out; oproj.Ch[2] = nullptr;
    h16_gemm_pipe<<<dim3(DM / 128, NTOK / 128, 1), 256>>>(oproj, NTOK, DM, DM);
}

// round 11
// speedup vs baseline: 5.7840x; 1.0878x over previous
#include <cuda_runtime.h>
#include <cuda_fp16.h>
#include <math.h>
#include <stdint.h>

// Problem constants (fixed by the reference)
#define SEQ   2048
#define BAT   2
#define NH    16
#define DHD   64
#define DM    1024
#define NTOK  (SEQ * BAT)   // 4096

// ---------------------------------------------------------------------------
// Arch-feature gate: tcgen05 only exists on the sm_103a ('a'-feature) target.
// The build also runs a plain compute_103 PTX pass, which must get a clean
// fallback. Wrong/missing macro ==> fallback everywhere (correct, slower).
// ---------------------------------------------------------------------------
#ifndef __CUDA_ARCH_HAS_FEATURE__
#define __CUDA_ARCH_HAS_FEATURE__(x) 0
#endif
#if defined(__CUDA_ARCH__) && \
    (defined(__CUDA_ARCH_FEAT_SM103_ALL) || __CUDA_ARCH_HAS_FEATURE__(SM103_ALL))
#define USE_TCG 1
#else
#define USE_TCG 0
#endif

// Scratch (allocation-free rule: __device__ globals)
__device__ __half  g_hq[NTOK * DM];       // fp16 copies of query/key/value (gemm A)
__device__ __half  g_hk[NTOK * DM];
__device__ __half  g_hv[NTOK * DM];
__device__ __half  g_pq[NTOK * DM];       // fp16 Q/K/V projections (flash input)
__device__ __half  g_pk[NTOK * DM];
__device__ __half  g_pv[NTOK * DM];
__device__ __half  g_hx[NTOK * DM];       // fp16 attention output (o-proj A)
__device__ uint32_t g_wt[4][DM * DM / 2]; // fp16 weights, transposed: Wt[n][k]

// ---------------------------------------------------------------------------
// common helpers
// ---------------------------------------------------------------------------
__device__ __forceinline__ void mma_f16(float* c, uint32_t a0, uint32_t a1,
                                        uint32_t a2, uint32_t a3,
                                        uint32_t b0, uint32_t b1) {
    asm volatile(
        "mma.sync.aligned.m16n8k16.row.col.f32.f16.f16.f32 "
        "{%0,%1,%2,%3}, {%4,%5,%6,%7}, {%8,%9}, {%0,%1,%2,%3};"
        : "+f"(c[0]), "+f"(c[1]), "+f"(c[2]), "+f"(c[3])
        : "r"(a0), "r"(a1), "r"(a2), "r"(a3), "r"(b0), "r"(b1));
}

__device__ __forceinline__ void ldsm_x4(uint32_t& r0, uint32_t& r1,
                                        uint32_t& r2, uint32_t& r3, uint32_t addr) {
    asm volatile("ldmatrix.sync.aligned.m8n8.x4.shared.b16 {%0,%1,%2,%3}, [%4];"
                 : "=r"(r0), "=r"(r1), "=r"(r2), "=r"(r3) : "r"(addr));
}

__device__ __forceinline__ void ldsm_x4_trans(uint32_t& r0, uint32_t& r1,
                                              uint32_t& r2, uint32_t& r3, uint32_t addr) {
    asm volatile("ldmatrix.sync.aligned.m8n8.x4.trans.shared.b16 {%0,%1,%2,%3}, [%4];"
                 : "=r"(r0), "=r"(r1), "=r"(r2), "=r"(r3) : "r"(addr));
}

__device__ __forceinline__ void cp16(uint32_t saddr, const void* g) {
    asm volatile("cp.async.cg.shared.global [%0], [%1], 16;" :: "r"(saddr), "l"(g));
}
#define CP_COMMIT() asm volatile("cp.async.commit_group;")
#define CP_WAIT0()  asm volatile("cp.async.wait_group 0;" ::: "memory")
#define CP_WAIT1()  asm volatile("cp.async.wait_group 1;" ::: "memory")
#define CP_WAIT2()  asm volatile("cp.async.wait_group 2;" ::: "memory")

// ---------------------------------------------------------------------------
// tcgen05 helpers (only referenced inside USE_TCG-guarded code)
// ---------------------------------------------------------------------------
#if USE_TCG
__device__ __forceinline__ uint32_t elect_one_pred() {
    uint32_t pred;
    asm volatile("{\n\t.reg .pred p;\n\telect.sync _|p, 0xFFFFFFFF;\n\t"
                 "selp.b32 %0, 1, 0, p;\n\t}" : "=r"(pred));
    return pred;
}

__device__ __forceinline__ void tcg_mma_f16_ss(uint32_t d_tmem, uint64_t a_desc,
                                               uint64_t b_desc, uint32_t idesc,
                                               bool accum) {
    uint32_t en = accum ? 1u : 0u;
    asm volatile(
        "{\n\t"
        ".reg .pred p;\n\t"
        "setp.ne.u32 p, %4, 0;\n\t"
        "tcgen05.mma.cta_group::1.kind::f16 [%0], %1, %2, %3, {%5,%5,%5,%5}, p;\n\t"
        "}"
        :: "r"(d_tmem), "l"(a_desc), "l"(b_desc), "r"(idesc), "r"(en), "r"(0u)
        : "memory");
}

#define TCG_ALLOC(sm_addr, ncols) \
    asm volatile("tcgen05.alloc.cta_group::1.sync.aligned.shared::cta.b32 [%0], %1;" \
                 :: "r"(sm_addr), "r"((uint32_t)(ncols)) : "memory")
#define TCG_DEALLOC(tmem, ncols) \
    asm volatile("tcgen05.dealloc.cta_group::1.sync.aligned.b32 %0, %1;" \
                 :: "r"(tmem), "r"((uint32_t)(ncols)))
#define TCG_COMMIT(mbar) \
    asm volatile("tcgen05.commit.cta_group::1.mbarrier::arrive::one.shared::cluster.b64 [%0];" \
                 :: "r"(mbar) : "memory")
#define TCG_FENCE_AFTER() asm volatile("tcgen05.fence::after_thread_sync;" ::: "memory")
#define TCG_WAIT_LD()     asm volatile("tcgen05.wait::ld.sync.aligned;" ::: "memory")
#define FENCE_ASYNC()     asm volatile("fence.proxy.async.shared::cta;" ::: "memory")

#define MBAR_INIT(a, n) \
    asm volatile("mbarrier.init.shared.b64 [%0], %1;" :: "r"(a), "r"((uint32_t)(n)) : "memory")
#define MBAR_WAIT(a, par) do {                                                  \
    asm volatile("{\n\t.reg .pred P1;\n\t"                                      \
        "WL_%=:\n\t"                                                            \
        "mbarrier.try_wait.parity.acquire.cta.shared::cta.b64 P1, [%0], %1, 0x989680;\n\t" \
        "@P1 bra.uni WD_%=;\n\t"                                                \
        "bra.uni WL_%=;\n\t"                                                    \
        "WD_%=:\n\t}" :: "r"(a), "r"((uint32_t)(par)) : "memory");              \
} while (0)

__device__ __forceinline__ void ldtm_x32(uint32_t* r, uint32_t tmem_addr) {
    asm volatile(
        "tcgen05.ld.sync.aligned.32x32b.x32.b32 "
        "{%0,%1,%2,%3,%4,%5,%6,%7,%8,%9,%10,%11,%12,%13,%14,%15,"
        "%16,%17,%18,%19,%20,%21,%22,%23,%24,%25,%26,%27,%28,%29,%30,%31}, [%32];"
        : "=r"(r[0]), "=r"(r[1]), "=r"(r[2]), "=r"(r[3]),
          "=r"(r[4]), "=r"(r[5]), "=r"(r[6]), "=r"(r[7]),
          "=r"(r[8]), "=r"(r[9]), "=r"(r[10]), "=r"(r[11]),
          "=r"(r[12]), "=r"(r[13]), "=r"(r[14]), "=r"(r[15]),
          "=r"(r[16]), "=r"(r[17]), "=r"(r[18]), "=r"(r[19]),
          "=r"(r[20]), "=r"(r[21]), "=r"(r[22]), "=r"(r[23]),
          "=r"(r[24]), "=r"(r[25]), "=r"(r[26]), "=r"(r[27]),
          "=r"(r[28]), "=r"(r[29]), "=r"(r[30]), "=r"(r[31])
        : "r"(tmem_addr));
}
#endif // USE_TCG

// ---------------------------------------------------------------------------
// Convert kernels
// ---------------------------------------------------------------------------
struct CvtArgs { const float* src[3]; __half* dst[3]; };

__global__ __launch_bounds__(256)
void cvt_f2h(CvtArgs ca, int n)
{
    const float* __restrict__ s = ca.src[blockIdx.z];
    __half* __restrict__ d = ca.dst[blockIdx.z];
    int idx = (blockIdx.x * 256 + threadIdx.x) * 4;
    if (idx < n) {
        float4 v = *(const float4*)(s + idx);
        __half2 h0 = __floats2half2_rn(v.x, v.y);
        __half2 h1 = __floats2half2_rn(v.z, v.w);
        uint2 u;
        u.x = *(uint32_t*)&h0;
        u.y = *(uint32_t*)&h1;
        *(uint2*)(d + idx) = u;
    }
}

// Weight convert + transpose: Wt[n][k] fp16 row-major
struct CvtWArgs { const float* W[4]; uint32_t* Wt[4]; };

__global__ __launch_bounds__(256)
void cvt_w_trans(CvtWArgs cw)
{
    __shared__ float T[32][33];
    const float* __restrict__ W = cw.W[blockIdx.z];
    uint32_t* __restrict__ Wt = cw.Wt[blockIdx.z];
    const int k0 = blockIdx.x * 32;
    const int n0 = blockIdx.y * 32;
    const int tid = threadIdx.x;

#pragma unroll
    for (int i = 0; i < 4; i++) {
        int kk = i * 8 + (tid >> 5);
        int nn = tid & 31;
        T[kk][nn] = W[(size_t)(k0 + kk) * DM + n0 + nn];
    }
    __syncthreads();

#pragma unroll
    for (int i = 0; i < 2; i++) {
        int p = tid + i * 256;
        int nn = p >> 4;
        int j2 = p & 15;
        __half2 h = __floats2half2_rn(T[2 * j2][nn], T[2 * j2 + 1][nn]);
        Wt[(size_t)(n0 + nn) * (DM / 2) + (k0 / 2) + j2] = *(uint32_t*)&h;
    }
}

// ---------------------------------------------------------------------------
// GEMM: C[M,N] = A[M,K] @ Wt[N,K]^T + bias   (fp16 in, f32 accum)
// sm_103a cubin: tcgen05 SS MMA (TMEM accumulator, SW128 smem, cp.async).
// PTX/other:     mma.sync m16n8k16 3-stage cp.async pipeline (proven R8 path).
// Both consume the same Wt[n][k] fp16 layout and same dynamic smem size.
// ---------------------------------------------------------------------------
#define GS_A0    0
#define GS_A1    16384
#define GS_B0    32768
#define GS_B1    49152
#define GS_MBAR0 67840
#define GS_MBAR1 67848
#define GS_TMEMP 67856
#define GS_BIAS  68096
#define GS_TOTAL 68608

struct TCGemmArgs {
    const __half* A[3];
    const __half* W[3];     // Wt[n][k] fp16
    const float*  bias[3];
    float*        C[3];     // fp32 out (if Ch null)
    __half*       Ch[3];    // fp16 out (if non-null)
};

__global__ __launch_bounds__(256)
void tc_gemm(TCGemmArgs ga, int M, int N, int K)
{
    extern __shared__ __align__(1024) unsigned char sm[];
    const int z = blockIdx.z;
    const __half* __restrict__ A = ga.A[z];
    const __half* __restrict__ W = ga.W[z];
    const float*  __restrict__ bias = ga.bias[z];

    const uint32_t smb = (uint32_t)__cvta_generic_to_shared(sm);
    const int tid  = threadIdx.x;
    const int lane = tid & 31;
    const int warp = tid >> 5;
    const int bm = blockIdx.y * 128;
    const int bn = blockIdx.x * 128;

#if USE_TCG
    // =================== tcgen05 path ===================
    if (tid == 0) {
        MBAR_INIT(smb + GS_MBAR0, 1);
        MBAR_INIT(smb + GS_MBAR1, 1);
    }
    if (warp == 0) TCG_ALLOC(smb + GS_TMEMP, 128);
    if (tid < 128) ((float*)(sm + GS_BIAS))[tid] = bias[bn + tid];

    // staging map: thread -> row rA, 4 16B chunks starting at cb (SW128 swizzle)
    const int rA = tid >> 1;
    const int cb = (tid & 1) * 4;
    int soff[4];
#pragma unroll
    for (int j = 0; j < 4; j++)
        soff[j] = (rA * 8 + ((cb + j) ^ (rA & 7))) * 16;

    const __half* Ag = A + (size_t)(bm + rA) * K + cb * 8;
    const __half* Wg = W + (size_t)(bn + rA) * K + cb * 8;
    const uint32_t bufA[2] = { smb + GS_A0, smb + GS_A1 };
    const uint32_t bufB[2] = { smb + GS_B0, smb + GS_B1 };

#pragma unroll
    for (int s = 0; s < 2; s++) {
#pragma unroll
        for (int j = 0; j < 4; j++) cp16(bufA[s] + soff[j], Ag + s * 64 + j * 8);
#pragma unroll
        for (int j = 0; j < 4; j++) cp16(bufB[s] + soff[j], Wg + s * 64 + j * 8);
        CP_COMMIT();
    }
    __syncthreads();   // mbar init + tmem ptr visible

    uint32_t tmem;
    asm volatile("ld.shared.b32 %0, [%1];" : "=r"(tmem) : "r"(smb + GS_TMEMP));

    // SW128 desc: layout=2, version=1, SBO=64, LBO=1
    const unsigned long long DESC_SW128 =
        (2ULL << 61) | (1ULL << 46) | (64ULL << 32) | (1ULL << 16);
    // idesc: M=128 (8<<24), N=128 (16<<17), f32 accum (1<<4), f16 a/b
    const uint32_t TC_IDESC = 0x08200010u;

    uint64_t dA[2], dB[2];
#pragma unroll
    for (int s = 0; s < 2; s++) {
        dA[s] = DESC_SW128 | ((uint64_t)(bufA[s] >> 4) & 0x3FFF);
        dB[s] = DESC_SW128 | ((uint64_t)(bufB[s] >> 4) & 0x3FFF);
    }

    const int NCH = K / 64;   // 16
    int ph0 = 0, ph1 = 0;
    for (int ch = 0; ch < NCH; ch++) {
        const int b = ch & 1;
        if (ch == NCH - 1) { CP_WAIT0(); } else { CP_WAIT1(); }
        __syncthreads();

        if (warp == 0 && elect_one_pred()) {
            FENCE_ASYNC();
#pragma unroll
            for (int ks = 0; ks < 4; ks++)
                tcg_mma_f16_ss(tmem, dA[b] + ks * 2, dB[b] + ks * 2, TC_IDESC,
                               !(ch == 0 && ks == 0));
            TCG_COMMIT(smb + (b ? GS_MBAR1 : GS_MBAR0));
        }

        if (b == 0) { MBAR_WAIT(smb + GS_MBAR0, ph0); ph0 ^= 1; }
        else        { MBAR_WAIT(smb + GS_MBAR1, ph1); ph1 ^= 1; }

        if (ch + 2 < NCH) {
            const __half* a2 = Ag + (ch + 2) * 64;
            const __half* w2 = Wg + (ch + 2) * 64;
#pragma unroll
            for (int j = 0; j < 4; j++) cp16(bufA[b] + soff[j], a2 + j * 8);
#pragma unroll
            for (int j = 0; j < 4; j++) cp16(bufB[b] + soff[j], w2 + j * 8);
            CP_COMMIT();
        }
    }

    // epilogue: TMEM -> smem -> gmem
    TCG_FENCE_AFTER();
    __half* Ch = ga.Ch[z];
    float*  C  = ga.C[z];

    if (warp < 4) {
        const int row = warp * 32 + lane;
#pragma unroll
        for (int cs = 0; cs < 4; cs++) {
            uint32_t r[32];
            ldtm_x32(r, tmem + cs * 32);
            TCG_WAIT_LD();
            if (Ch) {
                uint32_t* epi = (uint32_t*)sm;
#pragma unroll
                for (int j = 0; j < 16; j++) {
                    float v0 = __uint_as_float(r[2 * j])     + ((float*)(sm + GS_BIAS))[cs * 32 + 2 * j];
                    float v1 = __uint_as_float(r[2 * j + 1]) + ((float*)(sm + GS_BIAS))[cs * 32 + 2 * j + 1];
                    __half2 h = __floats2half2_rn(v0, v1);
                    epi[row * 66 + cs * 16 + j] = *(uint32_t*)&h;
                }
            } else {
                float* epi = (float*)sm;
#pragma unroll
                for (int j = 0; j < 32; j++)
                    epi[row * 132 + cs * 32 + j] =
                        __uint_as_float(r[j]) + ((float*)(sm + GS_BIAS))[cs * 32 + j];
            }
        }
    }
    __syncthreads();

    if (Ch) {
        const uint32_t* epi = (const uint32_t*)sm;
#pragma unroll
        for (int it = 0; it < 16; it++) {
            int idx = it * 256 + tid;
            int r = idx >> 5, c2 = idx & 31;
            uint2 v = *(const uint2*)(epi + r * 66 + c2 * 2);
            *(uint2*)(Ch + (size_t)(bm + r) * N + bn + c2 * 4) = v;
        }
    } else {
        const float* epi = (const float*)sm;
#pragma unroll
        for (int it = 0; it < 16; it++) {
            int idx = it * 256 + tid;
            int r = idx >> 5, c4 = (idx & 31) * 4;
            float4 v = *(const float4*)(epi + r * 132 + c4);
            *(float4*)(C + (size_t)(bm + r) * N + bn + c4) = v;
        }
    }

    __syncthreads();
    if (warp == 0) TCG_DEALLOC(tmem, 128);

#else
    // =================== mma.sync fallback (R8 pipeline) ===================
    // dynamic smem: smA[s] @ s*8192, smB[s] @ 24576 + s*8192  (3 stages)
    const uint32_t* Bt = (const uint32_t*)W;     // Wt[n][k] == pair-packed u32
    const int g = lane >> 2;
    const int t = lane & 3;
    const int wm = (warp & 1) * 64;
    const int wn = (warp >> 1) * 32;

    const int rS  = tid >> 1;
    const int cS0 = (tid & 1) * 2;
    const int swS = (rS >> 1) & 3;
    const int offA0 = (rS * 4 + (cS0 ^ swS)) * 16;
    const int offA1 = (rS * 4 + ((cS0 + 1) ^ swS)) * 16;
    const __half*   Agr = A  + (size_t)(bm + rS) * K + cS0 * 8;
    const uint32_t* Bgr = Bt + (size_t)(bn + rS) * (K / 2) + cS0 * 4;

    uint32_t saA[3], saB[3];
#pragma unroll
    for (int s = 0; s < 3; s++) {
        saA[s] = smb + s * 8192;
        saB[s] = smb + 24576 + s * 8192;
    }

    float acc[4][4][4];
#pragma unroll
    for (int i = 0; i < 4; i++)
#pragma unroll
        for (int j = 0; j < 4; j++)
#pragma unroll
            for (int r = 0; r < 4; r++) acc[i][j][r] = 0.0f;

    const int NIT = K / 32;

#pragma unroll
    for (int s = 0; s < 2; s++) {
        cp16(saA[s] + offA0, Agr + s * 32);
        cp16(saA[s] + offA1, Agr + s * 32 + 8);
        cp16(saB[s] + offA0, Bgr + s * 16);
        cp16(saB[s] + offA1, Bgr + s * 16 + 4);
        CP_COMMIT();
    }

    const int lr = lane & 15;
    const int lc = lane >> 4;
    int aoff[4][2];
#pragma unroll
    for (int mt = 0; mt < 4; mt++) {
        const int r = wm + mt * 16 + lr;
        const int sw = (r >> 1) & 3;
#pragma unroll
        for (int kk = 0; kk < 2; kk++)
            aoff[mt][kk] = (r * 4 + ((2 * kk + lc) ^ sw)) * 16;
    }

    int st = 0;
    for (int it = 0; it < NIT; it++) {
        CP_WAIT1();
        __syncthreads();

        if (it + 2 < NIT) {
            const int s2 = (st + 2) % 3;
            const int kof = (it + 2) * 32;
            cp16(saA[s2] + offA0, Agr + kof);
            cp16(saA[s2] + offA1, Agr + kof + 8);
            cp16(saB[s2] + offA0, Bgr + kof / 2);
            cp16(saB[s2] + offA1, Bgr + kof / 2 + 4);
        }
        CP_COMMIT();

        const uint32_t sa = saA[st];
        const uint32_t* Bs = (const uint32_t*)(sm + 24576 + st * 8192);
#pragma unroll
        for (int kk = 0; kk < 2; kk++) {
            uint32_t a[4][4];
#pragma unroll
            for (int mt = 0; mt < 4; mt++)
                ldsm_x4(a[mt][0], a[mt][1], a[mt][2], a[mt][3], sa + aoff[mt][kk]);
            uint32_t b0[4], b1[4];
#pragma unroll
            for (int nt = 0; nt < 4; nt++) {
                const int n = wn + nt * 8 + g;
                const int v = (n >> 1) & 3;
                b0[nt] = Bs[n * 16 + (((2 * kk)     ^ v) << 2) + t];
                b1[nt] = Bs[n * 16 + (((2 * kk + 1) ^ v) << 2) + t];
            }
#pragma unroll
            for (int mt = 0; mt < 4; mt++)
#pragma unroll
                for (int nt = 0; nt < 4; nt++)
                    mma_f16(acc[mt][nt], a[mt][0], a[mt][1], a[mt][2], a[mt][3],
                            b0[nt], b1[nt]);
        }
        st = (st + 1) % 3;
    }

    __half* Ch = ga.Ch[z];
    float*  C  = ga.C[z];
#pragma unroll
    for (int mt = 0; mt < 4; mt++) {
#pragma unroll
        for (int nt = 0; nt < 4; nt++) {
            const int row = bm + wm + mt * 16 + g;
            const int col = bn + wn + nt * 8 + t * 2;
            float b0 = bias[col], b1 = bias[col + 1];
            float v00 = acc[mt][nt][0] + b0, v01 = acc[mt][nt][1] + b1;
            float v10 = acc[mt][nt][2] + b0, v11 = acc[mt][nt][3] + b1;
            if (Ch) {
                __half2 h0 = __floats2half2_rn(v00, v01);
                __half2 h1 = __floats2half2_rn(v10, v11);
                *(uint32_t*)(Ch + (size_t)row * N + col)       = *(uint32_t*)&h0;
                *(uint32_t*)(Ch + (size_t)(row + 8) * N + col) = *(uint32_t*)&h1;
            } else {
                *(float2*)(C + (size_t)row * N + col)       = make_float2(v00, v01);
                *(float2*)(C + (size_t)(row + 8) * N + col) = make_float2(v10, v11);
            }
        }
    }
#endif
}

// ---------------------------------------------------------------------------
// Flash attention (causal), all-fp16 operands, fp32 accum. (unchanged — 101us)
// ---------------------------------------------------------------------------
#define STG 3

__global__ __launch_bounds__(256)
void flash_attn_mma(const __half* __restrict__ Q, const __half* __restrict__ K,
                    const __half* __restrict__ V, __half* __restrict__ X)
{
    __shared__ __align__(16) __half Ks[STG][64 * 64];
    __shared__ __align__(16) __half Vs[STG][64 * 64];

    const int qb = (int)(gridDim.x - 1 - blockIdx.x);  // heavy tiles first
    const int bh = blockIdx.y;
    const int b  = bh >> 4;
    const int h  = bh & 15;
    const int tid  = threadIdx.x;
    const int lane = tid & 31;
    const int warp = tid >> 5;
    const int g = lane >> 2;
    const int t = lane & 3;
    const int wr0 = warp * 16;

    const int rowstride = BAT * DM;               // 2048 halves
    const int headoff = b * DM + h * DHD;

    uint32_t ksb[STG], vsb[STG];
#pragma unroll
    for (int s = 0; s < STG; s++) {
        ksb[s] = (uint32_t)__cvta_generic_to_shared(&Ks[s][0]);
        vsb[s] = (uint32_t)__cvta_generic_to_shared(&Vs[s][0]);
    }

    const int rS = tid >> 2;
    const int c0 = (tid & 3) * 2;
    const int offS0 = (rS * 8 + (c0 ^ (rS & 7))) * 16;
    const int offS1 = (rS * 8 + ((c0 + 1) ^ (rS & 7))) * 16;
    const __half* Kgr = K + (size_t)rS * rowstride + headoff + c0 * 8;
    const __half* Vgr = V + (size_t)rS * rowstride + headoff + c0 * 8;

    uint32_t qa[4][4];
    {
        const __half* Qr0 = Q + (size_t)(qb * 128 + wr0 + g) * rowstride + headoff;
        const __half* Qr8 = Qr0 + 8 * rowstride;
#pragma unroll
        for (int kk = 0; kk < 4; kk++) {
            qa[kk][0] = *(const uint32_t*)(Qr0 + 16 * kk + 2 * t);
            qa[kk][1] = *(const uint32_t*)(Qr8 + 16 * kk + 2 * t);
            qa[kk][2] = *(const uint32_t*)(Qr0 + 16 * kk + 8 + 2 * t);
            qa[kk][3] = *(const uint32_t*)(Qr8 + 16 * kk + 8 + 2 * t);
        }
    }

    float o[8][4];
#pragma unroll
    for (int nt = 0; nt < 8; nt++)
#pragma unroll
        for (int r = 0; r < 4; r++) o[nt][r] = 0.0f;
    float m0 = -1e30f, m1 = -1e30f, l0 = 0.0f, l1 = 0.0f;

    const int kbmax = 2 * qb + 1;

#pragma unroll
    for (int s = 0; s < 2; s++) {
        const size_t go = (size_t)(s * 64) * rowstride;
        cp16(ksb[s] + offS0, Kgr + go);
        cp16(ksb[s] + offS1, Kgr + go + 8);
        cp16(vsb[s] + offS0, Vgr + go);
        cp16(vsb[s] + offS1, Vgr + go + 8);
        CP_COMMIT();
    }

    for (int kb = 0; kb <= kbmax; kb++) {
        const int st = kb % STG;
        __syncthreads();

        if (kb + 2 <= kbmax) {
            const int s2 = (kb + 2) % STG;
            const size_t go = (size_t)((kb + 2) * 64) * rowstride;
            cp16(ksb[s2] + offS0, Kgr + go);
            cp16(ksb[s2] + offS1, Kgr + go + 8);
            cp16(vsb[s2] + offS0, Vgr + go);
            cp16(vsb[s2] + offS1, Vgr + go + 8);
        }
        CP_COMMIT();
        CP_WAIT2();

        const uint32_t* KsW = (const uint32_t*)&Ks[st][0];
        float s[8][4];
#pragma unroll
        for (int nt = 0; nt < 8; nt++)
#pragma unroll
            for (int r = 0; r < 4; r++) s[nt][r] = 0.0f;

#pragma unroll
        for (int kk = 0; kk < 4; kk++) {
#pragma unroll
            for (int nt = 0; nt < 8; nt++) {
                const int n = nt * 8 + g;
                uint32_t b0 = KsW[n * 32 + (((2 * kk)     ^ g) << 2) + t];
                uint32_t b1 = KsW[n * 32 + (((2 * kk + 1) ^ g) << 2) + t];
                mma_f16(s[nt], qa[kk][0], qa[kk][1], qa[kk][2], qa[kk][3], b0, b1);
            }
        }

        const int rg  = qb * 128 + wr0 + g;
        const int rg8 = rg + 8;
        if (kb * 64 + 63 > qb * 128 + wr0) {
#pragma unroll
            for (int nt = 0; nt < 8; nt++) {
                int cc = kb * 64 + nt * 8 + 2 * t;
                s[nt][0] = (cc     > rg ) ? -1e30f : s[nt][0] * 0.125f;
                s[nt][1] = (cc + 1 > rg ) ? -1e30f : s[nt][1] * 0.125f;
                s[nt][2] = (cc     > rg8) ? -1e30f : s[nt][2] * 0.125f;
                s[nt][3] = (cc + 1 > rg8) ? -1e30f : s[nt][3] * 0.125f;
            }
        } else {
#pragma unroll
            for (int nt = 0; nt < 8; nt++)
#pragma unroll
                for (int r = 0; r < 4; r++) s[nt][r] *= 0.125f;
        }

        float mx0 = -1e30f, mx1 = -1e30f;
#pragma unroll
        for (int nt = 0; nt < 8; nt++) {
            mx0 = fmaxf(mx0, fmaxf(s[nt][0], s[nt][1]));
            mx1 = fmaxf(mx1, fmaxf(s[nt][2], s[nt][3]));
        }
        mx0 = fmaxf(mx0, __shfl_xor_sync(0xffffffffu, mx0, 1));
        mx0 = fmaxf(mx0, __shfl_xor_sync(0xffffffffu, mx0, 2));
        mx1 = fmaxf(mx1, __shfl_xor_sync(0xffffffffu, mx1, 1));
        mx1 = fmaxf(mx1, __shfl_xor_sync(0xffffffffu, mx1, 2));

        float mn0 = fmaxf(m0, mx0), mn1 = fmaxf(m1, mx1);
        float corr0 = __expf(m0 - mn0), corr1 = __expf(m1 - mn1);
        m0 = mn0; m1 = mn1;

        float rs0 = 0.0f, rs1 = 0.0f;
        uint32_t ph[8], ph8[8];
#pragma unroll
        for (int nt = 0; nt < 8; nt++) {
            float p0 = __expf(s[nt][0] - mn0);
            float p1 = __expf(s[nt][1] - mn0);
            float p2 = __expf(s[nt][2] - mn1);
            float p3 = __expf(s[nt][3] - mn1);
            rs0 += p0 + p1;
            rs1 += p2 + p3;
            __half2 h0 = __floats2half2_rn(p0, p1);
            __half2 h1 = __floats2half2_rn(p2, p3);
            ph[nt]  = *(uint32_t*)&h0;
            ph8[nt] = *(uint32_t*)&h1;
        }
        rs0 += __shfl_xor_sync(0xffffffffu, rs0, 1);
        rs0 += __shfl_xor_sync(0xffffffffu, rs0, 2);
        rs1 += __shfl_xor_sync(0xffffffffu, rs1, 1);
        rs1 += __shfl_xor_sync(0xffffffffu, rs1, 2);
        l0 = l0 * corr0 + rs0;
        l1 = l1 * corr1 + rs1;

#pragma unroll
        for (int nt = 0; nt < 8; nt++) {
            o[nt][0] *= corr0; o[nt][1] *= corr0;
            o[nt][2] *= corr1; o[nt][3] *= corr1;
        }

        const int lsub = lane & 7;
        const int sel  = lane >> 3;
        const int vrowbase = (sel & 1) * 8 + lsub;
        const int vchsel   = sel >> 1;
#pragma unroll
        for (int kk = 0; kk < 4; kk++) {
            const int vrow = 16 * kk + vrowbase;
#pragma unroll
            for (int ntp = 0; ntp < 4; ntp++) {
                const int chunk = 2 * ntp + vchsel;
                uint32_t addr = vsb[st] + (vrow * 8 + (chunk ^ (vrow & 7))) * 16;
                uint32_t r0, r1, r2, r3;
                ldsm_x4_trans(r0, r1, r2, r3, addr);
                mma_f16(o[2 * ntp],     ph[2 * kk], ph8[2 * kk],
                        ph[2 * kk + 1], ph8[2 * kk + 1], r0, r1);
                mma_f16(o[2 * ntp + 1], ph[2 * kk], ph8[2 * kk],
                        ph[2 * kk + 1], ph8[2 * kk + 1], r2, r3);
            }
        }
    }

    float inv0 = 1.0f / l0, inv1 = 1.0f / l1;
    __half* Xr0 = X + (size_t)(qb * 128 + wr0 + g) * rowstride + headoff;
    __half* Xr8 = Xr0 + 8 * rowstride;
#pragma unroll
    for (int nt = 0; nt < 8; nt++) {
        __half2 h0 = __floats2half2_rn(o[nt][0] * inv0, o[nt][1] * inv0);
        __half2 h1 = __floats2half2_rn(o[nt][2] * inv1, o[nt][3] * inv1);
        *(uint32_t*)(Xr0 + nt * 8 + 2 * t) = *(uint32_t*)&h0;
        *(uint32_t*)(Xr8 + nt * 8 + 2 * t) = *(uint32_t*)&h1;
    }
}

// ---------------------------------------------------------------------------
// kernel_launch
// Inputs: query, key, value, mask, Wq, bq, Wk, bk, Wv, bv, Wo, bo
// ---------------------------------------------------------------------------
extern "C" void kernel_launch(void* const* d_in, const int* in_sizes, int n_in,
                              void* d_out, int out_size)
{
    const float* query = (const float*)d_in[0];
    const float* key   = (const float*)d_in[1];
    const float* value = (const float*)d_in[2];
    // d_in[3] = mask (tril causal) — handled analytically in flash_attn_mma
    const float* Wq = (const float*)d_in[4];
    const float* bq = (const float*)d_in[5];
    const float* Wk = (const float*)d_in[6];
    const float* bk = (const float*)d_in[7];
    const float* Wv = (const float*)d_in[8];
    const float* bv = (const float*)d_in[9];
    const float* Wo = (const float*)d_in[10];
    const float* bo = (const float*)d_in[11];
    float* out = (float*)d_out;

    __half *hq, *hk, *hv, *pq, *pk, *pv, *hx;
    uint32_t* wt;
    cudaGetSymbolAddress((void**)&hq, g_hq);
    cudaGetSymbolAddress((void**)&hk, g_hk);
    cudaGetSymbolAddress((void**)&hv, g_hv);
    cudaGetSymbolAddress((void**)&pq, g_pq);
    cudaGetSymbolAddress((void**)&pk, g_pk);
    cudaGetSymbolAddress((void**)&pv, g_pv);
    cudaGetSymbolAddress((void**)&hx, g_hx);
    cudaGetSymbolAddress((void**)&wt, g_wt);

    uint32_t* wtq = wt;
    uint32_t* wtk = wt + (size_t)DM * DM / 2;
    uint32_t* wtv = wt + (size_t)DM * DM;
    uint32_t* wto = wt + (size_t)DM * DM * 3 / 2;

    cudaFuncSetAttribute(tc_gemm, cudaFuncAttributeMaxDynamicSharedMemorySize, GS_TOTAL);

    // 1) convert inputs fp32 -> fp16
    CvtArgs ca;
    ca.src[0] = query; ca.dst[0] = hq;
    ca.src[1] = key;   ca.dst[1] = hk;
    ca.src[2] = value; ca.dst[2] = hv;
    cvt_f2h<<<dim3(NTOK * DM / 1024, 1, 3), 256>>>(ca, NTOK * DM);

    // 2) convert + transpose weights -> Wt[n][k] fp16
    CvtWArgs cw;
    cw.W[0] = Wq; cw.Wt[0] = wtq;
    cw.W[1] = Wk; cw.Wt[1] = wtk;
    cw.W[2] = Wv; cw.Wt[2] = wtv;
    cw.W[3] = Wo; cw.Wt[3] = wto;
    cvt_w_trans<<<dim3(DM / 32, DM / 32, 4), 256>>>(cw);

    // 3) fused Q/K/V projections (fp16 outputs)
    TCGemmArgs proj;
    proj.A[0] = hq; proj.W[0] = (const __half*)wtq; proj.bias[0] = bq; proj.C[0] = nullptr; proj.Ch[0] = pq;
    proj.A[1] = hk; proj.W[1] = (const __half*)wtk; proj.bias[1] = bk; proj.C[1] = nullptr; proj.Ch[1] = pk;
    proj.A[2] = hv; proj.W[2] = (const __half*)wtv; proj.bias[2] = bv; proj.C[2] = nullptr; proj.Ch[2] = pv;
    tc_gemm<<<dim3(DM / 128, NTOK / 128, 3), 256, GS_TOTAL>>>(proj, NTOK, DM, DM);

    // 4) attention (fp16 in, fp16 out)
    flash_attn_mma<<<dim3(SEQ / 128, BAT * NH), 256>>>(pq, pk, pv, hx);

    // 5) output projection (fp32 output)
    TCGemmArgs oproj;
    oproj.A[0] = hx; oproj.W[0] = (const __half*)wto; oproj.bias[0] = bo; oproj.C[0] = out; oproj.Ch[0] = nullptr;
    oproj.A[1] = hx; oproj.W[1] = (const __half*)wto; oproj.bias[1] = bo; oproj.C[1] = out; oproj.Ch[1] = nullptr;
    oproj.A[2] = hx; oproj.W[2] = (const __half*)wto; oproj.bias[2] = bo; oproj.C[2] = out; oproj.Ch[2] = nullptr;
    tc_gemm<<<dim3(DM / 128, NTOK / 128, 1), 256, GS_TOTAL>>>(oproj, NTOK, DM, DM);
}

// round 12
// speedup vs baseline: 6.1273x; 1.0594x over previous
#include <cuda_runtime.h>
#include <cuda_fp16.h>
#include <math.h>
#include <stdint.h>

// Problem constants (fixed by the reference)
#define SEQ   2048
#define BAT   2
#define NH    16
#define DHD   64
#define DM    1024
#define NTOK  (SEQ * BAT)   // 4096

// ---------------------------------------------------------------------------
// Arch-feature gate: tcgen05 exists only on the sm_103a ('a') target; the
// compute_103 PTX fallback pass must compile clean without it.
// ---------------------------------------------------------------------------
#ifndef __CUDA_ARCH_HAS_FEATURE__
#define __CUDA_ARCH_HAS_FEATURE__(x) 0
#endif
#if defined(__CUDA_ARCH__) && \
    (defined(__CUDA_ARCH_FEAT_SM103_ALL) || __CUDA_ARCH_HAS_FEATURE__(SM103_ALL))
#define USE_TCG 1
#else
#define USE_TCG 0
#endif

// Scratch (allocation-free rule: __device__ globals)
__device__ __half  g_hq[NTOK * DM];
__device__ __half  g_hk[NTOK * DM];
__device__ __half  g_hv[NTOK * DM];
__device__ __half  g_pq[NTOK * DM];
__device__ __half  g_pk[NTOK * DM];
__device__ __half  g_pv[NTOK * DM];
__device__ __half  g_hx[NTOK * DM];
__device__ uint32_t g_wt[4][DM * DM / 2]; // fp16 weights, transposed: Wt[n][k]

// ---------------------------------------------------------------------------
// common helpers
// ---------------------------------------------------------------------------
__device__ __forceinline__ void mma_f16(float* c, uint32_t a0, uint32_t a1,
                                        uint32_t a2, uint32_t a3,
                                        uint32_t b0, uint32_t b1) {
    asm volatile(
        "mma.sync.aligned.m16n8k16.row.col.f32.f16.f16.f32 "
        "{%0,%1,%2,%3}, {%4,%5,%6,%7}, {%8,%9}, {%0,%1,%2,%3};"
        : "+f"(c[0]), "+f"(c[1]), "+f"(c[2]), "+f"(c[3])
        : "r"(a0), "r"(a1), "r"(a2), "r"(a3), "r"(b0), "r"(b1));
}

__device__ __forceinline__ void ldsm_x4(uint32_t& r0, uint32_t& r1,
                                        uint32_t& r2, uint32_t& r3, uint32_t addr) {
    asm volatile("ldmatrix.sync.aligned.m8n8.x4.shared.b16 {%0,%1,%2,%3}, [%4];"
                 : "=r"(r0), "=r"(r1), "=r"(r2), "=r"(r3) : "r"(addr));
}

__device__ __forceinline__ void ldsm_x4_trans(uint32_t& r0, uint32_t& r1,
                                              uint32_t& r2, uint32_t& r3, uint32_t addr) {
    asm volatile("ldmatrix.sync.aligned.m8n8.x4.trans.shared.b16 {%0,%1,%2,%3}, [%4];"
                 : "=r"(r0), "=r"(r1), "=r"(r2), "=r"(r3) : "r"(addr));
}

__device__ __forceinline__ void cp16(uint32_t saddr, const void* g) {
    asm volatile("cp.async.cg.shared.global [%0], [%1], 16;" :: "r"(saddr), "l"(g));
}
#define CP_COMMIT() asm volatile("cp.async.commit_group;")
#define CP_WAIT0()  asm volatile("cp.async.wait_group 0;" ::: "memory")
#define CP_WAIT1()  asm volatile("cp.async.wait_group 1;" ::: "memory")
#define CP_WAIT2()  asm volatile("cp.async.wait_group 2;" ::: "memory")

// ---------------------------------------------------------------------------
// tcgen05 helpers (only inside USE_TCG code)
// ---------------------------------------------------------------------------
#if USE_TCG
__device__ __forceinline__ uint32_t elect_one_pred() {
    uint32_t pred;
    asm volatile("{\n\t.reg .pred p;\n\telect.sync _|p, 0xFFFFFFFF;\n\t"
                 "selp.b32 %0, 1, 0, p;\n\t}" : "=r"(pred));
    return pred;
}

__device__ __forceinline__ void tcg_mma_f16_ss(uint32_t d_tmem, uint64_t a_desc,
                                               uint64_t b_desc, uint32_t idesc,
                                               bool accum) {
    uint32_t en = accum ? 1u : 0u;
    asm volatile(
        "{\n\t"
        ".reg .pred p;\n\t"
        "setp.ne.u32 p, %4, 0;\n\t"
        "tcgen05.mma.cta_group::1.kind::f16 [%0], %1, %2, %3, {%5,%5,%5,%5}, p;\n\t"
        "}"
        :: "r"(d_tmem), "l"(a_desc), "l"(b_desc), "r"(idesc), "r"(en), "r"(0u)
        : "memory");
}

#define TCG_ALLOC(sm_addr, ncols) \
    asm volatile("tcgen05.alloc.cta_group::1.sync.aligned.shared::cta.b32 [%0], %1;" \
                 :: "r"(sm_addr), "r"((uint32_t)(ncols)) : "memory")
#define TCG_DEALLOC(tmem, ncols) \
    asm volatile("tcgen05.dealloc.cta_group::1.sync.aligned.b32 %0, %1;" \
                 :: "r"(tmem), "r"((uint32_t)(ncols)))
#define TCG_COMMIT(mbar) \
    asm volatile("tcgen05.commit.cta_group::1.mbarrier::arrive::one.shared::cluster.b64 [%0];" \
                 :: "r"(mbar) : "memory")
#define TCG_FENCE_AFTER() asm volatile("tcgen05.fence::after_thread_sync;" ::: "memory")
#define TCG_WAIT_LD()     asm volatile("tcgen05.wait::ld.sync.aligned;" ::: "memory")
#define FENCE_ASYNC()     asm volatile("fence.proxy.async.shared::cta;" ::: "memory")

#define MBAR_INIT(a, n) \
    asm volatile("mbarrier.init.shared.b64 [%0], %1;" :: "r"(a), "r"((uint32_t)(n)) : "memory")
#define MBAR_WAIT(a, par) do {                                                  \
    asm volatile("{\n\t.reg .pred P1;\n\t"                                      \
        "WL_%=:\n\t"                                                            \
        "mbarrier.try_wait.parity.acquire.cta.shared::cta.b64 P1, [%0], %1, 0x989680;\n\t" \
        "@P1 bra.uni WD_%=;\n\t"                                                \
        "bra.uni WL_%=;\n\t"                                                    \
        "WD_%=:\n\t}" :: "r"(a), "r"((uint32_t)(par)) : "memory");              \
} while (0)

__device__ __forceinline__ void ldtm_x32(uint32_t* r, uint32_t tmem_addr) {
    asm volatile(
        "tcgen05.ld.sync.aligned.32x32b.x32.b32 "
        "{%0,%1,%2,%3,%4,%5,%6,%7,%8,%9,%10,%11,%12,%13,%14,%15,"
        "%16,%17,%18,%19,%20,%21,%22,%23,%24,%25,%26,%27,%28,%29,%30,%31}, [%32];"
        : "=r"(r[0]), "=r"(r[1]), "=r"(r[2]), "=r"(r[3]),
          "=r"(r[4]), "=r"(r[5]), "=r"(r[6]), "=r"(r[7]),
          "=r"(r[8]), "=r"(r[9]), "=r"(r[10]), "=r"(r[11]),
          "=r"(r[12]), "=r"(r[13]), "=r"(r[14]), "=r"(r[15]),
          "=r"(r[16]), "=r"(r[17]), "=r"(r[18]), "=r"(r[19]),
          "=r"(r[20]), "=r"(r[21]), "=r"(r[22]), "=r"(r[23]),
          "=r"(r[24]), "=r"(r[25]), "=r"(r[26]), "=r"(r[27]),
          "=r"(r[28]), "=r"(r[29]), "=r"(r[30]), "=r"(r[31])
        : "r"(tmem_addr));
}
#endif // USE_TCG

// ---------------------------------------------------------------------------
// Convert kernels
// ---------------------------------------------------------------------------
struct CvtArgs { const float* src[3]; __half* dst[3]; };

__global__ __launch_bounds__(256)
void cvt_f2h(CvtArgs ca, int n)
{
    const float* __restrict__ s = ca.src[blockIdx.z];
    __half* __restrict__ d = ca.dst[blockIdx.z];
    int idx = (blockIdx.x * 256 + threadIdx.x) * 4;
    if (idx < n) {
        float4 v = *(const float4*)(s + idx);
        __half2 h0 = __floats2half2_rn(v.x, v.y);
        __half2 h1 = __floats2half2_rn(v.z, v.w);
        uint2 u;
        u.x = *(uint32_t*)&h0;
        u.y = *(uint32_t*)&h1;
        *(uint2*)(d + idx) = u;
    }
}

struct CvtWArgs { const float* W[4]; uint32_t* Wt[4]; };

__global__ __launch_bounds__(256)
void cvt_w_trans(CvtWArgs cw)
{
    __shared__ float T[32][33];
    const float* __restrict__ W = cw.W[blockIdx.z];
    uint32_t* __restrict__ Wt = cw.Wt[blockIdx.z];
    const int k0 = blockIdx.x * 32;
    const int n0 = blockIdx.y * 32;
    const int tid = threadIdx.x;

#pragma unroll
    for (int i = 0; i < 4; i++) {
        int kk = i * 8 + (tid >> 5);
        int nn = tid & 31;
        T[kk][nn] = W[(size_t)(k0 + kk) * DM + n0 + nn];
    }
    __syncthreads();

#pragma unroll
    for (int i = 0; i < 2; i++) {
        int p = tid + i * 256;
        int nn = p >> 4;
        int j2 = p & 15;
        __half2 h = __floats2half2_rn(T[2 * j2][nn], T[2 * j2 + 1][nn]);
        Wt[(size_t)(n0 + nn) * (DM / 2) + (k0 / 2) + j2] = *(uint32_t*)&h;
    }
}

// ---------------------------------------------------------------------------
// GEMM: C[M,N] = A[M,K] @ Wt[N,K]^T + bias   (fp16 in, f32 accum)
// tcgen05 path: 3-stage cp.async ring; stage chunk ch+2 into the buffer last
// used by MMA(ch-1) (whose mbar wait is ~free). K-chunk 64 halves, SW128.
// Fallback: R8 mma.sync 3-stage pipeline.
// ---------------------------------------------------------------------------
#define GS_AS(s) ((s) * 16384)             // A stages: 0,16K,32K
#define GS_BS(s) (49152 + (s) * 16384)     // B stages: 48K,64K,80K
#define GS_MBAR  98304
#define GS_TMEMP 98312
#define GS_BIAS  98816
#define GS_TOTAL 99840

struct TCGemmArgs {
    const __half* A[3];
    const __half* W[3];     // Wt[n][k] fp16
    const float*  bias[3];
    float*        C[3];     // fp32 out (if Ch null)
    __half*       Ch[3];    // fp16 out (if non-null)
};

__global__ __launch_bounds__(256)
void tc_gemm(TCGemmArgs ga, int M, int N, int K)
{
    extern __shared__ __align__(1024) unsigned char sm[];
    const int z = blockIdx.z;
    const __half* __restrict__ A = ga.A[z];
    const __half* __restrict__ W = ga.W[z];
    const float*  __restrict__ bias = ga.bias[z];

    const uint32_t smb = (uint32_t)__cvta_generic_to_shared(sm);
    const int tid  = threadIdx.x;
    const int lane = tid & 31;
    const int warp = tid >> 5;
    const int bm = blockIdx.y * 128;
    const int bn = blockIdx.x * 128;

#if USE_TCG
    // =================== tcgen05 path ===================
    if (tid == 0) MBAR_INIT(smb + GS_MBAR, 1);
    if (warp == 0) TCG_ALLOC(smb + GS_TMEMP, 128);
    if (tid < 128) ((float*)(sm + GS_BIAS))[tid] = bias[bn + tid];

    // staging: thread -> row rA, 4 16B chunks from cb (SW128 swizzle)
    const int rA = tid >> 1;
    const int cb = (tid & 1) * 4;
    int soff[4];
#pragma unroll
    for (int j = 0; j < 4; j++)
        soff[j] = (rA * 8 + ((cb + j) ^ (rA & 7))) * 16;

    const __half* Ag = A + (size_t)(bm + rA) * K + cb * 8;
    const __half* Wg = W + (size_t)(bn + rA) * K + cb * 8;

    // prologue: stage chunks 0,1
#pragma unroll
    for (int s = 0; s < 2; s++) {
#pragma unroll
        for (int j = 0; j < 4; j++) cp16(smb + GS_AS(s) + soff[j], Ag + s * 64 + j * 8);
#pragma unroll
        for (int j = 0; j < 4; j++) cp16(smb + GS_BS(s) + soff[j], Wg + s * 64 + j * 8);
        CP_COMMIT();
    }
    __syncthreads();   // mbar init + tmem ptr visible

    uint32_t tmem;
    asm volatile("ld.shared.b32 %0, [%1];" : "=r"(tmem) : "r"(smb + GS_TMEMP));

    const unsigned long long DESC_SW128 =
        (2ULL << 61) | (1ULL << 46) | (64ULL << 32) | (1ULL << 16);
    const uint32_t TC_IDESC = 0x08200010u;   // M=128, N=128, f32 accum, f16 a/b

    uint64_t dA[3], dB[3];
#pragma unroll
    for (int s = 0; s < 3; s++) {
        dA[s] = DESC_SW128 | ((uint64_t)((smb + GS_AS(s)) >> 4) & 0x3FFF);
        dB[s] = DESC_SW128 | ((uint64_t)((smb + GS_BS(s)) >> 4) & 0x3FFF);
    }

    const int NCH = K / 64;   // 16
    int mpar = 0;
    for (int ch = 0; ch < NCH; ch++) {
        const int b = ch % 3;
        if (ch == NCH - 1) { CP_WAIT0(); } else { CP_WAIT1(); }
        __syncthreads();   // chunk ch staged & visible to all

        if (warp == 0 && elect_one_pred()) {
            FENCE_ASYNC();
#pragma unroll
            for (int ks = 0; ks < 4; ks++)
                tcg_mma_f16_ss(tmem, dA[b] + ks * 2, dB[b] + ks * 2, TC_IDESC,
                               !(ch == 0 && ks == 0));
            TCG_COMMIT(smb + GS_MBAR);
        }

        // wait MMA(ch-1) — its buffer ((ch+2)%3) is what we restage next;
        // commit was a full iteration ago, so this wait is ~free.
        if (ch > 0) { MBAR_WAIT(smb + GS_MBAR, mpar); mpar ^= 1; }

        if (ch + 2 < NCH) {
            const int s2 = (ch + 2) % 3;
            const __half* a2 = Ag + (ch + 2) * 64;
            const __half* w2 = Wg + (ch + 2) * 64;
#pragma unroll
            for (int j = 0; j < 4; j++) cp16(smb + GS_AS(s2) + soff[j], a2 + j * 8);
#pragma unroll
            for (int j = 0; j < 4; j++) cp16(smb + GS_BS(s2) + soff[j], w2 + j * 8);
            CP_COMMIT();
        }
    }
    // drain last MMA
    MBAR_WAIT(smb + GS_MBAR, mpar);

    // epilogue: TMEM -> smem -> gmem
    TCG_FENCE_AFTER();
    __half* Ch = ga.Ch[z];
    float*  C  = ga.C[z];

    if (warp < 4) {
        const int row = warp * 32 + lane;
#pragma unroll
        for (int cs = 0; cs < 4; cs++) {
            uint32_t r[32];
            ldtm_x32(r, tmem + cs * 32);
            TCG_WAIT_LD();
            if (Ch) {
                uint32_t* epi = (uint32_t*)sm;
#pragma unroll
                for (int j = 0; j < 16; j++) {
                    float v0 = __uint_as_float(r[2 * j])     + ((float*)(sm + GS_BIAS))[cs * 32 + 2 * j];
                    float v1 = __uint_as_float(r[2 * j + 1]) + ((float*)(sm + GS_BIAS))[cs * 32 + 2 * j + 1];
                    __half2 h = __floats2half2_rn(v0, v1);
                    epi[row * 66 + cs * 16 + j] = *(uint32_t*)&h;
                }
            } else {
                float* epi = (float*)sm;
#pragma unroll
                for (int j = 0; j < 32; j++)
                    epi[row * 132 + cs * 32 + j] =
                        __uint_as_float(r[j]) + ((float*)(sm + GS_BIAS))[cs * 32 + j];
            }
        }
    }
    __syncthreads();

    if (Ch) {
        const uint32_t* epi = (const uint32_t*)sm;
#pragma unroll
        for (int it = 0; it < 16; it++) {
            int idx = it * 256 + tid;
            int r = idx >> 5, c2 = idx & 31;
            uint2 v = *(const uint2*)(epi + r * 66 + c2 * 2);
            *(uint2*)(Ch + (size_t)(bm + r) * N + bn + c2 * 4) = v;
        }
    } else {
        const float* epi = (const float*)sm;
#pragma unroll
        for (int it = 0; it < 16; it++) {
            int idx = it * 256 + tid;
            int r = idx >> 5, c4 = (idx & 31) * 4;
            float4 v = *(const float4*)(epi + r * 132 + c4);
            *(float4*)(C + (size_t)(bm + r) * N + bn + c4) = v;
        }
    }

    __syncthreads();
    if (warp == 0) TCG_DEALLOC(tmem, 128);

#else
    // =================== mma.sync fallback (R8 pipeline) ===================
    const uint32_t* Bt = (const uint32_t*)W;
    const int g = lane >> 2;
    const int t = lane & 3;
    const int wm = (warp & 1) * 64;
    const int wn = (warp >> 1) * 32;

    const int rS  = tid >> 1;
    const int cS0 = (tid & 1) * 2;
    const int swS = (rS >> 1) & 3;
    const int offA0 = (rS * 4 + (cS0 ^ swS)) * 16;
    const int offA1 = (rS * 4 + ((cS0 + 1) ^ swS)) * 16;
    const __half*   Agr = A  + (size_t)(bm + rS) * K + cS0 * 8;
    const uint32_t* Bgr = Bt + (size_t)(bn + rS) * (K / 2) + cS0 * 4;

    uint32_t saA[3], saB[3];
#pragma unroll
    for (int s = 0; s < 3; s++) {
        saA[s] = smb + s * 8192;
        saB[s] = smb + 24576 + s * 8192;
    }

    float acc[4][4][4];
#pragma unroll
    for (int i = 0; i < 4; i++)
#pragma unroll
        for (int j = 0; j < 4; j++)
#pragma unroll
            for (int r = 0; r < 4; r++) acc[i][j][r] = 0.0f;

    const int NIT = K / 32;

#pragma unroll
    for (int s = 0; s < 2; s++) {
        cp16(saA[s] + offA0, Agr + s * 32);
        cp16(saA[s] + offA1, Agr + s * 32 + 8);
        cp16(saB[s] + offA0, Bgr + s * 16);
        cp16(saB[s] + offA1, Bgr + s * 16 + 4);
        CP_COMMIT();
    }

    const int lr = lane & 15;
    const int lc = lane >> 4;
    int aoff[4][2];
#pragma unroll
    for (int mt = 0; mt < 4; mt++) {
        const int r = wm + mt * 16 + lr;
        const int sw = (r >> 1) & 3;
#pragma unroll
        for (int kk = 0; kk < 2; kk++)
            aoff[mt][kk] = (r * 4 + ((2 * kk + lc) ^ sw)) * 16;
    }

    int st = 0;
    for (int it = 0; it < NIT; it++) {
        CP_WAIT1();
        __syncthreads();

        if (it + 2 < NIT) {
            const int s2 = (st + 2) % 3;
            const int kof = (it + 2) * 32;
            cp16(saA[s2] + offA0, Agr + kof);
            cp16(saA[s2] + offA1, Agr + kof + 8);
            cp16(saB[s2] + offA0, Bgr + kof / 2);
            cp16(saB[s2] + offA1, Bgr + kof / 2 + 4);
        }
        CP_COMMIT();

        const uint32_t sa = saA[st];
        const uint32_t* Bs = (const uint32_t*)(sm + 24576 + st * 8192);
#pragma unroll
        for (int kk = 0; kk < 2; kk++) {
            uint32_t a[4][4];
#pragma unroll
            for (int mt = 0; mt < 4; mt++)
                ldsm_x4(a[mt][0], a[mt][1], a[mt][2], a[mt][3], sa + aoff[mt][kk]);
            uint32_t b0[4], b1[4];
#pragma unroll
            for (int nt = 0; nt < 4; nt++) {
                const int n = wn + nt * 8 + g;
                const int v = (n >> 1) & 3;
                b0[nt] = Bs[n * 16 + (((2 * kk)     ^ v) << 2) + t];
                b1[nt] = Bs[n * 16 + (((2 * kk + 1) ^ v) << 2) + t];
            }
#pragma unroll
            for (int mt = 0; mt < 4; mt++)
#pragma unroll
                for (int nt = 0; nt < 4; nt++)
                    mma_f16(acc[mt][nt], a[mt][0], a[mt][1], a[mt][2], a[mt][3],
                            b0[nt], b1[nt]);
        }
        st = (st + 1) % 3;
    }

    __half* Ch = ga.Ch[z];
    float*  C  = ga.C[z];
#pragma unroll
    for (int mt = 0; mt < 4; mt++) {
#pragma unroll
        for (int nt = 0; nt < 4; nt++) {
            const int row = bm + wm + mt * 16 + g;
            const int col = bn + wn + nt * 8 + t * 2;
            float b0 = bias[col], b1 = bias[col + 1];
            float v00 = acc[mt][nt][0] + b0, v01 = acc[mt][nt][1] + b1;
            float v10 = acc[mt][nt][2] + b0, v11 = acc[mt][nt][3] + b1;
            if (Ch) {
                __half2 h0 = __floats2half2_rn(v00, v01);
                __half2 h1 = __floats2half2_rn(v10, v11);
                *(uint32_t*)(Ch + (size_t)row * N + col)       = *(uint32_t*)&h0;
                *(uint32_t*)(Ch + (size_t)(row + 8) * N + col) = *(uint32_t*)&h1;
            } else {
                *(float2*)(C + (size_t)row * N + col)       = make_float2(v00, v01);
                *(float2*)(C + (size_t)(row + 8) * N + col) = make_float2(v10, v11);
            }
        }
    }
#endif
}

// ---------------------------------------------------------------------------
// Flash attention (causal), all-fp16 operands, fp32 accum. (unchanged — 105us)
// ---------------------------------------------------------------------------
#define STG 3

__global__ __launch_bounds__(256)
void flash_attn_mma(const __half* __restrict__ Q, const __half* __restrict__ K,
                    const __half* __restrict__ V, __half* __restrict__ X)
{
    __shared__ __align__(16) __half Ks[STG][64 * 64];
    __shared__ __align__(16) __half Vs[STG][64 * 64];

    const int qb = (int)(gridDim.x - 1 - blockIdx.x);
    const int bh = blockIdx.y;
    const int b  = bh >> 4;
    const int h  = bh & 15;
    const int tid  = threadIdx.x;
    const int lane = tid & 31;
    const int warp = tid >> 5;
    const int g = lane >> 2;
    const int t = lane & 3;
    const int wr0 = warp * 16;

    const int rowstride = BAT * DM;
    const int headoff = b * DM + h * DHD;

    uint32_t ksb[STG], vsb[STG];
#pragma unroll
    for (int s = 0; s < STG; s++) {
        ksb[s] = (uint32_t)__cvta_generic_to_shared(&Ks[s][0]);
        vsb[s] = (uint32_t)__cvta_generic_to_shared(&Vs[s][0]);
    }

    const int rS = tid >> 2;
    const int c0 = (tid & 3) * 2;
    const int offS0 = (rS * 8 + (c0 ^ (rS & 7))) * 16;
    const int offS1 = (rS * 8 + ((c0 + 1) ^ (rS & 7))) * 16;
    const __half* Kgr = K + (size_t)rS * rowstride + headoff + c0 * 8;
    const __half* Vgr = V + (size_t)rS * rowstride + headoff + c0 * 8;

    uint32_t qa[4][4];
    {
        const __half* Qr0 = Q + (size_t)(qb * 128 + wr0 + g) * rowstride + headoff;
        const __half* Qr8 = Qr0 + 8 * rowstride;
#pragma unroll
        for (int kk = 0; kk < 4; kk++) {
            qa[kk][0] = *(const uint32_t*)(Qr0 + 16 * kk + 2 * t);
            qa[kk][1] = *(const uint32_t*)(Qr8 + 16 * kk + 2 * t);
            qa[kk][2] = *(const uint32_t*)(Qr0 + 16 * kk + 8 + 2 * t);
            qa[kk][3] = *(const uint32_t*)(Qr8 + 16 * kk + 8 + 2 * t);
        }
    }

    float o[8][4];
#pragma unroll
    for (int nt = 0; nt < 8; nt++)
#pragma unroll
        for (int r = 0; r < 4; r++) o[nt][r] = 0.0f;
    float m0 = -1e30f, m1 = -1e30f, l0 = 0.0f, l1 = 0.0f;

    const int kbmax = 2 * qb + 1;

#pragma unroll
    for (int s = 0; s < 2; s++) {
        const size_t go = (size_t)(s * 64) * rowstride;
        cp16(ksb[s] + offS0, Kgr + go);
        cp16(ksb[s] + offS1, Kgr + go + 8);
        cp16(vsb[s] + offS0, Vgr + go);
        cp16(vsb[s] + offS1, Vgr + go + 8);
        CP_COMMIT();
    }

    for (int kb = 0; kb <= kbmax; kb++) {
        const int st = kb % STG;
        __syncthreads();

        if (kb + 2 <= kbmax) {
            const int s2 = (kb + 2) % STG;
            const size_t go = (size_t)((kb + 2) * 64) * rowstride;
            cp16(ksb[s2] + offS0, Kgr + go);
            cp16(ksb[s2] + offS1, Kgr + go + 8);
            cp16(vsb[s2] + offS0, Vgr + go);
            cp16(vsb[s2] + offS1, Vgr + go + 8);
        }
        CP_COMMIT();
        CP_WAIT2();

        const uint32_t* KsW = (const uint32_t*)&Ks[st][0];
        float s[8][4];
#pragma unroll
        for (int nt = 0; nt < 8; nt++)
#pragma unroll
            for (int r = 0; r < 4; r++) s[nt][r] = 0.0f;

#pragma unroll
        for (int kk = 0; kk < 4; kk++) {
#pragma unroll
            for (int nt = 0; nt < 8; nt++) {
                const int n = nt * 8 + g;
                uint32_t b0 = KsW[n * 32 + (((2 * kk)     ^ g) << 2) + t];
                uint32_t b1 = KsW[n * 32 + (((2 * kk + 1) ^ g) << 2) + t];
                mma_f16(s[nt], qa[kk][0], qa[kk][1], qa[kk][2], qa[kk][3], b0, b1);
            }
        }

        const int rg  = qb * 128 + wr0 + g;
        const int rg8 = rg + 8;
        if (kb * 64 + 63 > qb * 128 + wr0) {
#pragma unroll
            for (int nt = 0; nt < 8; nt++) {
                int cc = kb * 64 + nt * 8 + 2 * t;
                s[nt][0] = (cc     > rg ) ? -1e30f : s[nt][0] * 0.125f;
                s[nt][1] = (cc + 1 > rg ) ? -1e30f : s[nt][1] * 0.125f;
                s[nt][2] = (cc     > rg8) ? -1e30f : s[nt][2] * 0.125f;
                s[nt][3] = (cc + 1 > rg8) ? -1e30f : s[nt][3] * 0.125f;
            }
        } else {
#pragma unroll
            for (int nt = 0; nt < 8; nt++)
#pragma unroll
                for (int r = 0; r < 4; r++) s[nt][r] *= 0.125f;
        }

        float mx0 = -1e30f, mx1 = -1e30f;
#pragma unroll
        for (int nt = 0; nt < 8; nt++) {
            mx0 = fmaxf(mx0, fmaxf(s[nt][0], s[nt][1]));
            mx1 = fmaxf(mx1, fmaxf(s[nt][2], s[nt][3]));
        }
        mx0 = fmaxf(mx0, __shfl_xor_sync(0xffffffffu, mx0, 1));
        mx0 = fmaxf(mx0, __shfl_xor_sync(0xffffffffu, mx0, 2));
        mx1 = fmaxf(mx1, __shfl_xor_sync(0xffffffffu, mx1, 1));
        mx1 = fmaxf(mx1, __shfl_xor_sync(0xffffffffu, mx1, 2));

        float mn0 = fmaxf(m0, mx0), mn1 = fmaxf(m1, mx1);
        float corr0 = __expf(m0 - mn0), corr1 = __expf(m1 - mn1);
        m0 = mn0; m1 = mn1;

        float rs0 = 0.0f, rs1 = 0.0f;
        uint32_t ph[8], ph8[8];
#pragma unroll
        for (int nt = 0; nt < 8; nt++) {
            float p0 = __expf(s[nt][0] - mn0);
            float p1 = __expf(s[nt][1] - mn0);
            float p2 = __expf(s[nt][2] - mn1);
            float p3 = __expf(s[nt][3] - mn1);
            rs0 += p0 + p1;
            rs1 += p2 + p3;
            __half2 h0 = __floats2half2_rn(p0, p1);
            __half2 h1 = __floats2half2_rn(p2, p3);
            ph[nt]  = *(uint32_t*)&h0;
            ph8[nt] = *(uint32_t*)&h1;
        }
        rs0 += __shfl_xor_sync(0xffffffffu, rs0, 1);
        rs0 += __shfl_xor_sync(0xffffffffu, rs0, 2);
        rs1 += __shfl_xor_sync(0xffffffffu, rs1, 1);
        rs1 += __shfl_xor_sync(0xffffffffu, rs1, 2);
        l0 = l0 * corr0 + rs0;
        l1 = l1 * corr1 + rs1;

#pragma unroll
        for (int nt = 0; nt < 8; nt++) {
            o[nt][0] *= corr0; o[nt][1] *= corr0;
            o[nt][2] *= corr1; o[nt][3] *= corr1;
        }

        const int lsub = lane & 7;
        const int sel  = lane >> 3;
        const int vrowbase = (sel & 1) * 8 + lsub;
        const int vchsel   = sel >> 1;
#pragma unroll
        for (int kk = 0; kk < 4; kk++) {
            const int vrow = 16 * kk + vrowbase;
#pragma unroll
            for (int ntp = 0; ntp < 4; ntp++) {
                const int chunk = 2 * ntp + vchsel;
                uint32_t addr = vsb[st] + (vrow * 8 + (chunk ^ (vrow & 7))) * 16;
                uint32_t r0, r1, r2, r3;
                ldsm_x4_trans(r0, r1, r2, r3, addr);
                mma_f16(o[2 * ntp],     ph[2 * kk], ph8[2 * kk],
                        ph[2 * kk + 1], ph8[2 * kk + 1], r0, r1);
                mma_f16(o[2 * ntp + 1], ph[2 * kk], ph8[2 * kk],
                        ph[2 * kk + 1], ph8[2 * kk + 1], r2, r3);
            }
        }
    }

    float inv0 = 1.0f / l0, inv1 = 1.0f / l1;
    __half* Xr0 = X + (size_t)(qb * 128 + wr0 + g) * rowstride + headoff;
    __half* Xr8 = Xr0 + 8 * rowstride;
#pragma unroll
    for (int nt = 0; nt < 8; nt++) {
        __half2 h0 = __floats2half2_rn(o[nt][0] * inv0, o[nt][1] * inv0);
        __half2 h1 = __floats2half2_rn(o[nt][2] * inv1, o[nt][3] * inv1);
        *(uint32_t*)(Xr0 + nt * 8 + 2 * t) = *(uint32_t*)&h0;
        *(uint32_t*)(Xr8 + nt * 8 + 2 * t) = *(uint32_t*)&h1;
    }
}

// ---------------------------------------------------------------------------
// kernel_launch
// Inputs: query, key, value, mask, Wq, bq, Wk, bk, Wv, bv, Wo, bo
// ---------------------------------------------------------------------------
extern "C" void kernel_launch(void* const* d_in, const int* in_sizes, int n_in,
                              void* d_out, int out_size)
{
    const float* query = (const float*)d_in[0];
    const float* key   = (const float*)d_in[1];
    const float* value = (const float*)d_in[2];
    // d_in[3] = mask (tril causal) — handled analytically in flash_attn_mma
    const float* Wq = (const float*)d_in[4];
    const float* bq = (const float*)d_in[5];
    const float* Wk = (const float*)d_in[6];
    const float* bk = (const float*)d_in[7];
    const float* Wv = (const float*)d_in[8];
    const float* bv = (const float*)d_in[9];
    const float* Wo = (const float*)d_in[10];
    const float* bo = (const float*)d_in[11];
    float* out = (float*)d_out;

    __half *hq, *hk, *hv, *pq, *pk, *pv, *hx;
    uint32_t* wt;
    cudaGetSymbolAddress((void**)&hq, g_hq);
    cudaGetSymbolAddress((void**)&hk, g_hk);
    cudaGetSymbolAddress((void**)&hv, g_hv);
    cudaGetSymbolAddress((void**)&pq, g_pq);
    cudaGetSymbolAddress((void**)&pk, g_pk);
    cudaGetSymbolAddress((void**)&pv, g_pv);
    cudaGetSymbolAddress((void**)&hx, g_hx);
    cudaGetSymbolAddress((void**)&wt, g_wt);

    uint32_t* wtq = wt;
    uint32_t* wtk = wt + (size_t)DM * DM / 2;
    uint32_t* wtv = wt + (size_t)DM * DM;
    uint32_t* wto = wt + (size_t)DM * DM * 3 / 2;

    cudaFuncSetAttribute(tc_gemm, cudaFuncAttributeMaxDynamicSharedMemorySize, GS_TOTAL);

    // 1) convert inputs fp32 -> fp16
    CvtArgs ca;
    ca.src[0] = query; ca.dst[0] = hq;
    ca.src[1] = key;   ca.dst[1] = hk;
    ca.src[2] = value; ca.dst[2] = hv;
    cvt_f2h<<<dim3(NTOK * DM / 1024, 1, 3), 256>>>(ca, NTOK * DM);

    // 2) convert + transpose weights -> Wt[n][k] fp16
    CvtWArgs cw;
    cw.W[0] = Wq; cw.Wt[0] = wtq;
    cw.W[1] = Wk; cw.Wt[1] = wtk;
    cw.W[2] = Wv; cw.Wt[2] = wtv;
    cw.W[3] = Wo; cw.Wt[3] = wto;
    cvt_w_trans<<<dim3(DM / 32, DM / 32, 4), 256>>>(cw);

    // 3) fused Q/K/V projections (fp16 outputs)
    TCGemmArgs proj;
    proj.A[0] = hq; proj.W[0] = (const __half*)wtq; proj.bias[0] = bq; proj.C[0] = nullptr; proj.Ch[0] = pq;
    proj.A[1] = hk; proj.W[1] = (const __half*)wtk; proj.bias[1] = bk; proj.C[1] = nullptr; proj.Ch[1] = pk;
    proj.A[2] = hv; proj.W[2] = (const __half*)wtv; proj.bias[2] = bv; proj.C[2] = nullptr; proj.Ch[2] = pv;
    tc_gemm<<<dim3(DM / 128, NTOK / 128, 3), 256, GS_TOTAL>>>(proj, NTOK, DM, DM);

    // 4) attention (fp16 in, fp16 out)
    flash_attn_mma<<<dim3(SEQ / 128, BAT * NH), 256>>>(pq, pk, pv, hx);

    // 5) output projection (fp32 output)
    TCGemmArgs oproj;
    oproj.A[0] = hx; oproj.W[0] = (const __half*)wto; oproj.bias[0] = bo; oproj.C[0] = out; oproj.Ch[0] = nullptr;
    oproj.A[1] = hx; oproj.W[1] = (const __half*)wto; oproj.bias[1] = bo; oproj.C[1] = out; oproj.Ch[1] = nullptr;
    oproj.A[2] = hx; oproj.W[2] = (const __half*)wto; oproj.bias[2] = bo; oproj.C[2] = out; oproj.Ch[2] = nullptr;
    tc_gemm<<<dim3(DM / 128, NTOK / 128, 1), 256, GS_TOTAL>>>(oproj, NTOK, DM, DM);
}

// round 13
// speedup vs baseline: 6.1900x; 1.0102x over previous
#include <cuda_runtime.h>
#include <cuda_fp16.h>
#include <math.h>
#include <stdint.h>

// Problem constants (fixed by the reference)
#define SEQ   2048
#define BAT   2
#define NH    16
#define DHD   64
#define DM    1024
#define NTOK  (SEQ * BAT)   // 4096

// ---------------------------------------------------------------------------
// Arch-feature gate, broadened: CUDA 12.9+ defines __CUDA_ARCH_SPECIFIC__ /
// __CUDA_ARCH_FAMILY_SPECIFIC__ for sm_103a / sm_103f targets; older spellings
// kept too. A plain compute_103 pass defines none of these -> clean fallback.
// ---------------------------------------------------------------------------
#ifndef __CUDA_ARCH_HAS_FEATURE__
#define __CUDA_ARCH_HAS_FEATURE__(x) 0
#endif
#if defined(__CUDA_ARCH__) && (__CUDA_ARCH__ >= 1000) && \
    (defined(__CUDA_ARCH_FEAT_SM103_ALL) || defined(__CUDA_ARCH_SPECIFIC__) || \
     defined(__CUDA_ARCH_FAMILY_SPECIFIC__) || __CUDA_ARCH_HAS_FEATURE__(SM103_ALL))
#define USE_TCG 1
#else
#define USE_TCG 0
#endif

// Scratch (allocation-free rule: __device__ globals)
__device__ __half  g_hq[NTOK * DM];
__device__ __half  g_hk[NTOK * DM];
__device__ __half  g_hv[NTOK * DM];
__device__ __half  g_pq[NTOK * DM];
__device__ __half  g_pk[NTOK * DM];
__device__ __half  g_pv[NTOK * DM];
__device__ __half  g_hx[NTOK * DM];
__device__ uint32_t g_wt[4][DM * DM / 2]; // fp16 weights, transposed: Wt[n][k]

// ---------------------------------------------------------------------------
// common helpers
// ---------------------------------------------------------------------------
__device__ __forceinline__ void mma_f16(float* c, uint32_t a0, uint32_t a1,
                                        uint32_t a2, uint32_t a3,
                                        uint32_t b0, uint32_t b1) {
    asm volatile(
        "mma.sync.aligned.m16n8k16.row.col.f32.f16.f16.f32 "
        "{%0,%1,%2,%3}, {%4,%5,%6,%7}, {%8,%9}, {%0,%1,%2,%3};"
        : "+f"(c[0]), "+f"(c[1]), "+f"(c[2]), "+f"(c[3])
        : "r"(a0), "r"(a1), "r"(a2), "r"(a3), "r"(b0), "r"(b1));
}

__device__ __forceinline__ void ldsm_x4(uint32_t& r0, uint32_t& r1,
                                        uint32_t& r2, uint32_t& r3, uint32_t addr) {
    asm volatile("ldmatrix.sync.aligned.m8n8.x4.shared.b16 {%0,%1,%2,%3}, [%4];"
                 : "=r"(r0), "=r"(r1), "=r"(r2), "=r"(r3) : "r"(addr));
}

__device__ __forceinline__ void ldsm_x4_trans(uint32_t& r0, uint32_t& r1,
                                              uint32_t& r2, uint32_t& r3, uint32_t addr) {
    asm volatile("ldmatrix.sync.aligned.m8n8.x4.trans.shared.b16 {%0,%1,%2,%3}, [%4];"
                 : "=r"(r0), "=r"(r1), "=r"(r2), "=r"(r3) : "r"(addr));
}

__device__ __forceinline__ void cp16(uint32_t saddr, const void* g) {
    asm volatile("cp.async.cg.shared.global [%0], [%1], 16;" :: "r"(saddr), "l"(g));
}
#define CP_COMMIT() asm volatile("cp.async.commit_group;")
#define CP_WAIT0()  asm volatile("cp.async.wait_group 0;" ::: "memory")
#define CP_WAIT1()  asm volatile("cp.async.wait_group 1;" ::: "memory")
#define CP_WAIT2()  asm volatile("cp.async.wait_group 2;" ::: "memory")

// ---------------------------------------------------------------------------
// tcgen05 helpers (only inside USE_TCG code)
// ---------------------------------------------------------------------------
#if USE_TCG
__device__ __forceinline__ uint32_t elect_one_pred() {
    uint32_t pred;
    asm volatile("{\n\t.reg .pred p;\n\telect.sync _|p, 0xFFFFFFFF;\n\t"
                 "selp.b32 %0, 1, 0, p;\n\t}" : "=r"(pred));
    return pred;
}

__device__ __forceinline__ void tcg_mma_f16_ss(uint32_t d_tmem, uint64_t a_desc,
                                               uint64_t b_desc, uint32_t idesc,
                                               bool accum) {
    uint32_t en = accum ? 1u : 0u;
    asm volatile(
        "{\n\t"
        ".reg .pred p;\n\t"
        "setp.ne.u32 p, %4, 0;\n\t"
        "tcgen05.mma.cta_group::1.kind::f16 [%0], %1, %2, %3, {%5,%5,%5,%5}, p;\n\t"
        "}"
        :: "r"(d_tmem), "l"(a_desc), "l"(b_desc), "r"(idesc), "r"(en), "r"(0u)
        : "memory");
}

#define TCG_ALLOC(sm_addr, ncols) \
    asm volatile("tcgen05.alloc.cta_group::1.sync.aligned.shared::cta.b32 [%0], %1;" \
                 :: "r"(sm_addr), "r"((uint32_t)(ncols)) : "memory")
#define TCG_DEALLOC(tmem, ncols) \
    asm volatile("tcgen05.dealloc.cta_group::1.sync.aligned.b32 %0, %1;" \
                 :: "r"(tmem), "r"((uint32_t)(ncols)))
#define TCG_COMMIT(mbar) \
    asm volatile("tcgen05.commit.cta_group::1.mbarrier::arrive::one.shared::cluster.b64 [%0];" \
                 :: "r"(mbar) : "memory")
#define TCG_FENCE_AFTER() asm volatile("tcgen05.fence::after_thread_sync;" ::: "memory")
#define TCG_WAIT_LD()     asm volatile("tcgen05.wait::ld.sync.aligned;" ::: "memory")
#define FENCE_ASYNC()     asm volatile("fence.proxy.async.shared::cta;" ::: "memory")

#define MBAR_INIT(a, n) \
    asm volatile("mbarrier.init.shared.b64 [%0], %1;" :: "r"(a), "r"((uint32_t)(n)) : "memory")
#define MBAR_WAIT(a, par) do {                                                  \
    asm volatile("{\n\t.reg .pred P1;\n\t"                                      \
        "WL_%=:\n\t"                                                            \
        "mbarrier.try_wait.parity.acquire.cta.shared::cta.b64 P1, [%0], %1, 0x989680;\n\t" \
        "@P1 bra.uni WD_%=;\n\t"                                                \
        "bra.uni WL_%=;\n\t"                                                    \
        "WD_%=:\n\t}" :: "r"(a), "r"((uint32_t)(par)) : "memory");              \
} while (0)

__device__ __forceinline__ void ldtm_x32(uint32_t* r, uint32_t tmem_addr) {
    asm volatile(
        "tcgen05.ld.sync.aligned.32x32b.x32.b32 "
        "{%0,%1,%2,%3,%4,%5,%6,%7,%8,%9,%10,%11,%12,%13,%14,%15,"
        "%16,%17,%18,%19,%20,%21,%22,%23,%24,%25,%26,%27,%28,%29,%30,%31}, [%32];"
        : "=r"(r[0]), "=r"(r[1]), "=r"(r[2]), "=r"(r[3]),
          "=r"(r[4]), "=r"(r[5]), "=r"(r[6]), "=r"(r[7]),
          "=r"(r[8]), "=r"(r[9]), "=r"(r[10]), "=r"(r[11]),
          "=r"(r[12]), "=r"(r[13]), "=r"(r[14]), "=r"(r[15]),
          "=r"(r[16]), "=r"(r[17]), "=r"(r[18]), "=r"(r[19]),
          "=r"(r[20]), "=r"(r[21]), "=r"(r[22]), "=r"(r[23]),
          "=r"(r[24]), "=r"(r[25]), "=r"(r[26]), "=r"(r[27]),
          "=r"(r[28]), "=r"(r[29]), "=r"(r[30]), "=r"(r[31])
        : "r"(tmem_addr));
}
#endif // USE_TCG

// ---------------------------------------------------------------------------
// Convert kernels
// ---------------------------------------------------------------------------
struct CvtArgs { const float* src[3]; __half* dst[3]; };

__global__ __launch_bounds__(256)
void cvt_f2h(CvtArgs ca, int n)
{
    const float* __restrict__ s = ca.src[blockIdx.z];
    __half* __restrict__ d = ca.dst[blockIdx.z];
    int idx = (blockIdx.x * 256 + threadIdx.x) * 4;
    if (idx < n) {
        float4 v = *(const float4*)(s + idx);
        __half2 h0 = __floats2half2_rn(v.x, v.y);
        __half2 h1 = __floats2half2_rn(v.z, v.w);
        uint2 u;
        u.x = *(uint32_t*)&h0;
        u.y = *(uint32_t*)&h1;
        *(uint2*)(d + idx) = u;
    }
}

struct CvtWArgs { const float* W[4]; uint32_t* Wt[4]; };

__global__ __launch_bounds__(256)
void cvt_w_trans(CvtWArgs cw)
{
    __shared__ float T[32][33];
    const float* __restrict__ W = cw.W[blockIdx.z];
    uint32_t* __restrict__ Wt = cw.Wt[blockIdx.z];
    const int k0 = blockIdx.x * 32;
    const int n0 = blockIdx.y * 32;
    const int tid = threadIdx.x;

#pragma unroll
    for (int i = 0; i < 4; i++) {
        int kk = i * 8 + (tid >> 5);
        int nn = tid & 31;
        T[kk][nn] = W[(size_t)(k0 + kk) * DM + n0 + nn];
    }
    __syncthreads();

#pragma unroll
    for (int i = 0; i < 2; i++) {
        int p = tid + i * 256;
        int nn = p >> 4;
        int j2 = p & 15;
        __half2 h = __floats2half2_rn(T[2 * j2][nn], T[2 * j2 + 1][nn]);
        Wt[(size_t)(n0 + nn) * (DM / 2) + (k0 / 2) + j2] = *(uint32_t*)&h;
    }
}

// ---------------------------------------------------------------------------
// GEMM: C[M,N] = A[M,K] @ Wt[N,K]^T + bias   (fp16 in, f32 accum)
// tcgen05 path: 3-stage cp.async ring, TMEM accumulator.
// Fallback: R8 mma.sync 3-stage pipeline.
// ---------------------------------------------------------------------------
#define GS_AS(s) ((s) * 16384)             // A stages: 0,16K,32K
#define GS_BS(s) (49152 + (s) * 16384)     // B stages: 48K,64K,80K
#define GS_MBAR  98304
#define GS_TMEMP 98312
#define GS_BIAS  98816
#define GS_TOTAL 99840

struct TCGemmArgs {
    const __half* A[3];
    const __half* W[3];     // Wt[n][k] fp16
    const float*  bias[3];
    float*        C[3];     // fp32 out (if Ch null)
    __half*       Ch[3];    // fp16 out (if non-null)
};

__global__ __launch_bounds__(256)
void tc_gemm(TCGemmArgs ga, int M, int N, int K)
{
    extern __shared__ __align__(1024) unsigned char sm[];
    const int z = blockIdx.z;
    const __half* __restrict__ A = ga.A[z];
    const __half* __restrict__ W = ga.W[z];
    const float*  __restrict__ bias = ga.bias[z];

    const uint32_t smb = (uint32_t)__cvta_generic_to_shared(sm);
    const int tid  = threadIdx.x;
    const int lane = tid & 31;
    const int warp = tid >> 5;
    const int bm = blockIdx.y * 128;
    const int bn = blockIdx.x * 128;

#if USE_TCG
    // =================== tcgen05 path ===================
    if (tid == 0) MBAR_INIT(smb + GS_MBAR, 1);
    if (warp == 0) TCG_ALLOC(smb + GS_TMEMP, 128);
    if (tid < 128) ((float*)(sm + GS_BIAS))[tid] = bias[bn + tid];

    const int rA = tid >> 1;
    const int cb = (tid & 1) * 4;
    int soff[4];
#pragma unroll
    for (int j = 0; j < 4; j++)
        soff[j] = (rA * 8 + ((cb + j) ^ (rA & 7))) * 16;

    const __half* Ag = A + (size_t)(bm + rA) * K + cb * 8;
    const __half* Wg = W + (size_t)(bn + rA) * K + cb * 8;

#pragma unroll
    for (int s = 0; s < 2; s++) {
#pragma unroll
        for (int j = 0; j < 4; j++) cp16(smb + GS_AS(s) + soff[j], Ag + s * 64 + j * 8);
#pragma unroll
        for (int j = 0; j < 4; j++) cp16(smb + GS_BS(s) + soff[j], Wg + s * 64 + j * 8);
        CP_COMMIT();
    }
    __syncthreads();

    uint32_t tmem;
    asm volatile("ld.shared.b32 %0, [%1];" : "=r"(tmem) : "r"(smb + GS_TMEMP));

    const unsigned long long DESC_SW128 =
        (2ULL << 61) | (1ULL << 46) | (64ULL << 32) | (1ULL << 16);
    const uint32_t TC_IDESC = 0x08200010u;   // M=128, N=128, f32 accum, f16 a/b

    uint64_t dA[3], dB[3];
#pragma unroll
    for (int s = 0; s < 3; s++) {
        dA[s] = DESC_SW128 | ((uint64_t)((smb + GS_AS(s)) >> 4) & 0x3FFF);
        dB[s] = DESC_SW128 | ((uint64_t)((smb + GS_BS(s)) >> 4) & 0x3FFF);
    }

    const int NCH = K / 64;   // 16
    int mpar = 0;
    for (int ch = 0; ch < NCH; ch++) {
        const int b = ch % 3;
        if (ch == NCH - 1) { CP_WAIT0(); } else { CP_WAIT1(); }
        __syncthreads();

        if (warp == 0 && elect_one_pred()) {
            FENCE_ASYNC();
#pragma unroll
            for (int ks = 0; ks < 4; ks++)
                tcg_mma_f16_ss(tmem, dA[b] + ks * 2, dB[b] + ks * 2, TC_IDESC,
                               !(ch == 0 && ks == 0));
            TCG_COMMIT(smb + GS_MBAR);
        }

        if (ch > 0) { MBAR_WAIT(smb + GS_MBAR, mpar); mpar ^= 1; }

        if (ch + 2 < NCH) {
            const int s2 = (ch + 2) % 3;
            const __half* a2 = Ag + (ch + 2) * 64;
            const __half* w2 = Wg + (ch + 2) * 64;
#pragma unroll
            for (int j = 0; j < 4; j++) cp16(smb + GS_AS(s2) + soff[j], a2 + j * 8);
#pragma unroll
            for (int j = 0; j < 4; j++) cp16(smb + GS_BS(s2) + soff[j], w2 + j * 8);
            CP_COMMIT();
        }
    }
    MBAR_WAIT(smb + GS_MBAR, mpar);

    TCG_FENCE_AFTER();
    __half* Ch = ga.Ch[z];
    float*  C  = ga.C[z];

    if (warp < 4) {
        const int row = warp * 32 + lane;
#pragma unroll
        for (int cs = 0; cs < 4; cs++) {
            uint32_t r[32];
            ldtm_x32(r, tmem + cs * 32);
            TCG_WAIT_LD();
            if (Ch) {
                uint32_t* epi = (uint32_t*)sm;
#pragma unroll
                for (int j = 0; j < 16; j++) {
                    float v0 = __uint_as_float(r[2 * j])     + ((float*)(sm + GS_BIAS))[cs * 32 + 2 * j];
                    float v1 = __uint_as_float(r[2 * j + 1]) + ((float*)(sm + GS_BIAS))[cs * 32 + 2 * j + 1];
                    __half2 h = __floats2half2_rn(v0, v1);
                    epi[row * 66 + cs * 16 + j] = *(uint32_t*)&h;
                }
            } else {
                float* epi = (float*)sm;
#pragma unroll
                for (int j = 0; j < 32; j++)
                    epi[row * 132 + cs * 32 + j] =
                        __uint_as_float(r[j]) + ((float*)(sm + GS_BIAS))[cs * 32 + j];
            }
        }
    }
    __syncthreads();

    if (Ch) {
        const uint32_t* epi = (const uint32_t*)sm;
#pragma unroll
        for (int it = 0; it < 16; it++) {
            int idx = it * 256 + tid;
            int r = idx >> 5, c2 = idx & 31;
            uint2 v = *(const uint2*)(epi + r * 66 + c2 * 2);
            *(uint2*)(Ch + (size_t)(bm + r) * N + bn + c2 * 4) = v;
        }
    } else {
        const float* epi = (const float*)sm;
#pragma unroll
        for (int it = 0; it < 16; it++) {
            int idx = it * 256 + tid;
            int r = idx >> 5, c4 = (idx & 31) * 4;
            float4 v = *(const float4*)(epi + r * 132 + c4);
            *(float4*)(C + (size_t)(bm + r) * N + bn + c4) = v;
        }
    }

    __syncthreads();
    if (warp == 0) TCG_DEALLOC(tmem, 128);

#else
    // =================== mma.sync fallback (R8 pipeline) ===================
    const uint32_t* Bt = (const uint32_t*)W;
    const int g = lane >> 2;
    const int t = lane & 3;
    const int wm = (warp & 1) * 64;
    const int wn = (warp >> 1) * 32;

    const int rS  = tid >> 1;
    const int cS0 = (tid & 1) * 2;
    const int swS = (rS >> 1) & 3;
    const int offA0 = (rS * 4 + (cS0 ^ swS)) * 16;
    const int offA1 = (rS * 4 + ((cS0 + 1) ^ swS)) * 16;
    const __half*   Agr = A  + (size_t)(bm + rS) * K + cS0 * 8;
    const uint32_t* Bgr = Bt + (size_t)(bn + rS) * (K / 2) + cS0 * 4;

    uint32_t saA[3], saB[3];
#pragma unroll
    for (int s = 0; s < 3; s++) {
        saA[s] = smb + s * 8192;
        saB[s] = smb + 24576 + s * 8192;
    }

    float acc[4][4][4];
#pragma unroll
    for (int i = 0; i < 4; i++)
#pragma unroll
        for (int j = 0; j < 4; j++)
#pragma unroll
            for (int r = 0; r < 4; r++) acc[i][j][r] = 0.0f;

    const int NIT = K / 32;

#pragma unroll
    for (int s = 0; s < 2; s++) {
        cp16(saA[s] + offA0, Agr + s * 32);
        cp16(saA[s] + offA1, Agr + s * 32 + 8);
        cp16(saB[s] + offA0, Bgr + s * 16);
        cp16(saB[s] + offA1, Bgr + s * 16 + 4);
        CP_COMMIT();
    }

    const int lr = lane & 15;
    const int lc = lane >> 4;
    int aoff[4][2];
#pragma unroll
    for (int mt = 0; mt < 4; mt++) {
        const int r = wm + mt * 16 + lr;
        const int sw = (r >> 1) & 3;
#pragma unroll
        for (int kk = 0; kk < 2; kk++)
            aoff[mt][kk] = (r * 4 + ((2 * kk + lc) ^ sw)) * 16;
    }

    int st = 0;
    for (int it = 0; it < NIT; it++) {
        CP_WAIT1();
        __syncthreads();

        if (it + 2 < NIT) {
            const int s2 = (st + 2) % 3;
            const int kof = (it + 2) * 32;
            cp16(saA[s2] + offA0, Agr + kof);
            cp16(saA[s2] + offA1, Agr + kof + 8);
            cp16(saB[s2] + offA0, Bgr + kof / 2);
            cp16(saB[s2] + offA1, Bgr + kof / 2 + 4);
        }
        CP_COMMIT();

        const uint32_t sa = saA[st];
        const uint32_t* Bs = (const uint32_t*)(sm + 24576 + st * 8192);
#pragma unroll
        for (int kk = 0; kk < 2; kk++) {
            uint32_t a[4][4];
#pragma unroll
            for (int mt = 0; mt < 4; mt++)
                ldsm_x4(a[mt][0], a[mt][1], a[mt][2], a[mt][3], sa + aoff[mt][kk]);
            uint32_t b0[4], b1[4];
#pragma unroll
            for (int nt = 0; nt < 4; nt++) {
                const int n = wn + nt * 8 + g;
                const int v = (n >> 1) & 3;
                b0[nt] = Bs[n * 16 + (((2 * kk)     ^ v) << 2) + t];
                b1[nt] = Bs[n * 16 + (((2 * kk + 1) ^ v) << 2) + t];
            }
#pragma unroll
            for (int mt = 0; mt < 4; mt++)
#pragma unroll
                for (int nt = 0; nt < 4; nt++)
                    mma_f16(acc[mt][nt], a[mt][0], a[mt][1], a[mt][2], a[mt][3],
                            b0[nt], b1[nt]);
        }
        st = (st + 1) % 3;
    }

    __half* Ch = ga.Ch[z];
    float*  C  = ga.C[z];
#pragma unroll
    for (int mt = 0; mt < 4; mt++) {
#pragma unroll
        for (int nt = 0; nt < 4; nt++) {
            const int row = bm + wm + mt * 16 + g;
            const int col = bn + wn + nt * 8 + t * 2;
            float b0 = bias[col], b1 = bias[col + 1];
            float v00 = acc[mt][nt][0] + b0, v01 = acc[mt][nt][1] + b1;
            float v10 = acc[mt][nt][2] + b0, v11 = acc[mt][nt][3] + b1;
            if (Ch) {
                __half2 h0 = __floats2half2_rn(v00, v01);
                __half2 h1 = __floats2half2_rn(v10, v11);
                *(uint32_t*)(Ch + (size_t)row * N + col)       = *(uint32_t*)&h0;
                *(uint32_t*)(Ch + (size_t)(row + 8) * N + col) = *(uint32_t*)&h1;
            } else {
                *(float2*)(C + (size_t)row * N + col)       = make_float2(v00, v01);
                *(float2*)(C + (size_t)(row + 8) * N + col) = make_float2(v10, v11);
            }
        }
    }
#endif
}

// ---------------------------------------------------------------------------
// Flash attention (causal), all-fp16, fp32 accum.
// Change this round: QK^T B-frags via ldsm.x4 (16 LDSM replace 64 LDS.32 per
// warp-tile; bit-exact same fragments through the same chunk-XOR swizzle).
// ---------------------------------------------------------------------------
#define STG 3

__global__ __launch_bounds__(256)
void flash_attn_mma(const __half* __restrict__ Q, const __half* __restrict__ K,
                    const __half* __restrict__ V, __half* __restrict__ X)
{
    __shared__ __align__(16) __half Ks[STG][64 * 64];
    __shared__ __align__(16) __half Vs[STG][64 * 64];

    const int qb = (int)(gridDim.x - 1 - blockIdx.x);
    const int bh = blockIdx.y;
    const int b  = bh >> 4;
    const int h  = bh & 15;
    const int tid  = threadIdx.x;
    const int lane = tid & 31;
    const int warp = tid >> 5;
    const int g = lane >> 2;
    const int t = lane & 3;
    const int wr0 = warp * 16;

    const int rowstride = BAT * DM;
    const int headoff = b * DM + h * DHD;

    uint32_t ksb[STG], vsb[STG];
#pragma unroll
    for (int s = 0; s < STG; s++) {
        ksb[s] = (uint32_t)__cvta_generic_to_shared(&Ks[s][0]);
        vsb[s] = (uint32_t)__cvta_generic_to_shared(&Vs[s][0]);
    }

    const int rS = tid >> 2;
    const int c0 = (tid & 3) * 2;
    const int offS0 = (rS * 8 + (c0 ^ (rS & 7))) * 16;
    const int offS1 = (rS * 8 + ((c0 + 1) ^ (rS & 7))) * 16;
    const __half* Kgr = K + (size_t)rS * rowstride + headoff + c0 * 8;
    const __half* Vgr = V + (size_t)rS * rowstride + headoff + c0 * 8;

    uint32_t qa[4][4];
    {
        const __half* Qr0 = Q + (size_t)(qb * 128 + wr0 + g) * rowstride + headoff;
        const __half* Qr8 = Qr0 + 8 * rowstride;
#pragma unroll
        for (int kk = 0; kk < 4; kk++) {
            qa[kk][0] = *(const uint32_t*)(Qr0 + 16 * kk + 2 * t);
            qa[kk][1] = *(const uint32_t*)(Qr8 + 16 * kk + 2 * t);
            qa[kk][2] = *(const uint32_t*)(Qr0 + 16 * kk + 8 + 2 * t);
            qa[kk][3] = *(const uint32_t*)(Qr8 + 16 * kk + 8 + 2 * t);
        }
    }

    float o[8][4];
#pragma unroll
    for (int nt = 0; nt < 8; nt++)
#pragma unroll
        for (int r = 0; r < 4; r++) o[nt][r] = 0.0f;
    float m0 = -1e30f, m1 = -1e30f, l0 = 0.0f, l1 = 0.0f;

    const int kbmax = 2 * qb + 1;

#pragma unroll
    for (int s = 0; s < 2; s++) {
        const size_t go = (size_t)(s * 64) * rowstride;
        cp16(ksb[s] + offS0, Kgr + go);
        cp16(ksb[s] + offS1, Kgr + go + 8);
        cp16(vsb[s] + offS0, Vgr + go);
        cp16(vsb[s] + offS1, Vgr + go + 8);
        CP_COMMIT();
    }

    // per-lane ldsm geometry for QK (constant over tiles)
    const int lsub8 = lane & 7;
    const int cbit  = (lane >> 3) & 1;       // chunk parity within k16
    const int rbit  = (lane >> 4) & 1;       // +8 rows (second n-tile of pair)
    const int row0  = rbit * 8 + lsub8;      // row within 16-row pair block

    for (int kb = 0; kb <= kbmax; kb++) {
        const int st = kb % STG;
        __syncthreads();

        if (kb + 2 <= kbmax) {
            const int s2 = (kb + 2) % STG;
            const size_t go = (size_t)((kb + 2) * 64) * rowstride;
            cp16(ksb[s2] + offS0, Kgr + go);
            cp16(ksb[s2] + offS1, Kgr + go + 8);
            cp16(vsb[s2] + offS0, Vgr + go);
            cp16(vsb[s2] + offS1, Vgr + go + 8);
        }
        CP_COMMIT();
        CP_WAIT2();

        // ---- S = Q @ K^T (B-frags via ldsm.x4) ----
        float s[8][4];
#pragma unroll
        for (int nt = 0; nt < 8; nt++)
#pragma unroll
            for (int r = 0; r < 4; r++) s[nt][r] = 0.0f;

#pragma unroll
        for (int kk = 0; kk < 4; kk++) {
#pragma unroll
            for (int np = 0; np < 4; np++) {
                const int row = np * 16 + row0;
                const int ch  = 2 * kk + cbit;
                uint32_t addr = ksb[st] + ((row << 3) + (ch ^ (row & 7))) * 16;
                uint32_t b0, b1, b2, b3;
                ldsm_x4(b0, b1, b2, b3, addr);
                mma_f16(s[2 * np],     qa[kk][0], qa[kk][1], qa[kk][2], qa[kk][3], b0, b1);
                mma_f16(s[2 * np + 1], qa[kk][0], qa[kk][1], qa[kk][2], qa[kk][3], b2, b3);
            }
        }

        const int rg  = qb * 128 + wr0 + g;
        const int rg8 = rg + 8;
        if (kb * 64 + 63 > qb * 128 + wr0) {
#pragma unroll
            for (int nt = 0; nt < 8; nt++) {
                int cc = kb * 64 + nt * 8 + 2 * t;
                s[nt][0] = (cc     > rg ) ? -1e30f : s[nt][0] * 0.125f;
                s[nt][1] = (cc + 1 > rg ) ? -1e30f : s[nt][1] * 0.125f;
                s[nt][2] = (cc     > rg8) ? -1e30f : s[nt][2] * 0.125f;
                s[nt][3] = (cc + 1 > rg8) ? -1e30f : s[nt][3] * 0.125f;
            }
        } else {
#pragma unroll
            for (int nt = 0; nt < 8; nt++)
#pragma unroll
                for (int r = 0; r < 4; r++) s[nt][r] *= 0.125f;
        }

        float mx0 = -1e30f, mx1 = -1e30f;
#pragma unroll
        for (int nt = 0; nt < 8; nt++) {
            mx0 = fmaxf(mx0, fmaxf(s[nt][0], s[nt][1]));
            mx1 = fmaxf(mx1, fmaxf(s[nt][2], s[nt][3]));
        }
        mx0 = fmaxf(mx0, __shfl_xor_sync(0xffffffffu, mx0, 1));
        mx0 = fmaxf(mx0, __shfl_xor_sync(0xffffffffu, mx0, 2));
        mx1 = fmaxf(mx1, __shfl_xor_sync(0xffffffffu, mx1, 1));
        mx1 = fmaxf(mx1, __shfl_xor_sync(0xffffffffu, mx1, 2));

        float mn0 = fmaxf(m0, mx0), mn1 = fmaxf(m1, mx1);
        float corr0 = __expf(m0 - mn0), corr1 = __expf(m1 - mn1);
        m0 = mn0; m1 = mn1;

        float rs0 = 0.0f, rs1 = 0.0f;
        uint32_t ph[8], ph8[8];
#pragma unroll
        for (int nt = 0; nt < 8; nt++) {
            float p0 = __expf(s[nt][0] - mn0);
            float p1 = __expf(s[nt][1] - mn0);
            float p2 = __expf(s[nt][2] - mn1);
            float p3 = __expf(s[nt][3] - mn1);
            rs0 += p0 + p1;
            rs1 += p2 + p3;
            __half2 h0 = __floats2half2_rn(p0, p1);
            __half2 h1 = __floats2half2_rn(p2, p3);
            ph[nt]  = *(uint32_t*)&h0;
            ph8[nt] = *(uint32_t*)&h1;
        }
        rs0 += __shfl_xor_sync(0xffffffffu, rs0, 1);
        rs0 += __shfl_xor_sync(0xffffffffu, rs0, 2);
        rs1 += __shfl_xor_sync(0xffffffffu, rs1, 1);
        rs1 += __shfl_xor_sync(0xffffffffu, rs1, 2);
        l0 = l0 * corr0 + rs0;
        l1 = l1 * corr1 + rs1;

#pragma unroll
        for (int nt = 0; nt < 8; nt++) {
            o[nt][0] *= corr0; o[nt][1] *= corr0;
            o[nt][2] *= corr1; o[nt][3] *= corr1;
        }

        const int vrowbase = ((lane >> 3) & 1) * 8 + lsub8;
        const int vchsel   = lane >> 4;
#pragma unroll
        for (int kk = 0; kk < 4; kk++) {
            const int vrow = 16 * kk + vrowbase;
#pragma unroll
            for (int ntp = 0; ntp < 4; ntp++) {
                const int chunk = 2 * ntp + vchsel;
                uint32_t addr = vsb[st] + (vrow * 8 + (chunk ^ (vrow & 7))) * 16;
                uint32_t r0, r1, r2, r3;
                ldsm_x4_trans(r0, r1, r2, r3, addr);
                mma_f16(o[2 * ntp],     ph[2 * kk], ph8[2 * kk],
                        ph[2 * kk + 1], ph8[2 * kk + 1], r0, r1);
                mma_f16(o[2 * ntp + 1], ph[2 * kk], ph8[2 * kk],
                        ph[2 * kk + 1], ph8[2 * kk + 1], r2, r3);
            }
        }
    }

    float inv0 = 1.0f / l0, inv1 = 1.0f / l1;
    __half* Xr0 = X + (size_t)(qb * 128 + wr0 + g) * rowstride + headoff;
    __half* Xr8 = Xr0 + 8 * rowstride;
#pragma unroll
    for (int nt = 0; nt < 8; nt++) {
        __half2 h0 = __floats2half2_rn(o[nt][0] * inv0, o[nt][1] * inv0);
        __half2 h1 = __floats2half2_rn(o[nt][2] * inv1, o[nt][3] * inv1);
        *(uint32_t*)(Xr0 + nt * 8 + 2 * t) = *(uint32_t*)&h0;
        *(uint32_t*)(Xr8 + nt * 8 + 2 * t) = *(uint32_t*)&h1;
    }
}

// ---------------------------------------------------------------------------
// kernel_launch
// Inputs: query, key, value, mask, Wq, bq, Wk, bk, Wv, bv, Wo, bo
// ---------------------------------------------------------------------------
extern "C" void kernel_launch(void* const* d_in, const int* in_sizes, int n_in,
                              void* d_out, int out_size)
{
    const float* query = (const float*)d_in[0];
    const float* key   = (const float*)d_in[1];
    const float* value = (const float*)d_in[2];
    // d_in[3] = mask (tril causal) — handled analytically in flash_attn_mma
    const float* Wq = (const float*)d_in[4];
    const float* bq = (const float*)d_in[5];
    const float* Wk = (const float*)d_in[6];
    const float* bk = (const float*)d_in[7];
    const float* Wv = (const float*)d_in[8];
    const float* bv = (const float*)d_in[9];
    const float* Wo = (const float*)d_in[10];
    const float* bo = (const float*)d_in[11];
    float* out = (float*)d_out;

    __half *hq, *hk, *hv, *pq, *pk, *pv, *hx;
    uint32_t* wt;
    cudaGetSymbolAddress((void**)&hq, g_hq);
    cudaGetSymbolAddress((void**)&hk, g_hk);
    cudaGetSymbolAddress((void**)&hv, g_hv);
    cudaGetSymbolAddress((void**)&pq, g_pq);
    cudaGetSymbolAddress((void**)&pk, g_pk);
    cudaGetSymbolAddress((void**)&pv, g_pv);
    cudaGetSymbolAddress((void**)&hx, g_hx);
    cudaGetSymbolAddress((void**)&wt, g_wt);

    uint32_t* wtq = wt;
    uint32_t* wtk = wt + (size_t)DM * DM / 2;
    uint32_t* wtv = wt + (size_t)DM * DM;
    uint32_t* wto = wt + (size_t)DM * DM * 3 / 2;

    cudaFuncSetAttribute(tc_gemm, cudaFuncAttributeMaxDynamicSharedMemorySize, GS_TOTAL);

    // 1) convert inputs fp32 -> fp16
    CvtArgs ca;
    ca.src[0] = query; ca.dst[0] = hq;
    ca.src[1] = key;   ca.dst[1] = hk;
    ca.src[2] = value; ca.dst[2] = hv;
    cvt_f2h<<<dim3(NTOK * DM / 1024, 1, 3), 256>>>(ca, NTOK * DM);

    // 2) convert + transpose weights -> Wt[n][k] fp16
    CvtWArgs cw;
    cw.W[0] = Wq; cw.Wt[0] = wtq;
    cw.W[1] = Wk; cw.Wt[1] = wtk;
    cw.W[2] = Wv; cw.Wt[2] = wtv;
    cw.W[3] = Wo; cw.Wt[3] = wto;
    cvt_w_trans<<<dim3(DM / 32, DM / 32, 4), 256>>>(cw);

    // 3) fused Q/K/V projections (fp16 outputs)
    TCGemmArgs proj;
    proj.A[0] = hq; proj.W[0] = (const __half*)wtq; proj.bias[0] = bq; proj.C[0] = nullptr; proj.Ch[0] = pq;
    proj.A[1] = hk; proj.W[1] = (const __half*)wtk; proj.bias[1] = bk; proj.C[1] = nullptr; proj.Ch[1] = pk;
    proj.A[2] = hv; proj.W[2] = (const __half*)wtv; proj.bias[2] = bv; proj.C[2] = nullptr; proj.Ch[2] = pv;
    tc_gemm<<<dim3(DM / 128, NTOK / 128, 3), 256, GS_TOTAL>>>(proj, NTOK, DM, DM);

    // 4) attention (fp16 in, fp16 out)
    flash_attn_mma<<<dim3(SEQ / 128, BAT * NH), 256>>>(pq, pk, pv, hx);

    // 5) output projection (fp32 output)
    TCGemmArgs oproj;
    oproj.A[0] = hx; oproj.W[0] = (const __half*)wto; oproj.bias[0] = bo; oproj.C[0] = out; oproj.Ch[0] = nullptr;
    oproj.A[1] = hx; oproj.W[1] = (const __half*)wto; oproj.bias[1] = bo; oproj.C[1] = out; oproj.Ch[1] = nullptr;
    oproj.A[2] = hx; oproj.W[2] = (const __half*)wto; oproj.bias[2] = bo; oproj.C[2] = out; oproj.Ch[2] = nullptr;
    tc_gemm<<<dim3(DM / 128, NTOK / 128, 1), 256, GS_TOTAL>>>(oproj, NTOK, DM, DM);
}